// round 4
// baseline (speedup 1.0000x reference)
#include <cuda_runtime.h>
#include <math.h>
#include <stdint.h>

// Problem constants
#define BB    8
#define CC    512
#define HH    56
#define WW_   56
#define HWSZ  3136
#define WS_   7
#define SS_   3
#define NH_   16
#define HD_   32
#define T_    49
#define NW_   64
#define BW_   512          // BB * NW_
#define NTOK  25088        // BW_ * T_
#define L_    64

// ---------------- scratch (device globals; no runtime alloc) ----------------
__device__ float g_vin [512 * 256];
__device__ float g_vec [BW_ * CC];
__device__ float g_tok [NTOK * CC];
__device__ float g_qkv [NTOK * 3 * CC];
__device__ float g_o1  [NTOK * CC];
__device__ float g_w2  [NTOK * CC];
__device__ float g_skipa[NTOK * CC];        // skip1 [B,HW,C] full fp32, unpermuted
__device__ float g_pq  [NTOK * CC];
__device__ float g_q2  [NTOK * CC];
__device__ float g_k2  [BW_ * CC];
__device__ float g_v2  [BW_ * CC];
__device__ float g_co1 [NTOK * CC];
__device__ float g_co2 [NTOK * CC];
__device__ float g_skip2[NTOK * CC];        // full fp32, unpermuted
__device__ float g_skip2r[NTOK * CC];       // tf32 + K-permuted (GEMM A)
__device__ float g_ffh [NTOK * 4 * CC];
__device__ float g_ffo [NTOK * CC];
__device__ float g_bias[NH_ * T_ * T_];
__device__ float g_bperm[7168];             // permuted biases

// transposed, tf32-rounded, doubly-permuted weights: [P(n), P(k)]
__device__ float g_tmw_t  [512 * 256];
__device__ float g_qkvw_t [1536 * 512];
__device__ float g_wprw_t [512 * 512];
__device__ float g_cain_t [1536 * 512];
__device__ float g_caout_t[512 * 512];
__device__ float g_ff1_t  [2048 * 512];
__device__ float g_ff2_t  [512 * 2048];

// bias scratch offsets
#define BP_TM    0
#define BP_QKV   512
#define BP_WPR   2048
#define BP_CAIN  2560
#define BP_CAOUT 4096
#define BP_FF1   4608
#define BP_FF2   6656

// ---------------- helpers ----------------
__device__ __forceinline__ int permc(int c) {          // within-8 rotation
    return (c & ~7) | ((c & 3) << 1) | ((c >> 2) & 1);
}
__device__ __forceinline__ float gelu_exact(float x) {
    return 0.5f * x * (1.0f + erff(x * 0.70710678118654752f));
}
__device__ __forceinline__ float tf32r(float x) {
    uint32_t o;
    asm("cvt.rna.tf32.f32 %0, %1;" : "=r"(o) : "f"(x));
    return __uint_as_float(o);
}
__device__ __forceinline__ uint32_t s2u(const void* p) {
    uint32_t a;
    asm("{ .reg .u64 t; cvta.to.shared.u64 t, %1; cvt.u32.u64 %0, t; }"
        : "=r"(a) : "l"(p));
    return a;
}

__device__ __forceinline__ void block_meanvar(float s, float ss, int n,
                                              float* mu, float* rstd) {
    #pragma unroll
    for (int o = 16; o > 0; o >>= 1) {
        s  += __shfl_down_sync(0xffffffffu, s,  o);
        ss += __shfl_down_sync(0xffffffffu, ss, o);
    }
    __shared__ float rs[8], rss[8], res[2];
    int lane = threadIdx.x & 31, wid = threadIdx.x >> 5;
    if (lane == 0) { rs[wid] = s; rss[wid] = ss; }
    __syncthreads();
    if (threadIdx.x == 0) {
        float S = 0.f, SS2 = 0.f;
        #pragma unroll
        for (int i = 0; i < 8; i++) { S += rs[i]; SS2 += rss[i]; }
        float m = S / n;
        float var = SS2 / n - m * m;
        res[0] = m; res[1] = rsqrtf(var + 1e-5f);
    }
    __syncthreads();
    *mu = res[0]; *rstd = res[1];
}

// ---------------- tf32 mma.sync GEMM (K-permuted operands) ----------------
#define EPI_NONE  0
#define EPI_GELU  1
#define EPI_SCALE 2

#define LDPAD 36
#define TILEF (128 * LDPAD)
#define TGEMM_SMEM (4 * TILEF * 4)

__device__ __forceinline__ void mma_tf32(float* c, const uint32_t* a,
                                         const uint32_t* b) {
    asm volatile(
        "mma.sync.aligned.m16n8k8.row.col.f32.tf32.tf32.f32 "
        "{%0,%1,%2,%3}, {%4,%5,%6,%7}, {%8,%9}, {%0,%1,%2,%3};"
        : "+f"(c[0]), "+f"(c[1]), "+f"(c[2]), "+f"(c[3])
        : "r"(a[0]), "r"(a[1]), "r"(a[2]), "r"(a[3]),
          "r"(b[0]), "r"(b[1]));
}

template <int EPI>
__global__ __launch_bounds__(256, 2)
void tgemm(const float* __restrict__ A, const float* __restrict__ W,
           const float* __restrict__ bias, float* __restrict__ C,
           int M, int N, int K, float alpha) {
    extern __shared__ float smem[];
    float* Abuf = smem;                 // [2][128][LDPAD]
    float* Bbuf = smem + 2 * TILEF;     // [2][128][LDPAD]
    const uint32_t sm_a = s2u(Abuf), sm_b = s2u(Bbuf);

    const int tid = threadIdx.x;
    const int wid = tid >> 5, lane = tid & 31;
    const int m0 = blockIdx.y << 7, n0 = blockIdx.x << 7;
    const int wm = wid & 3, wn = wid >> 2;
    const int m_off = wm << 5;
    const int n_off = wn << 6;

    const float* Abase = A + (size_t)m0 * K;
    const float* Wbase = W + (size_t)n0 * K;
    const int NC = K >> 5;

    const int seg = tid & 7;
    const int lr0 = tid >> 3;

    auto load_chunk = [&](int c, int sel) {
        uint32_t ab = sm_a + sel * (TILEF * 4);
        uint32_t bb = sm_b + sel * (TILEF * 4);
        const float* As = Abase + c * 32 + seg * 4;
        const float* Ws = Wbase + c * 32 + seg * 4;
        #pragma unroll
        for (int i = 0; i < 4; i++) {
            int r = lr0 + (i << 5);
            uint32_t so = (uint32_t)(r * (LDPAD * 4) + seg * 16);
            asm volatile("cp.async.cg.shared.global [%0], [%1], 16;"
                         :: "r"(ab + so), "l"(As + (size_t)r * K));
            asm volatile("cp.async.cg.shared.global [%0], [%1], 16;"
                         :: "r"(bb + so), "l"(Ws + (size_t)r * K));
        }
    };

    float acc[2][8][4];
    #pragma unroll
    for (int i = 0; i < 2; i++)
        #pragma unroll
        for (int j = 0; j < 8; j++)
            #pragma unroll
            for (int q = 0; q < 4; q++) acc[i][j][q] = 0.f;

    load_chunk(0, 0);
    asm volatile("cp.async.commit_group;" ::: "memory");

    const int qr = lane >> 2, qc = lane & 3;

    for (int c = 0; c < NC; c++) {
        int sel = c & 1;
        if (c + 1 < NC) {
            load_chunk(c + 1, sel ^ 1);
            asm volatile("cp.async.commit_group;" ::: "memory");
            asm volatile("cp.async.wait_group 1;" ::: "memory");
        } else {
            asm volatile("cp.async.wait_group 0;" ::: "memory");
        }
        __syncthreads();

        const float* As = Abuf + sel * TILEF;
        const float* Bs = Bbuf + sel * TILEF;

        // K-permuted layout: fragment pairs (qc, qc+4) are adjacent floats.
        #pragma unroll
        for (int k0 = 0; k0 < 32; k0 += 8) {
            uint32_t a[2][4], b[8][2];
            #pragma unroll
            for (int mt = 0; mt < 2; mt++) {
                float2 lo = *(const float2*)(As + (m_off + mt * 16 + qr) * LDPAD + k0 + qc * 2);
                float2 hi = *(const float2*)(As + (m_off + mt * 16 + qr + 8) * LDPAD + k0 + qc * 2);
                a[mt][0] = __float_as_uint(lo.x);
                a[mt][2] = __float_as_uint(lo.y);
                a[mt][1] = __float_as_uint(hi.x);
                a[mt][3] = __float_as_uint(hi.y);
            }
            #pragma unroll
            for (int nt = 0; nt < 8; nt++) {
                float2 bb = *(const float2*)(Bs + (n_off + nt * 8 + qr) * LDPAD + k0 + qc * 2);
                b[nt][0] = __float_as_uint(bb.x);
                b[nt][1] = __float_as_uint(bb.y);
            }
            #pragma unroll
            for (int mt = 0; mt < 2; mt++)
                #pragma unroll
                for (int nt = 0; nt < 8; nt++)
                    mma_tf32(acc[mt][nt], a[mt], b[nt]);
        }
        __syncthreads();
    }

    // epilogue (bias is pre-permuted to slot order)
    #pragma unroll
    for (int mt = 0; mt < 2; mt++) {
        #pragma unroll
        for (int half = 0; half < 2; half++) {
            int row = m0 + m_off + mt * 16 + qr + half * 8;
            float* Cp = C + (size_t)row * N + n0 + n_off;
            #pragma unroll
            for (int nt = 0; nt < 8; nt++) {
                int col = nt * 8 + qc * 2;
                float v0 = acc[mt][nt][half * 2 + 0] + bias[n0 + n_off + col];
                float v1 = acc[mt][nt][half * 2 + 1] + bias[n0 + n_off + col + 1];
                if (EPI == EPI_GELU)  { v0 = tf32r(gelu_exact(v0)); v1 = tf32r(gelu_exact(v1)); }
                if (EPI == EPI_SCALE) { v0 *= alpha; v1 *= alpha; }
                *(float2*)(Cp + col) = make_float2(v0, v1);
            }
        }
    }
}

// ---------------- weight transpose + tf32 round + double permutation --------
__global__ __launch_bounds__(256)
void transpose_w(const float* __restrict__ W, float* __restrict__ Wt,
                 int K, int N) {
    __shared__ float tile[32][33];
    int kb = blockIdx.y * 32, nb = blockIdx.x * 32;
    int tx = threadIdx.x & 31, ty = threadIdx.x >> 5;
    #pragma unroll
    for (int i = 0; i < 32; i += 8)
        tile[ty + i][tx] = W[(size_t)(kb + ty + i) * N + nb + tx];
    __syncthreads();
    #pragma unroll
    for (int i = 0; i < 32; i += 8)
        Wt[(size_t)permc(nb + ty + i) * K + permc(kb + tx)] = tf32r(tile[tx][ty + i]);
}

__global__ void round_copy(const float* __restrict__ in, float* __restrict__ o, int n) {
    int i = blockIdx.x * 256 + threadIdx.x;
    if (i < n) o[(i & ~255) | permc(i & 255)] = tf32r(in[i]);
}

__global__ void permute_bias(const float* __restrict__ s, float* __restrict__ d, int n) {
    int i = blockIdx.x * 256 + threadIdx.x;
    if (i < n) d[permc(i)] = s[i];
}

// ---------------- relative-position bias precompute ----------------
__global__ void bias_kernel(const float* __restrict__ w1, const float* __restrict__ b1,
                            const float* __restrict__ w2, const float* __restrict__ b2) {
    int pair = blockIdx.x;
    int q = pair / T_, k = pair % T_;
    float d0 = (float)(q / WS_ - k / WS_);
    float d1 = (float)(q % WS_ - k % WS_);
    float r0 = (d0 > 0.f ? 1.f : (d0 < 0.f ? -1.f : 0.f)) * log1pf(fabsf(d0));
    float r1 = (d1 > 0.f ? 1.f : (d1 < 0.f ? -1.f : 0.f)) * log1pf(fabsf(d1));
    int tid = threadIdx.x;
    __shared__ float hbuf[256];
    float hv = r0 * w1[tid] + r1 * w1[256 + tid] + b1[tid];
    hbuf[tid] = fmaxf(hv, 0.f);
    __syncthreads();
    if (tid < NH_) {
        float s = b2[tid];
        #pragma unroll 8
        for (int j = 0; j < 256; j++) s += hbuf[j] * w2[j * NH_ + tid];
        g_bias[tid * (T_ * T_) + pair] = s;
    }
}

// ---------------- roll(-3,-3) + unfold into token rows (tf32, permuted) -----
__global__ __launch_bounds__(256)
void unfold_kernel(const float* __restrict__ visual) {
    int r = blockIdx.x;
    int bw = r / T_, t = r % T_;
    int b = bw / NW_, win = bw % NW_, wh = win >> 3, ww = win & 7;
    int h = (wh * WS_ + t / WS_ + SS_) % HH;
    int w = (ww * WS_ + t % WS_ + SS_) % WW_;
    int hw = h * WW_ + w;
    for (int c = threadIdx.x; c < CC; c += 256)
        g_tok[(size_t)r * CC + permc(c)] = tf32r(visual[(size_t)(b * CC + c) * HWSZ + hw]);
}

// ---------------- window attention (permutation-transparent) ----------------
__global__ __launch_bounds__(256)
void win_attn(const float* __restrict__ tau) {
    int bw = blockIdx.x >> 4;
    int hh = blockIdx.x & 15;
    int tid = threadIdx.x;

    __shared__ __align__(16) float sq[T_ * HD_], sk[T_ * HD_], sv[T_ * HD_];
    __shared__ float ss[T_ * 50];
    __shared__ float nq[T_], nk[T_];
    __shared__ int   rg[T_];

    size_t base = (size_t)(bw * T_) * (3 * CC) + hh * HD_;
    for (int idx = tid; idx < T_ * 8; idx += 256) {
        int t = idx >> 3, d4 = idx & 7;
        const float* ro = g_qkv + base + (size_t)t * (3 * CC) + d4 * 4;
        ((float4*)sq)[t * 8 + d4] = *(const float4*)(ro);
        ((float4*)sk)[t * 8 + d4] = *(const float4*)(ro + CC);
        ((float4*)sv)[t * 8 + d4] = *(const float4*)(ro + 2 * CC);
    }
    int win = bw & 63, wh = win >> 3, ww = win & 7;
    if (tid < T_) {
        int row = wh * WS_ + tid / WS_;
        int col = ww * WS_ + tid % WS_;
        int rh = row < 49 ? 0 : (row < 53 ? 1 : 2);
        int rw = col < 49 ? 0 : (col < 53 ? 1 : 2);
        rg[tid] = rh * 3 + rw;
    }
    __syncthreads();

    if (tid < T_) {
        float4 s1 = make_float4(0.f, 0.f, 0.f, 0.f), s2 = s1;
        #pragma unroll
        for (int d4 = 0; d4 < 8; d4++) {
            float4 a = ((float4*)sq)[tid * 8 + d4];
            float4 b = ((float4*)sk)[tid * 8 + d4];
            s1.x += a.x * a.x; s1.y += a.y * a.y; s1.z += a.z * a.z; s1.w += a.w * a.w;
            s2.x += b.x * b.x; s2.y += b.y * b.y; s2.z += b.z * b.z; s2.w += b.w * b.w;
        }
        nq[tid] = sqrtf(s1.x + s1.y + s1.z + s1.w);
        nk[tid] = sqrtf(s2.x + s2.y + s2.z + s2.w);
    }
    __syncthreads();

    float tauh = fmaxf(tau[hh], 0.01f);
    const float* bh = &g_bias[hh * (T_ * T_)];
    for (int idx = tid; idx < T_ * T_; idx += 256) {
        int q = idx / T_, k = idx % T_;
        float4 d4a = make_float4(0.f, 0.f, 0.f, 0.f);
        #pragma unroll
        for (int d4 = 0; d4 < 8; d4++) {
            float4 a = ((float4*)sq)[q * 8 + d4];
            float4 b = ((float4*)sk)[k * 8 + d4];
            d4a.x += a.x * b.x; d4a.y += a.y * b.y;
            d4a.z += a.z * b.z; d4a.w += a.w * b.w;
        }
        float dot = d4a.x + d4a.y + d4a.z + d4a.w;
        float s = dot / fmaxf(nq[q] * nk[k], 1e-6f) / tauh + bh[idx];
        if (rg[q] != rg[k]) s -= 100.0f;
        ss[q * 50 + k] = s;
    }
    __syncthreads();

    if (tid < T_) {
        float m = -1e30f;
        for (int k = 0; k < T_; k++) m = fmaxf(m, ss[tid * 50 + k]);
        float sum = 0.f;
        for (int k = 0; k < T_; k++) {
            float e = expf(ss[tid * 50 + k] - m);
            ss[tid * 50 + k] = e; sum += e;
        }
        float inv = 1.f / sum;
        for (int k = 0; k < T_; k++) ss[tid * 50 + k] *= inv;
    }
    __syncthreads();

    for (int idx = tid; idx < T_ * 8; idx += 256) {
        int t = idx >> 3, d4 = idx & 7;
        float4 acc = make_float4(0.f, 0.f, 0.f, 0.f);
        #pragma unroll
        for (int k = 0; k < T_; k++) {
            float s = ss[t * 50 + k];
            float4 v = ((float4*)sv)[k * 8 + d4];
            acc.x += s * v.x; acc.y += s * v.y; acc.z += s * v.z; acc.w += s * v.w;
        }
        float4 o = make_float4(tf32r(acc.x), tf32r(acc.y), tf32r(acc.z), tf32r(acc.w));
        *(float4*)(g_o1 + (size_t)(bw * T_ + t) * CC + hh * HD_ + d4 * 4) = o;
    }
}

// ---------------- fold+roll(+3) + LN1 + residual; emit CA query tokens ------
__global__ __launch_bounds__(256)
void merge_ln1(const float* __restrict__ visual,
               const float* __restrict__ g, const float* __restrict__ bt) {
    int pos = blockIdx.x;
    int b = pos / HWSZ, hw = pos % HWSZ;
    int h = hw / WW_, w = hw % WW_;
    int hp = (h + HH - SS_) % HH, wp = (w + WW_ - SS_) % WW_;
    int rm = (b * NW_ + (hp / WS_) * 8 + (wp / WS_)) * T_ + (hp % WS_) * WS_ + (wp % WS_);

    __shared__ float x[CC];
    int tid = threadIdx.x;
    float s = 0.f, ss2 = 0.f;
    for (int c = tid; c < CC; c += 256) {
        float v = g_w2[(size_t)rm * CC + permc(c)];   // w2 stored slot-permuted
        x[c] = v; s += v; ss2 += v * v;
    }
    float mu, rstd;
    block_meanvar(s, ss2, CC, &mu, &rstd);
    for (int c = tid; c < CC; c += 256) {
        float v = (x[c] - mu) * rstd * g[c] + bt[c]
                + visual[(size_t)(b * CC + c) * HWSZ + hw];
        g_skipa[(size_t)pos * CC + c] = v;
        g_pq  [(size_t)rm  * CC + permc(c)] = tf32r(v);
    }
}

// ---------------- cross attention ----------------
__global__ __launch_bounds__(256)
void ca_attn() {
    int bw = blockIdx.x >> 4;
    int hh = blockIdx.x & 15;
    int bkv = bw & 7;
    int tid = threadIdx.x;

    __shared__ __align__(16) float sq[T_ * HD_], sk[L_ * HD_], sv[L_ * HD_];
    __shared__ float ss[T_ * 65];

    for (int idx = tid; idx < T_ * 8; idx += 256) {
        int t = idx >> 3, d4 = idx & 7;
        ((float4*)sq)[t * 8 + d4] =
            *(const float4*)(g_q2 + (size_t)(bw * T_ + t) * CC + hh * HD_ + d4 * 4);
    }
    for (int idx = tid; idx < L_ * 8; idx += 256) {
        int l = idx >> 3, d4 = idx & 7;
        size_t ro = (size_t)(bkv * L_ + l) * CC + hh * HD_ + d4 * 4;
        ((float4*)sk)[l * 8 + d4] = *(const float4*)(g_k2 + ro);
        ((float4*)sv)[l * 8 + d4] = *(const float4*)(g_v2 + ro);
    }
    __syncthreads();

    for (int idx = tid; idx < T_ * L_; idx += 256) {
        int q = idx / L_, l = idx % L_;
        float4 d4a = make_float4(0.f, 0.f, 0.f, 0.f);
        #pragma unroll
        for (int d4 = 0; d4 < 8; d4++) {
            float4 a = ((float4*)sq)[q * 8 + d4];
            float4 b = ((float4*)sk)[l * 8 + d4];
            d4a.x += a.x * b.x; d4a.y += a.y * b.y;
            d4a.z += a.z * b.z; d4a.w += a.w * b.w;
        }
        ss[q * 65 + l] = d4a.x + d4a.y + d4a.z + d4a.w;
    }
    __syncthreads();

    if (tid < T_) {
        float m = -1e30f;
        for (int l = 0; l < L_; l++) m = fmaxf(m, ss[tid * 65 + l]);
        float sum = 0.f;
        for (int l = 0; l < L_; l++) {
            float e = expf(ss[tid * 65 + l] - m);
            ss[tid * 65 + l] = e; sum += e;
        }
        float inv = 1.f / sum;
        for (int l = 0; l < L_; l++) ss[tid * 65 + l] *= inv;
    }
    __syncthreads();

    for (int idx = tid; idx < T_ * 8; idx += 256) {
        int t = idx >> 3, d4 = idx & 7;
        float4 acc = make_float4(0.f, 0.f, 0.f, 0.f);
        #pragma unroll
        for (int l = 0; l < L_; l++) {
            float s = ss[t * 65 + l];
            float4 v = ((float4*)sv)[l * 8 + d4];
            acc.x += s * v.x; acc.y += s * v.y; acc.z += s * v.z; acc.w += s * v.w;
        }
        float4 o = make_float4(tf32r(acc.x), tf32r(acc.y), tf32r(acc.z), tf32r(acc.w));
        *(float4*)(g_co1 + (size_t)(bw * T_ + t) * CC + hh * HD_ + d4 * 4) = o;
    }
}

// ---------------- LN2 + fold+roll(+3) + residual ----------------
__global__ __launch_bounds__(256)
void ca_ln2(const float* __restrict__ g, const float* __restrict__ bt) {
    int r = blockIdx.x;
    int bw = r / T_, t = r % T_;
    int b = bw / NW_, win = bw % NW_, wh = win >> 3, ww = win & 7;
    int h = (wh * WS_ + t / WS_ + SS_) % HH;
    int w = (ww * WS_ + t % WS_ + SS_) % WW_;
    int pos = b * HWSZ + h * WW_ + w;

    __shared__ float x[CC];
    int tid = threadIdx.x;
    float s = 0.f, ss2 = 0.f;
    for (int c = tid; c < CC; c += 256) {
        float v = g_co2[(size_t)r * CC + permc(c)];
        x[c] = v; s += v; ss2 += v * v;
    }
    float mu, rstd;
    block_meanvar(s, ss2, CC, &mu, &rstd);
    for (int c = tid; c < CC; c += 256) {
        float v = (x[c] - mu) * rstd * g[c] + bt[c]
                + g_skipa[(size_t)pos * CC + c];
        g_skip2 [(size_t)pos * CC + c] = v;
        g_skip2r[(size_t)pos * CC + permc(c)] = tf32r(v);
    }
}

// ---------------- LN3(ff) + skip2, write [B,C,H,W] ----------------
__global__ __launch_bounds__(256)
void final_kernel(float* __restrict__ out,
                  const float* __restrict__ g, const float* __restrict__ bt) {
    int pos = blockIdx.x;
    int b = pos / HWSZ, hw = pos % HWSZ;

    __shared__ float x[CC];
    int tid = threadIdx.x;
    float s = 0.f, ss2 = 0.f;
    for (int c = tid; c < CC; c += 256) {
        float v = g_ffo[(size_t)pos * CC + permc(c)];
        x[c] = v; s += v; ss2 += v * v;
    }
    float mu, rstd;
    block_meanvar(s, ss2, CC, &mu, &rstd);
    for (int c = tid; c < CC; c += 256) {
        float v = (x[c] - mu) * rstd * g[c] + bt[c];
        out[(size_t)(b * CC + c) * HWSZ + hw] = g_skip2[(size_t)pos * CC + c] + v;
    }
}

// ---------------- launch ----------------
extern "C" void kernel_launch(void* const* d_in, const int* in_sizes, int n_in,
                              void* d_out, int out_size) {
    const float* visual   = (const float*)d_in[0];
    const float* vector   = (const float*)d_in[1];
    const float* tm_w     = (const float*)d_in[2];
    const float* tm_b     = (const float*)d_in[3];
    const float* ln1_g    = (const float*)d_in[4];
    const float* ln1_b    = (const float*)d_in[5];
    const float* ln2_g    = (const float*)d_in[6];
    const float* ln2_b    = (const float*)d_in[7];
    const float* ln3_g    = (const float*)d_in[8];
    const float* ln3_b    = (const float*)d_in[9];
    const float* qkv_w    = (const float*)d_in[10];
    const float* qkv_b    = (const float*)d_in[11];
    const float* wproj_w  = (const float*)d_in[12];
    const float* wproj_b  = (const float*)d_in[13];
    const float* meta_w1  = (const float*)d_in[14];
    const float* meta_b1  = (const float*)d_in[15];
    const float* meta_w2  = (const float*)d_in[16];
    const float* meta_b2  = (const float*)d_in[17];
    const float* tau      = (const float*)d_in[18];
    const float* ca_in_w  = (const float*)d_in[19];
    const float* ca_in_b  = (const float*)d_in[20];
    const float* ca_out_w = (const float*)d_in[21];
    const float* ca_out_b = (const float*)d_in[22];
    const float* ff_w1    = (const float*)d_in[23];
    const float* ff_b1    = (const float*)d_in[24];
    const float* ff_w2    = (const float*)d_in[25];
    const float* ff_b2    = (const float*)d_in[26];
    float* out = (float*)d_out;

    float *vin, *vec, *tok, *qkv, *o1, *w2, *pq, *q2, *k2, *v2, *co1, *co2,
          *sk2r, *ffh, *ffo, *bp;
    float *tmwt, *qkvwt, *wprwt, *caint, *caoutt, *ff1t, *ff2t;
    cudaGetSymbolAddress((void**)&vin,   g_vin);
    cudaGetSymbolAddress((void**)&vec,   g_vec);
    cudaGetSymbolAddress((void**)&tok,   g_tok);
    cudaGetSymbolAddress((void**)&qkv,   g_qkv);
    cudaGetSymbolAddress((void**)&o1,    g_o1);
    cudaGetSymbolAddress((void**)&w2,    g_w2);
    cudaGetSymbolAddress((void**)&pq,    g_pq);
    cudaGetSymbolAddress((void**)&q2,    g_q2);
    cudaGetSymbolAddress((void**)&k2,    g_k2);
    cudaGetSymbolAddress((void**)&v2,    g_v2);
    cudaGetSymbolAddress((void**)&co1,   g_co1);
    cudaGetSymbolAddress((void**)&co2,   g_co2);
    cudaGetSymbolAddress((void**)&sk2r,  g_skip2r);
    cudaGetSymbolAddress((void**)&ffh,   g_ffh);
    cudaGetSymbolAddress((void**)&ffo,   g_ffo);
    cudaGetSymbolAddress((void**)&bp,    g_bperm);
    cudaGetSymbolAddress((void**)&tmwt,  g_tmw_t);
    cudaGetSymbolAddress((void**)&qkvwt, g_qkvw_t);
    cudaGetSymbolAddress((void**)&wprwt, g_wprw_t);
    cudaGetSymbolAddress((void**)&caint, g_cain_t);
    cudaGetSymbolAddress((void**)&caoutt,g_caout_t);
    cudaGetSymbolAddress((void**)&ff1t,  g_ff1_t);
    cudaGetSymbolAddress((void**)&ff2t,  g_ff2_t);

    cudaFuncSetAttribute(tgemm<EPI_NONE>,  cudaFuncAttributeMaxDynamicSharedMemorySize, TGEMM_SMEM);
    cudaFuncSetAttribute(tgemm<EPI_GELU>,  cudaFuncAttributeMaxDynamicSharedMemorySize, TGEMM_SMEM);
    cudaFuncSetAttribute(tgemm<EPI_SCALE>, cudaFuncAttributeMaxDynamicSharedMemorySize, TGEMM_SMEM);

    // weight transposes (+tf32 rounding + double permutation)
    transpose_w<<<dim3(16,  8), 256>>>(tm_w,     tmwt,  256,  512);
    transpose_w<<<dim3(48, 16), 256>>>(qkv_w,    qkvwt, 512, 1536);
    transpose_w<<<dim3(16, 16), 256>>>(wproj_w,  wprwt, 512,  512);
    transpose_w<<<dim3(48, 16), 256>>>(ca_in_w,  caint, 512, 1536);
    transpose_w<<<dim3(16, 16), 256>>>(ca_out_w, caoutt,512,  512);
    transpose_w<<<dim3(64, 16), 256>>>(ff_w1,    ff1t,  512, 2048);
    transpose_w<<<dim3(16, 64), 256>>>(ff_w2,    ff2t, 2048,  512);
    round_copy<<<512, 256>>>(vector, vin, 512 * 256);

    // bias permutations
    permute_bias<<<2, 256>>>(tm_b,     bp + BP_TM,    512);
    permute_bias<<<6, 256>>>(qkv_b,    bp + BP_QKV,   1536);
    permute_bias<<<2, 256>>>(wproj_b,  bp + BP_WPR,   512);
    permute_bias<<<6, 256>>>(ca_in_b,  bp + BP_CAIN,  1536);
    permute_bias<<<2, 256>>>(ca_out_b, bp + BP_CAOUT, 512);
    permute_bias<<<8, 256>>>(ff_b1,    bp + BP_FF1,   2048);
    permute_bias<<<2, 256>>>(ff_b2,    bp + BP_FF2,   512);

    bias_kernel<<<T_ * T_, 256>>>(meta_w1, meta_b1, meta_w2, meta_b2);

    // vec = gelu(vector @ tm_w + tm_b)
    tgemm<EPI_GELU><<<dim3(4, 4), 256, TGEMM_SMEM>>>(vin, tmwt, bp + BP_TM, vec, 512, 512, 256, 0.f);
    // K2/V2 (only B distinct kv sets)
    tgemm<EPI_NONE><<<dim3(4, 4), 256, TGEMM_SMEM>>>(vec, caint + 512 * 512,  bp + BP_CAIN + 512,  k2, 512, 512, 512, 0.f);
    tgemm<EPI_NONE><<<dim3(4, 4), 256, TGEMM_SMEM>>>(vec, caint + 1024 * 512, bp + BP_CAIN + 1024, v2, 512, 512, 512, 0.f);

    unfold_kernel<<<NTOK, 256>>>(visual);
    tgemm<EPI_NONE><<<dim3(12, 196), 256, TGEMM_SMEM>>>(tok, qkvwt, bp + BP_QKV, qkv, NTOK, 3 * CC, CC, 0.f);
    win_attn<<<BW_ * NH_, 256>>>(tau);
    tgemm<EPI_NONE><<<dim3(4, 196), 256, TGEMM_SMEM>>>(o1, wprwt, bp + BP_WPR, w2, NTOK, CC, CC, 0.f);
    merge_ln1<<<BB * HWSZ, 256>>>(visual, ln1_g, ln1_b);
    tgemm<EPI_SCALE><<<dim3(4, 196), 256, TGEMM_SMEM>>>(pq, caint, bp + BP_CAIN, q2, NTOK, CC, CC, 0.17677669529663687f);
    ca_attn<<<BW_ * NH_, 256>>>();
    tgemm<EPI_NONE><<<dim3(4, 196), 256, TGEMM_SMEM>>>(co1, caoutt, bp + BP_CAOUT, co2, NTOK, CC, CC, 0.f);
    ca_ln2<<<NTOK, 256>>>(ln2_g, ln2_b);
    tgemm<EPI_GELU><<<dim3(16, 196), 256, TGEMM_SMEM>>>(sk2r, ff1t, bp + BP_FF1, ffh, NTOK, 4 * CC, CC, 0.f);
    tgemm<EPI_NONE><<<dim3(4, 196), 256, TGEMM_SMEM>>>(ffh, ff2t, bp + BP_FF2, ffo, NTOK, CC, 2048, 0.f);
    final_kernel<<<BB * HWSZ, 256>>>(out, ln3_g, ln3_b);
}

// round 5
// speedup vs baseline: 1.0525x; 1.0525x over previous
#include <cuda_runtime.h>
#include <math.h>
#include <stdint.h>

// Problem constants
#define BB    8
#define CC    512
#define HH    56
#define WW_   56
#define HWSZ  3136
#define WS_   7
#define SS_   3
#define NH_   16
#define HD_   32
#define T_    49
#define NW_   64
#define BW_   512          // BB * NW_
#define NTOK  25088        // BW_ * T_
#define L_    64

// ---------------- scratch (device globals; no runtime alloc) ----------------
__device__ float g_vin [512 * 256];
__device__ float g_vec [BW_ * CC];
__device__ float g_tok [NTOK * CC];
__device__ float g_qkv [NTOK * 3 * CC];
__device__ float g_o1  [NTOK * CC];
__device__ float g_w2  [NTOK * CC];
__device__ float g_skipa[NTOK * CC];        // skip1 [B,HW,C] full fp32
__device__ float g_pq  [NTOK * CC];
__device__ float g_q2  [NTOK * CC];
__device__ float g_k2  [BW_ * CC];
__device__ float g_v2  [BW_ * CC];
__device__ float g_co1 [NTOK * CC];
__device__ float g_co2 [NTOK * CC];
__device__ float g_skip2[NTOK * CC];        // full fp32
__device__ float g_skip2r[NTOK * CC];       // tf32-rounded copy for GEMM
__device__ float g_ffh [NTOK * 4 * CC];
__device__ float g_ffo [NTOK * CC];
__device__ float g_bias[NH_ * T_ * T_];

// transposed (and tf32-rounded) weights: [N, K] K-contiguous
__device__ float g_tmw_t  [512 * 256];
__device__ float g_qkvw_t [1536 * 512];
__device__ float g_wprw_t [512 * 512];
__device__ float g_cain_t [1536 * 512];
__device__ float g_caout_t[512 * 512];
__device__ float g_ff1_t  [2048 * 512];
__device__ float g_ff2_t  [512 * 2048];

// ---------------- helpers ----------------
__device__ __forceinline__ float gelu_exact(float x) {
    return 0.5f * x * (1.0f + erff(x * 0.70710678118654752f));
}
__device__ __forceinline__ float tf32r(float x) {
    uint32_t o;
    asm("cvt.rna.tf32.f32 %0, %1;" : "=r"(o) : "f"(x));
    return __uint_as_float(o);
}
__device__ __forceinline__ uint32_t s2u(const void* p) {
    uint32_t a;
    asm("{ .reg .u64 t; cvta.to.shared.u64 t, %1; cvt.u32.u64 %0, t; }"
        : "=r"(a) : "l"(p));
    return a;
}

__device__ __forceinline__ void block_meanvar(float s, float ss, int n,
                                              float* mu, float* rstd) {
    #pragma unroll
    for (int o = 16; o > 0; o >>= 1) {
        s  += __shfl_down_sync(0xffffffffu, s,  o);
        ss += __shfl_down_sync(0xffffffffu, ss, o);
    }
    __shared__ float rs[8], rss[8], res[2];
    int lane = threadIdx.x & 31, wid = threadIdx.x >> 5;
    if (lane == 0) { rs[wid] = s; rss[wid] = ss; }
    __syncthreads();
    if (threadIdx.x == 0) {
        float S = 0.f, SS2 = 0.f;
        #pragma unroll
        for (int i = 0; i < 8; i++) { S += rs[i]; SS2 += rss[i]; }
        float m = S / n;
        float var = SS2 / n - m * m;
        res[0] = m; res[1] = rsqrtf(var + 1e-5f);
    }
    __syncthreads();
    *mu = res[0]; *rstd = res[1];
}

// ---------------- tf32 mma.sync GEMM ----------------
// C[M,N] = epi(A[M,K] @ W[N,K]^T + bias), all tf32-rounded inputs.
// M%256==0, N%128==0, K%32==0.
// 256 threads, 256x128 CTA tile, K-chunk 32, double-buffered cp.async.
// Warp layout: 4 (M) x 2 (N); each warp 64x64 via m16n8k8 frags (4x8).
#define EPI_NONE  0
#define EPI_GELU  1
#define EPI_SCALE 2

#define LDPAD 36
#define ATILEF (256 * LDPAD)
#define BTILEF (128 * LDPAD)
#define TGEMM_SMEM ((2 * ATILEF + 2 * BTILEF) * 4)   // 110592 bytes

__device__ __forceinline__ void mma_tf32(float* c, const uint32_t* a,
                                         const uint32_t* b) {
    asm volatile(
        "mma.sync.aligned.m16n8k8.row.col.f32.tf32.tf32.f32 "
        "{%0,%1,%2,%3}, {%4,%5,%6,%7}, {%8,%9}, {%0,%1,%2,%3};"
        : "+f"(c[0]), "+f"(c[1]), "+f"(c[2]), "+f"(c[3])
        : "r"(a[0]), "r"(a[1]), "r"(a[2]), "r"(a[3]),
          "r"(b[0]), "r"(b[1]));
}

template <int EPI>
__global__ __launch_bounds__(256, 1)
void tgemm(const float* __restrict__ A, const float* __restrict__ W,
           const float* __restrict__ bias, float* __restrict__ C,
           int M, int N, int K, float alpha) {
    extern __shared__ float smem[];
    float* Abuf = smem;                   // [2][256][LDPAD]
    float* Bbuf = smem + 2 * ATILEF;      // [2][128][LDPAD]
    const uint32_t sm_a = s2u(Abuf), sm_b = s2u(Bbuf);

    const int tid = threadIdx.x;
    const int wid = tid >> 5, lane = tid & 31;
    const int m0 = blockIdx.y << 8, n0 = blockIdx.x << 7;
    const int wm = wid & 3, wn = wid >> 2;
    const int m_off = wm << 6;            // 64-row warp tile
    const int n_off = wn << 6;            // 64-col warp tile

    const float* Abase = A + (size_t)m0 * K;
    const float* Wbase = W + (size_t)n0 * K;
    const int NC = K >> 5;

    const int seg = tid & 7;              // 4-float segment within 32 cols
    const int lr0 = tid >> 3;             // 0..31

    auto load_chunk = [&](int c, int sel) {
        uint32_t ab = sm_a + sel * (ATILEF * 4);
        uint32_t bb = sm_b + sel * (BTILEF * 4);
        const float* As = Abase + c * 32 + seg * 4;
        const float* Ws = Wbase + c * 32 + seg * 4;
        #pragma unroll
        for (int i = 0; i < 8; i++) {
            int r = lr0 + (i << 5);       // 0..255
            uint32_t so = (uint32_t)(r * (LDPAD * 4) + seg * 16);
            asm volatile("cp.async.cg.shared.global [%0], [%1], 16;"
                         :: "r"(ab + so), "l"(As + (size_t)r * K));
        }
        #pragma unroll
        for (int i = 0; i < 4; i++) {
            int r = lr0 + (i << 5);       // 0..127
            uint32_t so = (uint32_t)(r * (LDPAD * 4) + seg * 16);
            asm volatile("cp.async.cg.shared.global [%0], [%1], 16;"
                         :: "r"(bb + so), "l"(Ws + (size_t)r * K));
        }
    };

    float acc[4][8][4];
    #pragma unroll
    for (int i = 0; i < 4; i++)
        #pragma unroll
        for (int j = 0; j < 8; j++)
            #pragma unroll
            for (int q = 0; q < 4; q++) acc[i][j][q] = 0.f;

    load_chunk(0, 0);
    asm volatile("cp.async.commit_group;" ::: "memory");

    const int qr = lane >> 2, qc = lane & 3;

    for (int c = 0; c < NC; c++) {
        int sel = c & 1;
        if (c + 1 < NC) {
            load_chunk(c + 1, sel ^ 1);
            asm volatile("cp.async.commit_group;" ::: "memory");
            asm volatile("cp.async.wait_group 1;" ::: "memory");
        } else {
            asm volatile("cp.async.wait_group 0;" ::: "memory");
        }
        __syncthreads();

        const float* As = Abuf + sel * ATILEF;
        const float* Bs = Bbuf + sel * BTILEF;

        #pragma unroll
        for (int k0 = 0; k0 < 32; k0 += 8) {
            uint32_t a[4][4], b[8][2];
            #pragma unroll
            for (int mt = 0; mt < 4; mt++) {
                const float* ap = As + (m_off + mt * 16 + qr) * LDPAD + k0 + qc;
                a[mt][0] = __float_as_uint(ap[0]);
                a[mt][1] = __float_as_uint(ap[8 * LDPAD]);
                a[mt][2] = __float_as_uint(ap[4]);
                a[mt][3] = __float_as_uint(ap[8 * LDPAD + 4]);
            }
            #pragma unroll
            for (int nt = 0; nt < 8; nt++) {
                const float* bp = Bs + (n_off + nt * 8 + qr) * LDPAD + k0 + qc;
                b[nt][0] = __float_as_uint(bp[0]);
                b[nt][1] = __float_as_uint(bp[4]);
            }
            #pragma unroll
            for (int mt = 0; mt < 4; mt++)
                #pragma unroll
                for (int nt = 0; nt < 8; nt++)
                    mma_tf32(acc[mt][nt], a[mt], b[nt]);
        }
        __syncthreads();
    }

    // epilogue
    #pragma unroll
    for (int mt = 0; mt < 4; mt++) {
        #pragma unroll
        for (int half = 0; half < 2; half++) {
            int row = m0 + m_off + mt * 16 + qr + half * 8;
            float* Cp = C + (size_t)row * N + n0 + n_off;
            #pragma unroll
            for (int nt = 0; nt < 8; nt++) {
                int col = nt * 8 + qc * 2;
                float v0 = acc[mt][nt][half * 2 + 0] + bias[n0 + n_off + col];
                float v1 = acc[mt][nt][half * 2 + 1] + bias[n0 + n_off + col + 1];
                if (EPI == EPI_GELU)  { v0 = tf32r(gelu_exact(v0)); v1 = tf32r(gelu_exact(v1)); }
                if (EPI == EPI_SCALE) { v0 *= alpha; v1 *= alpha; }
                *(float2*)(Cp + col) = make_float2(v0, v1);
            }
        }
    }
}

// ---------------- weight transpose + tf32 round:  Wt[n,k] = rna(W[k,n]) ----
__global__ __launch_bounds__(256)
void transpose_w(const float* __restrict__ W, float* __restrict__ Wt,
                 int K, int N) {
    __shared__ float tile[32][33];
    int kb = blockIdx.y * 32, nb = blockIdx.x * 32;
    int tx = threadIdx.x & 31, ty = threadIdx.x >> 5;
    #pragma unroll
    for (int i = 0; i < 32; i += 8)
        tile[ty + i][tx] = W[(size_t)(kb + ty + i) * N + nb + tx];
    __syncthreads();
    #pragma unroll
    for (int i = 0; i < 32; i += 8)
        Wt[(size_t)(nb + ty + i) * K + kb + tx] = tf32r(tile[tx][ty + i]);
}

__global__ void round_copy(const float* __restrict__ in, float* __restrict__ o, int n) {
    int i = blockIdx.x * 256 + threadIdx.x;
    if (i < n) o[i] = tf32r(in[i]);
}

// ---------------- relative-position bias precompute ----------------
__global__ void bias_kernel(const float* __restrict__ w1, const float* __restrict__ b1,
                            const float* __restrict__ w2, const float* __restrict__ b2) {
    int pair = blockIdx.x;
    int q = pair / T_, k = pair % T_;
    float d0 = (float)(q / WS_ - k / WS_);
    float d1 = (float)(q % WS_ - k % WS_);
    float r0 = (d0 > 0.f ? 1.f : (d0 < 0.f ? -1.f : 0.f)) * log1pf(fabsf(d0));
    float r1 = (d1 > 0.f ? 1.f : (d1 < 0.f ? -1.f : 0.f)) * log1pf(fabsf(d1));
    int tid = threadIdx.x;
    __shared__ float hbuf[256];
    float hv = r0 * w1[tid] + r1 * w1[256 + tid] + b1[tid];
    hbuf[tid] = fmaxf(hv, 0.f);
    __syncthreads();
    if (tid < NH_) {
        float s = b2[tid];
        #pragma unroll 8
        for (int j = 0; j < 256; j++) s += hbuf[j] * w2[j * NH_ + tid];
        g_bias[tid * (T_ * T_) + pair] = s;
    }
}

// ---------------- roll(-3,-3) + unfold into token rows (tf32) ---------------
__global__ __launch_bounds__(256)
void unfold_kernel(const float* __restrict__ visual) {
    int r = blockIdx.x;
    int bw = r / T_, t = r % T_;
    int b = bw / NW_, win = bw % NW_, wh = win >> 3, ww = win & 7;
    int h = (wh * WS_ + t / WS_ + SS_) % HH;
    int w = (ww * WS_ + t % WS_ + SS_) % WW_;
    int hw = h * WW_ + w;
    for (int c = threadIdx.x; c < CC; c += 256)
        g_tok[(size_t)r * CC + c] = tf32r(visual[(size_t)(b * CC + c) * HWSZ + hw]);
}

// ---------------- window attention (vectorized) ----------------
__global__ __launch_bounds__(256)
void win_attn(const float* __restrict__ tau) {
    int bw = blockIdx.x >> 4;
    int hh = blockIdx.x & 15;
    int tid = threadIdx.x;

    __shared__ __align__(16) float sq[T_ * HD_], sk[T_ * HD_], sv[T_ * HD_];
    __shared__ float ss[T_ * 50];
    __shared__ float nq[T_], nk[T_];
    __shared__ int   rg[T_];

    size_t base = (size_t)(bw * T_) * (3 * CC) + hh * HD_;
    for (int idx = tid; idx < T_ * 8; idx += 256) {
        int t = idx >> 3, d4 = idx & 7;
        const float* ro = g_qkv + base + (size_t)t * (3 * CC) + d4 * 4;
        ((float4*)sq)[t * 8 + d4] = *(const float4*)(ro);
        ((float4*)sk)[t * 8 + d4] = *(const float4*)(ro + CC);
        ((float4*)sv)[t * 8 + d4] = *(const float4*)(ro + 2 * CC);
    }
    int win = bw & 63, wh = win >> 3, ww = win & 7;
    if (tid < T_) {
        int row = wh * WS_ + tid / WS_;
        int col = ww * WS_ + tid % WS_;
        int rh = row < 49 ? 0 : (row < 53 ? 1 : 2);
        int rw = col < 49 ? 0 : (col < 53 ? 1 : 2);
        rg[tid] = rh * 3 + rw;
    }
    __syncthreads();

    if (tid < T_) {
        float4 s1 = make_float4(0.f, 0.f, 0.f, 0.f), s2 = s1;
        #pragma unroll
        for (int d4 = 0; d4 < 8; d4++) {
            float4 a = ((float4*)sq)[tid * 8 + d4];
            float4 b = ((float4*)sk)[tid * 8 + d4];
            s1.x += a.x * a.x; s1.y += a.y * a.y; s1.z += a.z * a.z; s1.w += a.w * a.w;
            s2.x += b.x * b.x; s2.y += b.y * b.y; s2.z += b.z * b.z; s2.w += b.w * b.w;
        }
        nq[tid] = sqrtf(s1.x + s1.y + s1.z + s1.w);
        nk[tid] = sqrtf(s2.x + s2.y + s2.z + s2.w);
    }
    __syncthreads();

    float tauh = fmaxf(tau[hh], 0.01f);
    const float* bh = &g_bias[hh * (T_ * T_)];
    for (int idx = tid; idx < T_ * T_; idx += 256) {
        int q = idx / T_, k = idx % T_;
        float4 d4a = make_float4(0.f, 0.f, 0.f, 0.f);
        #pragma unroll
        for (int d4 = 0; d4 < 8; d4++) {
            float4 a = ((float4*)sq)[q * 8 + d4];
            float4 b = ((float4*)sk)[k * 8 + d4];
            d4a.x += a.x * b.x; d4a.y += a.y * b.y;
            d4a.z += a.z * b.z; d4a.w += a.w * b.w;
        }
        float dot = d4a.x + d4a.y + d4a.z + d4a.w;
        float s = dot / fmaxf(nq[q] * nk[k], 1e-6f) / tauh + bh[idx];
        if (rg[q] != rg[k]) s -= 100.0f;
        ss[q * 50 + k] = s;
    }
    __syncthreads();

    if (tid < T_) {
        float m = -1e30f;
        for (int k = 0; k < T_; k++) m = fmaxf(m, ss[tid * 50 + k]);
        float sum = 0.f;
        for (int k = 0; k < T_; k++) {
            float e = expf(ss[tid * 50 + k] - m);
            ss[tid * 50 + k] = e; sum += e;
        }
        float inv = 1.f / sum;
        for (int k = 0; k < T_; k++) ss[tid * 50 + k] *= inv;
    }
    __syncthreads();

    for (int idx = tid; idx < T_ * 8; idx += 256) {
        int t = idx >> 3, d4 = idx & 7;
        float4 acc = make_float4(0.f, 0.f, 0.f, 0.f);
        #pragma unroll
        for (int k = 0; k < T_; k++) {
            float s = ss[t * 50 + k];
            float4 v = ((float4*)sv)[k * 8 + d4];
            acc.x += s * v.x; acc.y += s * v.y; acc.z += s * v.z; acc.w += s * v.w;
        }
        float4 o = make_float4(tf32r(acc.x), tf32r(acc.y), tf32r(acc.z), tf32r(acc.w));
        *(float4*)(g_o1 + (size_t)(bw * T_ + t) * CC + hh * HD_ + d4 * 4) = o;
    }
}

// ---------------- fold+roll(+3) + LN1 + residual; emit CA query tokens ------
__global__ __launch_bounds__(256)
void merge_ln1(const float* __restrict__ visual,
               const float* __restrict__ g, const float* __restrict__ bt) {
    int pos = blockIdx.x;
    int b = pos / HWSZ, hw = pos % HWSZ;
    int h = hw / WW_, w = hw % WW_;
    int hp = (h + HH - SS_) % HH, wp = (w + WW_ - SS_) % WW_;
    int rm = (b * NW_ + (hp / WS_) * 8 + (wp / WS_)) * T_ + (hp % WS_) * WS_ + (wp % WS_);

    __shared__ float x[CC];
    int tid = threadIdx.x;
    float s = 0.f, ss2 = 0.f;
    for (int c = tid; c < CC; c += 256) {
        float v = g_w2[(size_t)rm * CC + c];
        x[c] = v; s += v; ss2 += v * v;
    }
    float mu, rstd;
    block_meanvar(s, ss2, CC, &mu, &rstd);
    for (int c = tid; c < CC; c += 256) {
        float v = (x[c] - mu) * rstd * g[c] + bt[c]
                + visual[(size_t)(b * CC + c) * HWSZ + hw];
        g_skipa[(size_t)pos * CC + c] = v;
        g_pq  [(size_t)rm  * CC + c] = tf32r(v);
    }
}

// ---------------- cross attention (vectorized) ----------------
__global__ __launch_bounds__(256)
void ca_attn() {
    int bw = blockIdx.x >> 4;
    int hh = blockIdx.x & 15;
    int bkv = bw & 7;
    int tid = threadIdx.x;

    __shared__ __align__(16) float sq[T_ * HD_], sk[L_ * HD_], sv[L_ * HD_];
    __shared__ float ss[T_ * 65];

    for (int idx = tid; idx < T_ * 8; idx += 256) {
        int t = idx >> 3, d4 = idx & 7;
        ((float4*)sq)[t * 8 + d4] =
            *(const float4*)(g_q2 + (size_t)(bw * T_ + t) * CC + hh * HD_ + d4 * 4);
    }
    for (int idx = tid; idx < L_ * 8; idx += 256) {
        int l = idx >> 3, d4 = idx & 7;
        size_t ro = (size_t)(bkv * L_ + l) * CC + hh * HD_ + d4 * 4;
        ((float4*)sk)[l * 8 + d4] = *(const float4*)(g_k2 + ro);
        ((float4*)sv)[l * 8 + d4] = *(const float4*)(g_v2 + ro);
    }
    __syncthreads();

    for (int idx = tid; idx < T_ * L_; idx += 256) {
        int q = idx / L_, l = idx % L_;
        float4 d4a = make_float4(0.f, 0.f, 0.f, 0.f);
        #pragma unroll
        for (int d4 = 0; d4 < 8; d4++) {
            float4 a = ((float4*)sq)[q * 8 + d4];
            float4 b = ((float4*)sk)[l * 8 + d4];
            d4a.x += a.x * b.x; d4a.y += a.y * b.y;
            d4a.z += a.z * b.z; d4a.w += a.w * b.w;
        }
        ss[q * 65 + l] = d4a.x + d4a.y + d4a.z + d4a.w;
    }
    __syncthreads();

    if (tid < T_) {
        float m = -1e30f;
        for (int l = 0; l < L_; l++) m = fmaxf(m, ss[tid * 65 + l]);
        float sum = 0.f;
        for (int l = 0; l < L_; l++) {
            float e = expf(ss[tid * 65 + l] - m);
            ss[tid * 65 + l] = e; sum += e;
        }
        float inv = 1.f / sum;
        for (int l = 0; l < L_; l++) ss[tid * 65 + l] *= inv;
    }
    __syncthreads();

    for (int idx = tid; idx < T_ * 8; idx += 256) {
        int t = idx >> 3, d4 = idx & 7;
        float4 acc = make_float4(0.f, 0.f, 0.f, 0.f);
        #pragma unroll
        for (int l = 0; l < L_; l++) {
            float s = ss[t * 65 + l];
            float4 v = ((float4*)sv)[l * 8 + d4];
            acc.x += s * v.x; acc.y += s * v.y; acc.z += s * v.z; acc.w += s * v.w;
        }
        float4 o = make_float4(tf32r(acc.x), tf32r(acc.y), tf32r(acc.z), tf32r(acc.w));
        *(float4*)(g_co1 + (size_t)(bw * T_ + t) * CC + hh * HD_ + d4 * 4) = o;
    }
}

// ---------------- LN2 + fold+roll(+3) + residual ----------------
__global__ __launch_bounds__(256)
void ca_ln2(const float* __restrict__ g, const float* __restrict__ bt) {
    int r = blockIdx.x;
    int bw = r / T_, t = r % T_;
    int b = bw / NW_, win = bw % NW_, wh = win >> 3, ww = win & 7;
    int h = (wh * WS_ + t / WS_ + SS_) % HH;
    int w = (ww * WS_ + t % WS_ + SS_) % WW_;
    int pos = b * HWSZ + h * WW_ + w;

    __shared__ float x[CC];
    int tid = threadIdx.x;
    float s = 0.f, ss2 = 0.f;
    for (int c = tid; c < CC; c += 256) {
        float v = g_co2[(size_t)r * CC + c];
        x[c] = v; s += v; ss2 += v * v;
    }
    float mu, rstd;
    block_meanvar(s, ss2, CC, &mu, &rstd);
    for (int c = tid; c < CC; c += 256) {
        float v = (x[c] - mu) * rstd * g[c] + bt[c]
                + g_skipa[(size_t)pos * CC + c];
        g_skip2 [(size_t)pos * CC + c] = v;
        g_skip2r[(size_t)pos * CC + c] = tf32r(v);
    }
}

// ---------------- LN3(ff) + skip2, write [B,C,H,W] ----------------
__global__ __launch_bounds__(256)
void final_kernel(float* __restrict__ out,
                  const float* __restrict__ g, const float* __restrict__ bt) {
    int pos = blockIdx.x;
    int b = pos / HWSZ, hw = pos % HWSZ;

    __shared__ float x[CC];
    int tid = threadIdx.x;
    float s = 0.f, ss2 = 0.f;
    for (int c = tid; c < CC; c += 256) {
        float v = g_ffo[(size_t)pos * CC + c];
        x[c] = v; s += v; ss2 += v * v;
    }
    float mu, rstd;
    block_meanvar(s, ss2, CC, &mu, &rstd);
    for (int c = tid; c < CC; c += 256) {
        float v = (x[c] - mu) * rstd * g[c] + bt[c];
        out[(size_t)(b * CC + c) * HWSZ + hw] = g_skip2[(size_t)pos * CC + c] + v;
    }
}

// ---------------- launch ----------------
extern "C" void kernel_launch(void* const* d_in, const int* in_sizes, int n_in,
                              void* d_out, int out_size) {
    const float* visual   = (const float*)d_in[0];
    const float* vector   = (const float*)d_in[1];
    const float* tm_w     = (const float*)d_in[2];
    const float* tm_b     = (const float*)d_in[3];
    const float* ln1_g    = (const float*)d_in[4];
    const float* ln1_b    = (const float*)d_in[5];
    const float* ln2_g    = (const float*)d_in[6];
    const float* ln2_b    = (const float*)d_in[7];
    const float* ln3_g    = (const float*)d_in[8];
    const float* ln3_b    = (const float*)d_in[9];
    const float* qkv_w    = (const float*)d_in[10];
    const float* qkv_b    = (const float*)d_in[11];
    const float* wproj_w  = (const float*)d_in[12];
    const float* wproj_b  = (const float*)d_in[13];
    const float* meta_w1  = (const float*)d_in[14];
    const float* meta_b1  = (const float*)d_in[15];
    const float* meta_w2  = (const float*)d_in[16];
    const float* meta_b2  = (const float*)d_in[17];
    const float* tau      = (const float*)d_in[18];
    const float* ca_in_w  = (const float*)d_in[19];
    const float* ca_in_b  = (const float*)d_in[20];
    const float* ca_out_w = (const float*)d_in[21];
    const float* ca_out_b = (const float*)d_in[22];
    const float* ff_w1    = (const float*)d_in[23];
    const float* ff_b1    = (const float*)d_in[24];
    const float* ff_w2    = (const float*)d_in[25];
    const float* ff_b2    = (const float*)d_in[26];
    float* out = (float*)d_out;

    float *vin, *vec, *tok, *qkv, *o1, *w2, *pq, *q2, *k2, *v2, *co1, *co2,
          *sk2r, *ffh, *ffo;
    float *tmwt, *qkvwt, *wprwt, *caint, *caoutt, *ff1t, *ff2t;
    cudaGetSymbolAddress((void**)&vin,   g_vin);
    cudaGetSymbolAddress((void**)&vec,   g_vec);
    cudaGetSymbolAddress((void**)&tok,   g_tok);
    cudaGetSymbolAddress((void**)&qkv,   g_qkv);
    cudaGetSymbolAddress((void**)&o1,    g_o1);
    cudaGetSymbolAddress((void**)&w2,    g_w2);
    cudaGetSymbolAddress((void**)&pq,    g_pq);
    cudaGetSymbolAddress((void**)&q2,    g_q2);
    cudaGetSymbolAddress((void**)&k2,    g_k2);
    cudaGetSymbolAddress((void**)&v2,    g_v2);
    cudaGetSymbolAddress((void**)&co1,   g_co1);
    cudaGetSymbolAddress((void**)&co2,   g_co2);
    cudaGetSymbolAddress((void**)&sk2r,  g_skip2r);
    cudaGetSymbolAddress((void**)&ffh,   g_ffh);
    cudaGetSymbolAddress((void**)&ffo,   g_ffo);
    cudaGetSymbolAddress((void**)&tmwt,  g_tmw_t);
    cudaGetSymbolAddress((void**)&qkvwt, g_qkvw_t);
    cudaGetSymbolAddress((void**)&wprwt, g_wprw_t);
    cudaGetSymbolAddress((void**)&caint, g_cain_t);
    cudaGetSymbolAddress((void**)&caoutt,g_caout_t);
    cudaGetSymbolAddress((void**)&ff1t,  g_ff1_t);
    cudaGetSymbolAddress((void**)&ff2t,  g_ff2_t);

    cudaFuncSetAttribute(tgemm<EPI_NONE>,  cudaFuncAttributeMaxDynamicSharedMemorySize, TGEMM_SMEM);
    cudaFuncSetAttribute(tgemm<EPI_GELU>,  cudaFuncAttributeMaxDynamicSharedMemorySize, TGEMM_SMEM);
    cudaFuncSetAttribute(tgemm<EPI_SCALE>, cudaFuncAttributeMaxDynamicSharedMemorySize, TGEMM_SMEM);

    // weight transposes (+tf32 rounding)
    transpose_w<<<dim3(16,  8), 256>>>(tm_w,     tmwt,  256,  512);
    transpose_w<<<dim3(48, 16), 256>>>(qkv_w,    qkvwt, 512, 1536);
    transpose_w<<<dim3(16, 16), 256>>>(wproj_w,  wprwt, 512,  512);
    transpose_w<<<dim3(48, 16), 256>>>(ca_in_w,  caint, 512, 1536);
    transpose_w<<<dim3(16, 16), 256>>>(ca_out_w, caoutt,512,  512);
    transpose_w<<<dim3(64, 16), 256>>>(ff_w1,    ff1t,  512, 2048);
    transpose_w<<<dim3(16, 64), 256>>>(ff_w2,    ff2t, 2048,  512);
    round_copy<<<512, 256>>>(vector, vin, 512 * 256);

    bias_kernel<<<T_ * T_, 256>>>(meta_w1, meta_b1, meta_w2, meta_b2);

    // vec = gelu(vector @ tm_w + tm_b)
    tgemm<EPI_GELU><<<dim3(4, 2), 256, TGEMM_SMEM>>>(vin, tmwt, tm_b, vec, 512, 512, 256, 0.f);
    // K2/V2 (only B distinct kv sets)
    tgemm<EPI_NONE><<<dim3(4, 2), 256, TGEMM_SMEM>>>(vec, caint + 512 * 512,  ca_in_b + 512,  k2, 512, 512, 512, 0.f);
    tgemm<EPI_NONE><<<dim3(4, 2), 256, TGEMM_SMEM>>>(vec, caint + 1024 * 512, ca_in_b + 1024, v2, 512, 512, 512, 0.f);

    unfold_kernel<<<NTOK, 256>>>(visual);
    tgemm<EPI_NONE><<<dim3(12, 98), 256, TGEMM_SMEM>>>(tok, qkvwt, qkv_b, qkv, NTOK, 3 * CC, CC, 0.f);
    win_attn<<<BW_ * NH_, 256>>>(tau);
    tgemm<EPI_NONE><<<dim3(4, 98), 256, TGEMM_SMEM>>>(o1, wprwt, wproj_b, w2, NTOK, CC, CC, 0.f);
    merge_ln1<<<BB * HWSZ, 256>>>(visual, ln1_g, ln1_b);
    tgemm<EPI_SCALE><<<dim3(4, 98), 256, TGEMM_SMEM>>>(pq, caint, ca_in_b, q2, NTOK, CC, CC, 0.17677669529663687f);
    ca_attn<<<BW_ * NH_, 256>>>();
    tgemm<EPI_NONE><<<dim3(4, 98), 256, TGEMM_SMEM>>>(co1, caoutt, ca_out_b, co2, NTOK, CC, CC, 0.f);
    ca_ln2<<<NTOK, 256>>>(ln2_g, ln2_b);
    tgemm<EPI_GELU><<<dim3(16, 98), 256, TGEMM_SMEM>>>(sk2r, ff1t, ff_b1, ffh, NTOK, 4 * CC, CC, 0.f);
    tgemm<EPI_NONE><<<dim3(4, 98), 256, TGEMM_SMEM>>>(ffh, ff2t, ff_b2, ffo, NTOK, CC, 2048, 0.f);
    final_kernel<<<BB * HWSZ, 256>>>(out, ln3_g, ln3_b);
}

// round 6
// speedup vs baseline: 1.0878x; 1.0336x over previous
#include <cuda_runtime.h>
#include <math.h>
#include <stdint.h>

// Problem constants
#define BB    8
#define CC    512
#define HH    56
#define WW_   56
#define HWSZ  3136
#define WS_   7
#define SS_   3
#define NH_   16
#define HD_   32
#define T_    49
#define NW_   64
#define BW_   512          // BB * NW_
#define NTOK  25088        // BW_ * T_
#define L_    64

// ---------------- scratch (device globals; no runtime alloc) ----------------
__device__ float g_vin [512 * 256];
__device__ float g_vec [BW_ * CC];
__device__ float g_tok [NTOK * CC];
__device__ float g_vis_t[NTOK * CC];        // visual in [B, HW, C] (full fp32)
__device__ float g_qkv [NTOK * 3 * CC];
__device__ float g_o1  [NTOK * CC];
__device__ float g_w2  [NTOK * CC];
__device__ float g_skipa[NTOK * CC];        // skip1 [B,HW,C] full fp32
__device__ float g_pq  [NTOK * CC];
__device__ float g_q2  [NTOK * CC];
__device__ float g_k2  [BW_ * CC];
__device__ float g_v2  [BW_ * CC];
__device__ float g_co1 [NTOK * CC];
__device__ float g_co2 [NTOK * CC];
__device__ float g_skip2[NTOK * CC];        // full fp32
__device__ float g_skip2r[NTOK * CC];       // tf32-rounded copy for GEMM
__device__ float g_ffh [NTOK * 4 * CC];
__device__ float g_ffo [NTOK * CC];
__device__ float g_res [NTOK * CC];         // final result in [B,HW,C]
__device__ float g_bias[NH_ * T_ * T_];

// transposed (and tf32-rounded) weights: [N, K] K-contiguous
__device__ float g_tmw_t  [512 * 256];
__device__ float g_qkvw_t [1536 * 512];
__device__ float g_wprw_t [512 * 512];
__device__ float g_cain_t [1536 * 512];
__device__ float g_caout_t[512 * 512];
__device__ float g_ff1_t  [2048 * 512];
__device__ float g_ff2_t  [512 * 2048];

// ---------------- helpers ----------------
__device__ __forceinline__ float gelu_exact(float x) {
    return 0.5f * x * (1.0f + erff(x * 0.70710678118654752f));
}
__device__ __forceinline__ float tf32r(float x) {
    uint32_t o;
    asm("cvt.rna.tf32.f32 %0, %1;" : "=r"(o) : "f"(x));
    return __uint_as_float(o);
}
__device__ __forceinline__ uint32_t s2u(const void* p) {
    uint32_t a;
    asm("{ .reg .u64 t; cvta.to.shared.u64 t, %1; cvt.u32.u64 %0, t; }"
        : "=r"(a) : "l"(p));
    return a;
}

__device__ __forceinline__ void block_meanvar(float s, float ss, int n,
                                              float* mu, float* rstd) {
    #pragma unroll
    for (int o = 16; o > 0; o >>= 1) {
        s  += __shfl_down_sync(0xffffffffu, s,  o);
        ss += __shfl_down_sync(0xffffffffu, ss, o);
    }
    __shared__ float rs[8], rss[8], res[2];
    int lane = threadIdx.x & 31, wid = threadIdx.x >> 5;
    if (lane == 0) { rs[wid] = s; rss[wid] = ss; }
    __syncthreads();
    if (threadIdx.x == 0) {
        float S = 0.f, SS2 = 0.f;
        #pragma unroll
        for (int i = 0; i < 8; i++) { S += rs[i]; SS2 += rss[i]; }
        float m = S / n;
        float var = SS2 / n - m * m;
        res[0] = m; res[1] = rsqrtf(var + 1e-5f);
    }
    __syncthreads();
    *mu = res[0]; *rstd = res[1];
}

// ---------------- tf32 mma.sync GEMM (exact R3 version) ----------------
// C[M,N] = epi(A[M,K] @ W[N,K]^T + bias), all tf32-rounded inputs.
// M%128==0, N%128==0, K%32==0.
#define EPI_NONE  0
#define EPI_GELU  1
#define EPI_SCALE 2

#define LDPAD 36
#define TILEF (128 * LDPAD)
#define TGEMM_SMEM (4 * TILEF * 4)

__device__ __forceinline__ void mma_tf32(float* c, const uint32_t* a,
                                         const uint32_t* b) {
    asm volatile(
        "mma.sync.aligned.m16n8k8.row.col.f32.tf32.tf32.f32 "
        "{%0,%1,%2,%3}, {%4,%5,%6,%7}, {%8,%9}, {%0,%1,%2,%3};"
        : "+f"(c[0]), "+f"(c[1]), "+f"(c[2]), "+f"(c[3])
        : "r"(a[0]), "r"(a[1]), "r"(a[2]), "r"(a[3]),
          "r"(b[0]), "r"(b[1]));
}

template <int EPI>
__global__ __launch_bounds__(256)
void tgemm(const float* __restrict__ A, const float* __restrict__ W,
           const float* __restrict__ bias, float* __restrict__ C,
           int M, int N, int K, float alpha) {
    extern __shared__ float smem[];
    float* Abuf = smem;                 // [2][128][LDPAD]
    float* Bbuf = smem + 2 * TILEF;     // [2][128][LDPAD]
    const uint32_t sm_a = s2u(Abuf), sm_b = s2u(Bbuf);

    const int tid = threadIdx.x;
    const int wid = tid >> 5, lane = tid & 31;
    const int m0 = blockIdx.y << 7, n0 = blockIdx.x << 7;
    const int wm = wid & 3, wn = wid >> 2;
    const int m_off = wm << 5;
    const int n_off = wn << 6;

    const float* Abase = A + (size_t)m0 * K;
    const float* Wbase = W + (size_t)n0 * K;
    const int NC = K >> 5;

    const int seg = tid & 7;
    const int lr0 = tid >> 3;

    auto load_chunk = [&](int c, int sel) {
        uint32_t ab = sm_a + sel * (TILEF * 4);
        uint32_t bb = sm_b + sel * (TILEF * 4);
        const float* As = Abase + c * 32 + seg * 4;
        const float* Ws = Wbase + c * 32 + seg * 4;
        #pragma unroll
        for (int i = 0; i < 4; i++) {
            int r = lr0 + (i << 5);
            uint32_t so = (uint32_t)(r * (LDPAD * 4) + seg * 16);
            asm volatile("cp.async.cg.shared.global [%0], [%1], 16;"
                         :: "r"(ab + so), "l"(As + (size_t)r * K));
            asm volatile("cp.async.cg.shared.global [%0], [%1], 16;"
                         :: "r"(bb + so), "l"(Ws + (size_t)r * K));
        }
    };

    float acc[2][8][4];
    #pragma unroll
    for (int i = 0; i < 2; i++)
        #pragma unroll
        for (int j = 0; j < 8; j++)
            #pragma unroll
            for (int q = 0; q < 4; q++) acc[i][j][q] = 0.f;

    load_chunk(0, 0);
    asm volatile("cp.async.commit_group;" ::: "memory");

    const int qr = lane >> 2, qc = lane & 3;

    for (int c = 0; c < NC; c++) {
        int sel = c & 1;
        if (c + 1 < NC) {
            load_chunk(c + 1, sel ^ 1);
            asm volatile("cp.async.commit_group;" ::: "memory");
            asm volatile("cp.async.wait_group 1;" ::: "memory");
        } else {
            asm volatile("cp.async.wait_group 0;" ::: "memory");
        }
        __syncthreads();

        const float* As = Abuf + sel * TILEF;
        const float* Bs = Bbuf + sel * TILEF;

        #pragma unroll
        for (int k0 = 0; k0 < 32; k0 += 8) {
            uint32_t a[2][4], b[8][2];
            #pragma unroll
            for (int mt = 0; mt < 2; mt++) {
                const float* ap = As + (m_off + mt * 16 + qr) * LDPAD + k0 + qc;
                a[mt][0] = __float_as_uint(ap[0]);
                a[mt][1] = __float_as_uint(ap[8 * LDPAD]);
                a[mt][2] = __float_as_uint(ap[4]);
                a[mt][3] = __float_as_uint(ap[8 * LDPAD + 4]);
            }
            #pragma unroll
            for (int nt = 0; nt < 8; nt++) {
                const float* bp = Bs + (n_off + nt * 8 + qr) * LDPAD + k0 + qc;
                b[nt][0] = __float_as_uint(bp[0]);
                b[nt][1] = __float_as_uint(bp[4]);
            }
            #pragma unroll
            for (int mt = 0; mt < 2; mt++)
                #pragma unroll
                for (int nt = 0; nt < 8; nt++)
                    mma_tf32(acc[mt][nt], a[mt], b[nt]);
        }
        __syncthreads();
    }

    // epilogue
    #pragma unroll
    for (int mt = 0; mt < 2; mt++) {
        #pragma unroll
        for (int half = 0; half < 2; half++) {
            int row = m0 + m_off + mt * 16 + qr + half * 8;
            float* Cp = C + (size_t)row * N + n0 + n_off;
            #pragma unroll
            for (int nt = 0; nt < 8; nt++) {
                int col = nt * 8 + qc * 2;
                float v0 = acc[mt][nt][half * 2 + 0] + bias[n0 + n_off + col];
                float v1 = acc[mt][nt][half * 2 + 1] + bias[n0 + n_off + col + 1];
                if (EPI == EPI_GELU)  { v0 = tf32r(gelu_exact(v0)); v1 = tf32r(gelu_exact(v1)); }
                if (EPI == EPI_SCALE) { v0 *= alpha; v1 *= alpha; }
                *(float2*)(Cp + col) = make_float2(v0, v1);
            }
        }
    }
}

// ---------------- weight transpose + tf32 round:  Wt[n,k] = rna(W[k,n]) ----
__global__ __launch_bounds__(256)
void transpose_w(const float* __restrict__ W, float* __restrict__ Wt,
                 int K, int N) {
    __shared__ float tile[32][33];
    int kb = blockIdx.y * 32, nb = blockIdx.x * 32;
    int tx = threadIdx.x & 31, ty = threadIdx.x >> 5;
    #pragma unroll
    for (int i = 0; i < 32; i += 8)
        tile[ty + i][tx] = W[(size_t)(kb + ty + i) * N + nb + tx];
    __syncthreads();
    #pragma unroll
    for (int i = 0; i < 32; i += 8)
        Wt[(size_t)(nb + ty + i) * K + kb + tx] = tf32r(tile[tx][ty + i]);
}

__global__ void round_copy(const float* __restrict__ in, float* __restrict__ o, int n) {
    int i = blockIdx.x * 256 + threadIdx.x;
    if (i < n) o[i] = tf32r(in[i]);
}

// ---------------- relative-position bias precompute ----------------
__global__ void bias_kernel(const float* __restrict__ w1, const float* __restrict__ b1,
                            const float* __restrict__ w2, const float* __restrict__ b2) {
    int pair = blockIdx.x;
    int q = pair / T_, k = pair % T_;
    float d0 = (float)(q / WS_ - k / WS_);
    float d1 = (float)(q % WS_ - k % WS_);
    float r0 = (d0 > 0.f ? 1.f : (d0 < 0.f ? -1.f : 0.f)) * log1pf(fabsf(d0));
    float r1 = (d1 > 0.f ? 1.f : (d1 < 0.f ? -1.f : 0.f)) * log1pf(fabsf(d1));
    int tid = threadIdx.x;
    __shared__ float hbuf[256];
    float hv = r0 * w1[tid] + r1 * w1[256 + tid] + b1[tid];
    hbuf[tid] = fmaxf(hv, 0.f);
    __syncthreads();
    if (tid < NH_) {
        float s = b2[tid];
        #pragma unroll 8
        for (int j = 0; j < 256; j++) s += hbuf[j] * w2[j * NH_ + tid];
        g_bias[tid * (T_ * T_) + pair] = s;
    }
}

// ---------------- visual [B,C,HW] -> vis_t [B,HW,C] + g_tok (rolled/unfold) -
// Tiled transpose: both global accesses coalesced.
__global__ __launch_bounds__(256)
void transpose_in(const float* __restrict__ visual) {
    __shared__ float tile[32][33];
    int b = blockIdx.z;
    int cb = blockIdx.y * 32, hwb = blockIdx.x * 32;
    int tx = threadIdx.x & 31, ty = threadIdx.x >> 5;   // 32 x 8
    #pragma unroll
    for (int i = 0; i < 32; i += 8)
        tile[ty + i][tx] = visual[(size_t)(b * CC + cb + ty + i) * HWSZ + hwb + tx];
    __syncthreads();
    #pragma unroll
    for (int i = 0; i < 32; i += 8) {
        int hw = hwb + ty + i;
        float v = tile[tx][ty + i];
        g_vis_t[(size_t)(b * HWSZ + hw) * CC + cb + tx] = v;
        // token row: inverse roll (-3,-3): h' = (h+53)%56
        int h = hw / WW_, w = hw % WW_;
        int hp = (h + HH - SS_) % HH, wp = (w + WW_ - SS_) % WW_;
        int r = (b * NW_ + (hp / WS_) * 8 + (wp / WS_)) * T_
              + (hp % WS_) * WS_ + (wp % WS_);
        g_tok[(size_t)r * CC + cb + tx] = tf32r(v);
    }
}

// ---------------- g_res [B,HW,C] -> out [B,C,HW] ----------------
__global__ __launch_bounds__(256)
void transpose_out(float* __restrict__ out) {
    __shared__ float tile[32][33];
    int b = blockIdx.z;
    int cb = blockIdx.y * 32, hwb = blockIdx.x * 32;
    int tx = threadIdx.x & 31, ty = threadIdx.x >> 5;
    #pragma unroll
    for (int i = 0; i < 32; i += 8)
        tile[ty + i][tx] = g_res[(size_t)(b * HWSZ + hwb + ty + i) * CC + cb + tx];
    __syncthreads();
    #pragma unroll
    for (int i = 0; i < 32; i += 8)
        out[(size_t)(b * CC + cb + ty + i) * HWSZ + hwb + tx] = tile[tx][ty + i];
}

// ---------------- window attention (vectorized) ----------------
__global__ __launch_bounds__(256)
void win_attn(const float* __restrict__ tau) {
    int bw = blockIdx.x >> 4;
    int hh = blockIdx.x & 15;
    int tid = threadIdx.x;

    __shared__ __align__(16) float sq[T_ * HD_], sk[T_ * HD_], sv[T_ * HD_];
    __shared__ float ss[T_ * 50];
    __shared__ float nq[T_], nk[T_];
    __shared__ int   rg[T_];

    size_t base = (size_t)(bw * T_) * (3 * CC) + hh * HD_;
    for (int idx = tid; idx < T_ * 8; idx += 256) {
        int t = idx >> 3, d4 = idx & 7;
        const float* ro = g_qkv + base + (size_t)t * (3 * CC) + d4 * 4;
        ((float4*)sq)[t * 8 + d4] = *(const float4*)(ro);
        ((float4*)sk)[t * 8 + d4] = *(const float4*)(ro + CC);
        ((float4*)sv)[t * 8 + d4] = *(const float4*)(ro + 2 * CC);
    }
    int win = bw & 63, wh = win >> 3, ww = win & 7;
    if (tid < T_) {
        int row = wh * WS_ + tid / WS_;
        int col = ww * WS_ + tid % WS_;
        int rh = row < 49 ? 0 : (row < 53 ? 1 : 2);
        int rw = col < 49 ? 0 : (col < 53 ? 1 : 2);
        rg[tid] = rh * 3 + rw;
    }
    __syncthreads();

    if (tid < T_) {
        float4 s1 = make_float4(0.f, 0.f, 0.f, 0.f), s2 = s1;
        #pragma unroll
        for (int d4 = 0; d4 < 8; d4++) {
            float4 a = ((float4*)sq)[tid * 8 + d4];
            float4 b = ((float4*)sk)[tid * 8 + d4];
            s1.x += a.x * a.x; s1.y += a.y * a.y; s1.z += a.z * a.z; s1.w += a.w * a.w;
            s2.x += b.x * b.x; s2.y += b.y * b.y; s2.z += b.z * b.z; s2.w += b.w * b.w;
        }
        nq[tid] = sqrtf(s1.x + s1.y + s1.z + s1.w);
        nk[tid] = sqrtf(s2.x + s2.y + s2.z + s2.w);
    }
    __syncthreads();

    float tauh = fmaxf(tau[hh], 0.01f);
    const float* bh = &g_bias[hh * (T_ * T_)];
    for (int idx = tid; idx < T_ * T_; idx += 256) {
        int q = idx / T_, k = idx % T_;
        float4 d4a = make_float4(0.f, 0.f, 0.f, 0.f);
        #pragma unroll
        for (int d4 = 0; d4 < 8; d4++) {
            float4 a = ((float4*)sq)[q * 8 + d4];
            float4 b = ((float4*)sk)[k * 8 + d4];
            d4a.x += a.x * b.x; d4a.y += a.y * b.y;
            d4a.z += a.z * b.z; d4a.w += a.w * b.w;
        }
        float dot = d4a.x + d4a.y + d4a.z + d4a.w;
        float s = dot / fmaxf(nq[q] * nk[k], 1e-6f) / tauh + bh[idx];
        if (rg[q] != rg[k]) s -= 100.0f;
        ss[q * 50 + k] = s;
    }
    __syncthreads();

    if (tid < T_) {
        float m = -1e30f;
        for (int k = 0; k < T_; k++) m = fmaxf(m, ss[tid * 50 + k]);
        float sum = 0.f;
        for (int k = 0; k < T_; k++) {
            float e = expf(ss[tid * 50 + k] - m);
            ss[tid * 50 + k] = e; sum += e;
        }
        float inv = 1.f / sum;
        for (int k = 0; k < T_; k++) ss[tid * 50 + k] *= inv;
    }
    __syncthreads();

    for (int idx = tid; idx < T_ * 8; idx += 256) {
        int t = idx >> 3, d4 = idx & 7;
        float4 acc = make_float4(0.f, 0.f, 0.f, 0.f);
        #pragma unroll
        for (int k = 0; k < T_; k++) {
            float s = ss[t * 50 + k];
            float4 v = ((float4*)sv)[k * 8 + d4];
            acc.x += s * v.x; acc.y += s * v.y; acc.z += s * v.z; acc.w += s * v.w;
        }
        float4 o = make_float4(tf32r(acc.x), tf32r(acc.y), tf32r(acc.z), tf32r(acc.w));
        *(float4*)(g_o1 + (size_t)(bw * T_ + t) * CC + hh * HD_ + d4 * 4) = o;
    }
}

// ---------------- fold+roll(+3) + LN1 + residual; emit CA query tokens ------
__global__ __launch_bounds__(256)
void merge_ln1(const float* __restrict__ g, const float* __restrict__ bt) {
    int pos = blockIdx.x;
    int b = pos / HWSZ, hw = pos % HWSZ;
    int h = hw / WW_, w = hw % WW_;
    int hp = (h + HH - SS_) % HH, wp = (w + WW_ - SS_) % WW_;
    int rm = (b * NW_ + (hp / WS_) * 8 + (wp / WS_)) * T_ + (hp % WS_) * WS_ + (wp % WS_);

    __shared__ float x[CC];
    int tid = threadIdx.x;
    float s = 0.f, ss2 = 0.f;
    for (int c = tid; c < CC; c += 256) {
        float v = g_w2[(size_t)rm * CC + c];
        x[c] = v; s += v; ss2 += v * v;
    }
    float mu, rstd;
    block_meanvar(s, ss2, CC, &mu, &rstd);
    for (int c = tid; c < CC; c += 256) {
        float v = (x[c] - mu) * rstd * g[c] + bt[c]
                + g_vis_t[(size_t)pos * CC + c];
        g_skipa[(size_t)pos * CC + c] = v;
        g_pq  [(size_t)rm  * CC + c] = tf32r(v);
    }
}

// ---------------- cross attention (vectorized) ----------------
__global__ __launch_bounds__(256)
void ca_attn() {
    int bw = blockIdx.x >> 4;
    int hh = blockIdx.x & 15;
    int bkv = bw & 7;
    int tid = threadIdx.x;

    __shared__ __align__(16) float sq[T_ * HD_], sk[L_ * HD_], sv[L_ * HD_];
    __shared__ float ss[T_ * 65];

    for (int idx = tid; idx < T_ * 8; idx += 256) {
        int t = idx >> 3, d4 = idx & 7;
        ((float4*)sq)[t * 8 + d4] =
            *(const float4*)(g_q2 + (size_t)(bw * T_ + t) * CC + hh * HD_ + d4 * 4);
    }
    for (int idx = tid; idx < L_ * 8; idx += 256) {
        int l = idx >> 3, d4 = idx & 7;
        size_t ro = (size_t)(bkv * L_ + l) * CC + hh * HD_ + d4 * 4;
        ((float4*)sk)[l * 8 + d4] = *(const float4*)(g_k2 + ro);
        ((float4*)sv)[l * 8 + d4] = *(const float4*)(g_v2 + ro);
    }
    __syncthreads();

    for (int idx = tid; idx < T_ * L_; idx += 256) {
        int q = idx / L_, l = idx % L_;
        float4 d4a = make_float4(0.f, 0.f, 0.f, 0.f);
        #pragma unroll
        for (int d4 = 0; d4 < 8; d4++) {
            float4 a = ((float4*)sq)[q * 8 + d4];
            float4 b = ((float4*)sk)[l * 8 + d4];
            d4a.x += a.x * b.x; d4a.y += a.y * b.y;
            d4a.z += a.z * b.z; d4a.w += a.w * b.w;
        }
        ss[q * 65 + l] = d4a.x + d4a.y + d4a.z + d4a.w;
    }
    __syncthreads();

    if (tid < T_) {
        float m = -1e30f;
        for (int l = 0; l < L_; l++) m = fmaxf(m, ss[tid * 65 + l]);
        float sum = 0.f;
        for (int l = 0; l < L_; l++) {
            float e = expf(ss[tid * 65 + l] - m);
            ss[tid * 65 + l] = e; sum += e;
        }
        float inv = 1.f / sum;
        for (int l = 0; l < L_; l++) ss[tid * 65 + l] *= inv;
    }
    __syncthreads();

    for (int idx = tid; idx < T_ * 8; idx += 256) {
        int t = idx >> 3, d4 = idx & 7;
        float4 acc = make_float4(0.f, 0.f, 0.f, 0.f);
        #pragma unroll
        for (int l = 0; l < L_; l++) {
            float s = ss[t * 65 + l];
            float4 v = ((float4*)sv)[l * 8 + d4];
            acc.x += s * v.x; acc.y += s * v.y; acc.z += s * v.z; acc.w += s * v.w;
        }
        float4 o = make_float4(tf32r(acc.x), tf32r(acc.y), tf32r(acc.z), tf32r(acc.w));
        *(float4*)(g_co1 + (size_t)(bw * T_ + t) * CC + hh * HD_ + d4 * 4) = o;
    }
}

// ---------------- LN2 + fold+roll(+3) + residual ----------------
__global__ __launch_bounds__(256)
void ca_ln2(const float* __restrict__ g, const float* __restrict__ bt) {
    int r = blockIdx.x;
    int bw = r / T_, t = r % T_;
    int b = bw / NW_, win = bw % NW_, wh = win >> 3, ww = win & 7;
    int h = (wh * WS_ + t / WS_ + SS_) % HH;
    int w = (ww * WS_ + t % WS_ + SS_) % WW_;
    int pos = b * HWSZ + h * WW_ + w;

    __shared__ float x[CC];
    int tid = threadIdx.x;
    float s = 0.f, ss2 = 0.f;
    for (int c = tid; c < CC; c += 256) {
        float v = g_co2[(size_t)r * CC + c];
        x[c] = v; s += v; ss2 += v * v;
    }
    float mu, rstd;
    block_meanvar(s, ss2, CC, &mu, &rstd);
    for (int c = tid; c < CC; c += 256) {
        float v = (x[c] - mu) * rstd * g[c] + bt[c]
                + g_skipa[(size_t)pos * CC + c];
        g_skip2 [(size_t)pos * CC + c] = v;
        g_skip2r[(size_t)pos * CC + c] = tf32r(v);
    }
}

// ---------------- LN3(ff) + skip2 -> g_res [B,HW,C] ----------------
__global__ __launch_bounds__(256)
void final_kernel(const float* __restrict__ g, const float* __restrict__ bt) {
    int pos = blockIdx.x;

    __shared__ float x[CC];
    int tid = threadIdx.x;
    float s = 0.f, ss2 = 0.f;
    for (int c = tid; c < CC; c += 256) {
        float v = g_ffo[(size_t)pos * CC + c];
        x[c] = v; s += v; ss2 += v * v;
    }
    float mu, rstd;
    block_meanvar(s, ss2, CC, &mu, &rstd);
    for (int c = tid; c < CC; c += 256) {
        float v = (x[c] - mu) * rstd * g[c] + bt[c];
        g_res[(size_t)pos * CC + c] = g_skip2[(size_t)pos * CC + c] + v;
    }
}

// ---------------- launch ----------------
extern "C" void kernel_launch(void* const* d_in, const int* in_sizes, int n_in,
                              void* d_out, int out_size) {
    const float* visual   = (const float*)d_in[0];
    const float* vector   = (const float*)d_in[1];
    const float* tm_w     = (const float*)d_in[2];
    const float* tm_b     = (const float*)d_in[3];
    const float* ln1_g    = (const float*)d_in[4];
    const float* ln1_b    = (const float*)d_in[5];
    const float* ln2_g    = (const float*)d_in[6];
    const float* ln2_b    = (const float*)d_in[7];
    const float* ln3_g    = (const float*)d_in[8];
    const float* ln3_b    = (const float*)d_in[9];
    const float* qkv_w    = (const float*)d_in[10];
    const float* qkv_b    = (const float*)d_in[11];
    const float* wproj_w  = (const float*)d_in[12];
    const float* wproj_b  = (const float*)d_in[13];
    const float* meta_w1  = (const float*)d_in[14];
    const float* meta_b1  = (const float*)d_in[15];
    const float* meta_w2  = (const float*)d_in[16];
    const float* meta_b2  = (const float*)d_in[17];
    const float* tau      = (const float*)d_in[18];
    const float* ca_in_w  = (const float*)d_in[19];
    const float* ca_in_b  = (const float*)d_in[20];
    const float* ca_out_w = (const float*)d_in[21];
    const float* ca_out_b = (const float*)d_in[22];
    const float* ff_w1    = (const float*)d_in[23];
    const float* ff_b1    = (const float*)d_in[24];
    const float* ff_w2    = (const float*)d_in[25];
    const float* ff_b2    = (const float*)d_in[26];
    float* out = (float*)d_out;

    float *vin, *vec, *tok, *qkv, *o1, *w2, *pq, *q2, *k2, *v2, *co1, *co2,
          *sk2r, *ffh, *ffo;
    float *tmwt, *qkvwt, *wprwt, *caint, *caoutt, *ff1t, *ff2t;
    cudaGetSymbolAddress((void**)&vin,   g_vin);
    cudaGetSymbolAddress((void**)&vec,   g_vec);
    cudaGetSymbolAddress((void**)&tok,   g_tok);
    cudaGetSymbolAddress((void**)&qkv,   g_qkv);
    cudaGetSymbolAddress((void**)&o1,    g_o1);
    cudaGetSymbolAddress((void**)&w2,    g_w2);
    cudaGetSymbolAddress((void**)&pq,    g_pq);
    cudaGetSymbolAddress((void**)&q2,    g_q2);
    cudaGetSymbolAddress((void**)&k2,    g_k2);
    cudaGetSymbolAddress((void**)&v2,    g_v2);
    cudaGetSymbolAddress((void**)&co1,   g_co1);
    cudaGetSymbolAddress((void**)&co2,   g_co2);
    cudaGetSymbolAddress((void**)&sk2r,  g_skip2r);
    cudaGetSymbolAddress((void**)&ffh,   g_ffh);
    cudaGetSymbolAddress((void**)&ffo,   g_ffo);
    cudaGetSymbolAddress((void**)&tmwt,  g_tmw_t);
    cudaGetSymbolAddress((void**)&qkvwt, g_qkvw_t);
    cudaGetSymbolAddress((void**)&wprwt, g_wprw_t);
    cudaGetSymbolAddress((void**)&caint, g_cain_t);
    cudaGetSymbolAddress((void**)&caoutt,g_caout_t);
    cudaGetSymbolAddress((void**)&ff1t,  g_ff1_t);
    cudaGetSymbolAddress((void**)&ff2t,  g_ff2_t);

    cudaFuncSetAttribute(tgemm<EPI_NONE>,  cudaFuncAttributeMaxDynamicSharedMemorySize, TGEMM_SMEM);
    cudaFuncSetAttribute(tgemm<EPI_GELU>,  cudaFuncAttributeMaxDynamicSharedMemorySize, TGEMM_SMEM);
    cudaFuncSetAttribute(tgemm<EPI_SCALE>, cudaFuncAttributeMaxDynamicSharedMemorySize, TGEMM_SMEM);

    // weight transposes (+tf32 rounding)
    transpose_w<<<dim3(16,  8), 256>>>(tm_w,     tmwt,  256,  512);
    transpose_w<<<dim3(48, 16), 256>>>(qkv_w,    qkvwt, 512, 1536);
    transpose_w<<<dim3(16, 16), 256>>>(wproj_w,  wprwt, 512,  512);
    transpose_w<<<dim3(48, 16), 256>>>(ca_in_w,  caint, 512, 1536);
    transpose_w<<<dim3(16, 16), 256>>>(ca_out_w, caoutt,512,  512);
    transpose_w<<<dim3(64, 16), 256>>>(ff_w1,    ff1t,  512, 2048);
    transpose_w<<<dim3(16, 64), 256>>>(ff_w2,    ff2t, 2048,  512);
    round_copy<<<512, 256>>>(vector, vin, 512 * 256);

    bias_kernel<<<T_ * T_, 256>>>(meta_w1, meta_b1, meta_w2, meta_b2);

    // vec = gelu(vector @ tm_w + tm_b)
    tgemm<EPI_GELU><<<dim3(4, 4), 256, TGEMM_SMEM>>>(vin, tmwt, tm_b, vec, 512, 512, 256, 0.f);
    // K2/V2 (only B distinct kv sets)
    tgemm<EPI_NONE><<<dim3(4, 4), 256, TGEMM_SMEM>>>(vec, caint + 512 * 512,  ca_in_b + 512,  k2, 512, 512, 512, 0.f);
    tgemm<EPI_NONE><<<dim3(4, 4), 256, TGEMM_SMEM>>>(vec, caint + 1024 * 512, ca_in_b + 1024, v2, 512, 512, 512, 0.f);

    // visual transpose + roll/unfold tokens (coalesced both sides)
    transpose_in<<<dim3(98, 16, BB), 256>>>(visual);

    tgemm<EPI_NONE><<<dim3(12, 196), 256, TGEMM_SMEM>>>(tok, qkvwt, qkv_b, qkv, NTOK, 3 * CC, CC, 0.f);
    win_attn<<<BW_ * NH_, 256>>>(tau);
    tgemm<EPI_NONE><<<dim3(4, 196), 256, TGEMM_SMEM>>>(o1, wprwt, wproj_b, w2, NTOK, CC, CC, 0.f);
    merge_ln1<<<BB * HWSZ, 256>>>(ln1_g, ln1_b);
    tgemm<EPI_SCALE><<<dim3(4, 196), 256, TGEMM_SMEM>>>(pq, caint, ca_in_b, q2, NTOK, CC, CC, 0.17677669529663687f);
    ca_attn<<<BW_ * NH_, 256>>>();
    tgemm<EPI_NONE><<<dim3(4, 196), 256, TGEMM_SMEM>>>(co1, caoutt, ca_out_b, co2, NTOK, CC, CC, 0.f);
    ca_ln2<<<NTOK, 256>>>(ln2_g, ln2_b);
    tgemm<EPI_GELU><<<dim3(16, 196), 256, TGEMM_SMEM>>>(sk2r, ff1t, ff_b1, ffh, NTOK, 4 * CC, CC, 0.f);
    tgemm<EPI_NONE><<<dim3(4, 196), 256, TGEMM_SMEM>>>(ffh, ff2t, ff_b2, ffo, NTOK, CC, 2048, 0.f);
    final_kernel<<<BB * HWSZ, 256>>>(ln3_g, ln3_b);
    transpose_out<<<dim3(98, 16, BB), 256>>>(out);
}

// round 7
// speedup vs baseline: 1.2103x; 1.1126x over previous
#include <cuda_runtime.h>
#include <math.h>
#include <stdint.h>

// Problem constants
#define BB    8
#define CC    512
#define HH    56
#define WW_   56
#define HWSZ  3136
#define WS_   7
#define SS_   3
#define NH_   16
#define HD_   32
#define T_    49
#define NW_   64
#define BW_   512          // BB * NW_
#define NTOK  25088        // BW_ * T_
#define L_    64

// ---------------- scratch (device globals; no runtime alloc) ----------------
__device__ float g_vin [512 * 256];
__device__ float g_vec [BW_ * CC];
__device__ float g_tok [NTOK * CC];
__device__ float g_qkv [NTOK * 3 * CC];
__device__ float g_o1  [NTOK * CC];
__device__ float g_w2  [NTOK * CC];
__device__ float g_skipa[NTOK * CC];        // skip1 [B,HW,C] full fp32
__device__ float g_pq  [NTOK * CC];
__device__ float g_q2  [NTOK * CC];
__device__ float g_k2  [BW_ * CC];
__device__ float g_v2  [BW_ * CC];
__device__ float g_co1 [NTOK * CC];
__device__ float g_co2 [NTOK * CC];
__device__ float g_skip2[NTOK * CC];        // full fp32
__device__ float g_skip2r[NTOK * CC];       // tf32-rounded copy for GEMM
__device__ float g_ffh [NTOK * 4 * CC];
__device__ float g_ffo [NTOK * CC];
__device__ float g_bias[NH_ * T_ * T_];

// transposed (and tf32-rounded) weights: [N, K] K-contiguous
__device__ float g_tmw_t  [512 * 256];
__device__ float g_qkvw_t [1536 * 512];
__device__ float g_wprw_t [512 * 512];
__device__ float g_cain_t [1536 * 512];
__device__ float g_caout_t[512 * 512];
__device__ float g_ff1_t  [2048 * 512];
__device__ float g_ff2_t  [512 * 2048];

// ---------------- helpers ----------------
__device__ __forceinline__ float gelu_exact(float x) {
    return 0.5f * x * (1.0f + erff(x * 0.70710678118654752f));
}
__device__ __forceinline__ float tf32r(float x) {
    uint32_t o;
    asm("cvt.rna.tf32.f32 %0, %1;" : "=r"(o) : "f"(x));
    return __uint_as_float(o);
}
__device__ __forceinline__ uint32_t s2u(const void* p) {
    uint32_t a;
    asm("{ .reg .u64 t; cvta.to.shared.u64 t, %1; cvt.u32.u64 %0, t; }"
        : "=r"(a) : "l"(p));
    return a;
}

__device__ __forceinline__ void block_meanvar(float s, float ss, int n,
                                              float* mu, float* rstd) {
    #pragma unroll
    for (int o = 16; o > 0; o >>= 1) {
        s  += __shfl_down_sync(0xffffffffu, s,  o);
        ss += __shfl_down_sync(0xffffffffu, ss, o);
    }
    __shared__ float rs[8], rss[8], res[2];
    int lane = threadIdx.x & 31, wid = threadIdx.x >> 5;
    if (lane == 0) { rs[wid] = s; rss[wid] = ss; }
    __syncthreads();
    if (threadIdx.x == 0) {
        float S = 0.f, SS2 = 0.f;
        #pragma unroll
        for (int i = 0; i < 8; i++) { S += rs[i]; SS2 += rss[i]; }
        float m = S / n;
        float var = SS2 / n - m * m;
        res[0] = m; res[1] = rsqrtf(var + 1e-5f);
    }
    __syncthreads();
    *mu = res[0]; *rstd = res[1];
}

// ---------------- tf32 mma.sync GEMM (R3 math, 3-stage pipeline) -----------
// C[M,N] = epi(A[M,K] @ W[N,K]^T + bias), all tf32-rounded inputs.
// M%128==0, N%128==0, K%32==0.
#define EPI_NONE  0
#define EPI_GELU  1
#define EPI_SCALE 2

#define LDPAD 36
#define TILEF (128 * LDPAD)
#define TGEMM_SMEM (6 * TILEF * 4)      // 3 stages x (A + B) = 110592 bytes

__device__ __forceinline__ void mma_tf32(float* c, const uint32_t* a,
                                         const uint32_t* b) {
    asm volatile(
        "mma.sync.aligned.m16n8k8.row.col.f32.tf32.tf32.f32 "
        "{%0,%1,%2,%3}, {%4,%5,%6,%7}, {%8,%9}, {%0,%1,%2,%3};"
        : "+f"(c[0]), "+f"(c[1]), "+f"(c[2]), "+f"(c[3])
        : "r"(a[0]), "r"(a[1]), "r"(a[2]), "r"(a[3]),
          "r"(b[0]), "r"(b[1]));
}

template <int EPI>
__global__ __launch_bounds__(256)
void tgemm(const float* __restrict__ A, const float* __restrict__ W,
           const float* __restrict__ bias, float* __restrict__ C,
           int M, int N, int K, float alpha) {
    extern __shared__ float smem[];
    float* Abuf = smem;                 // [3][128][LDPAD]
    float* Bbuf = smem + 3 * TILEF;     // [3][128][LDPAD]
    const uint32_t sm_a = s2u(Abuf), sm_b = s2u(Bbuf);

    const int tid = threadIdx.x;
    const int wid = tid >> 5, lane = tid & 31;
    const int m0 = blockIdx.y << 7, n0 = blockIdx.x << 7;
    const int wm = wid & 3, wn = wid >> 2;
    const int m_off = wm << 5;
    const int n_off = wn << 6;

    const float* Abase = A + (size_t)m0 * K;
    const float* Wbase = W + (size_t)n0 * K;
    const int NC = K >> 5;

    const int seg = tid & 7;
    const int lr0 = tid >> 3;

    auto load_chunk = [&](int c, int sel) {
        uint32_t ab = sm_a + sel * (TILEF * 4);
        uint32_t bb = sm_b + sel * (TILEF * 4);
        const float* As = Abase + c * 32 + seg * 4;
        const float* Ws = Wbase + c * 32 + seg * 4;
        #pragma unroll
        for (int i = 0; i < 4; i++) {
            int r = lr0 + (i << 5);
            uint32_t so = (uint32_t)(r * (LDPAD * 4) + seg * 16);
            asm volatile("cp.async.cg.shared.global [%0], [%1], 16;"
                         :: "r"(ab + so), "l"(As + (size_t)r * K));
            asm volatile("cp.async.cg.shared.global [%0], [%1], 16;"
                         :: "r"(bb + so), "l"(Ws + (size_t)r * K));
        }
        asm volatile("cp.async.commit_group;" ::: "memory");
    };

    float acc[2][8][4];
    #pragma unroll
    for (int i = 0; i < 2; i++)
        #pragma unroll
        for (int j = 0; j < 8; j++)
            #pragma unroll
            for (int q = 0; q < 4; q++) acc[i][j][q] = 0.f;

    // prefetch 2 chunks (3-stage ring, distance 2)
    load_chunk(0, 0);
    if (NC > 1) load_chunk(1, 1);

    const int qr = lane >> 2, qc = lane & 3;
    int sel = 0;

    for (int c = 0; c < NC; c++) {
        // ensure chunk c has arrived (allow chunk c+1 in flight)
        if (c + 1 < NC)
            asm volatile("cp.async.wait_group 1;" ::: "memory");
        else
            asm volatile("cp.async.wait_group 0;" ::: "memory");
        // all warps done reading the buffer that chunk c+2 will overwrite
        __syncthreads();
        if (c + 2 < NC) {
            int s2 = sel + 2; if (s2 >= 3) s2 -= 3;
            load_chunk(c + 2, s2);
        }

        const float* As = Abuf + sel * TILEF;
        const float* Bs = Bbuf + sel * TILEF;

        #pragma unroll
        for (int k0 = 0; k0 < 32; k0 += 8) {
            uint32_t a[2][4], b[8][2];
            #pragma unroll
            for (int mt = 0; mt < 2; mt++) {
                const float* ap = As + (m_off + mt * 16 + qr) * LDPAD + k0 + qc;
                a[mt][0] = __float_as_uint(ap[0]);
                a[mt][1] = __float_as_uint(ap[8 * LDPAD]);
                a[mt][2] = __float_as_uint(ap[4]);
                a[mt][3] = __float_as_uint(ap[8 * LDPAD + 4]);
            }
            #pragma unroll
            for (int nt = 0; nt < 8; nt++) {
                const float* bp = Bs + (n_off + nt * 8 + qr) * LDPAD + k0 + qc;
                b[nt][0] = __float_as_uint(bp[0]);
                b[nt][1] = __float_as_uint(bp[4]);
            }
            #pragma unroll
            for (int mt = 0; mt < 2; mt++)
                #pragma unroll
                for (int nt = 0; nt < 8; nt++)
                    mma_tf32(acc[mt][nt], a[mt], b[nt]);
        }
        if (++sel >= 3) sel = 0;
    }

    // epilogue
    #pragma unroll
    for (int mt = 0; mt < 2; mt++) {
        #pragma unroll
        for (int half = 0; half < 2; half++) {
            int row = m0 + m_off + mt * 16 + qr + half * 8;
            float* Cp = C + (size_t)row * N + n0 + n_off;
            #pragma unroll
            for (int nt = 0; nt < 8; nt++) {
                int col = nt * 8 + qc * 2;
                float v0 = acc[mt][nt][half * 2 + 0] + bias[n0 + n_off + col];
                float v1 = acc[mt][nt][half * 2 + 1] + bias[n0 + n_off + col + 1];
                if (EPI == EPI_GELU)  { v0 = tf32r(gelu_exact(v0)); v1 = tf32r(gelu_exact(v1)); }
                if (EPI == EPI_SCALE) { v0 *= alpha; v1 *= alpha; }
                *(float2*)(Cp + col) = make_float2(v0, v1);
            }
        }
    }
}

// ---------------- weight transpose + tf32 round:  Wt[n,k] = rna(W[k,n]) ----
__global__ __launch_bounds__(256)
void transpose_w(const float* __restrict__ W, float* __restrict__ Wt,
                 int K, int N) {
    __shared__ float tile[32][33];
    int kb = blockIdx.y * 32, nb = blockIdx.x * 32;
    int tx = threadIdx.x & 31, ty = threadIdx.x >> 5;
    #pragma unroll
    for (int i = 0; i < 32; i += 8)
        tile[ty + i][tx] = W[(size_t)(kb + ty + i) * N + nb + tx];
    __syncthreads();
    #pragma unroll
    for (int i = 0; i < 32; i += 8)
        Wt[(size_t)(nb + ty + i) * K + kb + tx] = tf32r(tile[tx][ty + i]);
}

__global__ void round_copy(const float* __restrict__ in, float* __restrict__ o, int n) {
    int i = blockIdx.x * 256 + threadIdx.x;
    if (i < n) o[i] = tf32r(in[i]);
}

// ---------------- relative-position bias precompute ----------------
__global__ void bias_kernel(const float* __restrict__ w1, const float* __restrict__ b1,
                            const float* __restrict__ w2, const float* __restrict__ b2) {
    int pair = blockIdx.x;
    int q = pair / T_, k = pair % T_;
    float d0 = (float)(q / WS_ - k / WS_);
    float d1 = (float)(q % WS_ - k % WS_);
    float r0 = (d0 > 0.f ? 1.f : (d0 < 0.f ? -1.f : 0.f)) * log1pf(fabsf(d0));
    float r1 = (d1 > 0.f ? 1.f : (d1 < 0.f ? -1.f : 0.f)) * log1pf(fabsf(d1));
    int tid = threadIdx.x;
    __shared__ float hbuf[256];
    float hv = r0 * w1[tid] + r1 * w1[256 + tid] + b1[tid];
    hbuf[tid] = fmaxf(hv, 0.f);
    __syncthreads();
    if (tid < NH_) {
        float s = b2[tid];
        #pragma unroll 8
        for (int j = 0; j < 256; j++) s += hbuf[j] * w2[j * NH_ + tid];
        g_bias[tid * (T_ * T_) + pair] = s;
    }
}

// ---------------- roll(-3,-3) + unfold into token rows (tf32) ---------------
__global__ __launch_bounds__(256)
void unfold_kernel(const float* __restrict__ visual) {
    int r = blockIdx.x;
    int bw = r / T_, t = r % T_;
    int b = bw / NW_, win = bw % NW_, wh = win >> 3, ww = win & 7;
    int h = (wh * WS_ + t / WS_ + SS_) % HH;
    int w = (ww * WS_ + t % WS_ + SS_) % WW_;
    int hw = h * WW_ + w;
    for (int c = threadIdx.x; c < CC; c += 256)
        g_tok[(size_t)r * CC + c] = tf32r(visual[(size_t)(b * CC + c) * HWSZ + hw]);
}

// ---------------- window attention ----------------
__global__ __launch_bounds__(256)
void win_attn(const float* __restrict__ tau) {
    int bw = blockIdx.x >> 4;
    int hh = blockIdx.x & 15;
    int tid = threadIdx.x;

    __shared__ float sq[T_ * HD_], sk[T_ * HD_], sv[T_ * HD_];
    __shared__ float ss[T_ * 50];
    __shared__ float nq[T_], nk[T_];
    __shared__ int   rg[T_];

    size_t base = (size_t)(bw * T_) * (3 * CC);
    for (int idx = tid; idx < T_ * HD_; idx += 256) {
        int t = idx / HD_, d = idx % HD_;
        size_t ro = base + (size_t)t * (3 * CC) + hh * HD_ + d;
        sq[idx] = g_qkv[ro];
        sk[idx] = g_qkv[ro + CC];
        sv[idx] = g_qkv[ro + 2 * CC];
    }
    int win = bw & 63, wh = win >> 3, ww = win & 7;
    if (tid < T_) {
        int row = wh * WS_ + tid / WS_;
        int col = ww * WS_ + tid % WS_;
        int rh = row < 49 ? 0 : (row < 53 ? 1 : 2);
        int rw = col < 49 ? 0 : (col < 53 ? 1 : 2);
        rg[tid] = rh * 3 + rw;
    }
    __syncthreads();

    if (tid < T_) {
        float s1 = 0.f, s2 = 0.f;
        #pragma unroll
        for (int d = 0; d < HD_; d++) {
            float a = sq[tid * HD_ + d], b = sk[tid * HD_ + d];
            s1 += a * a; s2 += b * b;
        }
        nq[tid] = sqrtf(s1); nk[tid] = sqrtf(s2);
    }
    __syncthreads();

    float tauh = fmaxf(tau[hh], 0.01f);
    const float* bh = &g_bias[hh * (T_ * T_)];
    for (int idx = tid; idx < T_ * T_; idx += 256) {
        int q = idx / T_, k = idx % T_;
        float dot = 0.f;
        #pragma unroll
        for (int d = 0; d < HD_; d++) dot += sq[q * HD_ + d] * sk[k * HD_ + d];
        float s = dot / fmaxf(nq[q] * nk[k], 1e-6f) / tauh + bh[idx];
        if (rg[q] != rg[k]) s -= 100.0f;
        ss[q * 50 + k] = s;
    }
    __syncthreads();

    if (tid < T_) {
        float m = -1e30f;
        for (int k = 0; k < T_; k++) m = fmaxf(m, ss[tid * 50 + k]);
        float sum = 0.f;
        for (int k = 0; k < T_; k++) {
            float e = expf(ss[tid * 50 + k] - m);
            ss[tid * 50 + k] = e; sum += e;
        }
        float inv = 1.f / sum;
        for (int k = 0; k < T_; k++) ss[tid * 50 + k] *= inv;
    }
    __syncthreads();

    for (int idx = tid; idx < T_ * HD_; idx += 256) {
        int t = idx / HD_, d = idx % HD_;
        float acc = 0.f;
        #pragma unroll
        for (int k = 0; k < T_; k++) acc += ss[t * 50 + k] * sv[k * HD_ + d];
        g_o1[(size_t)(bw * T_ + t) * CC + hh * HD_ + d] = tf32r(acc);
    }
}

// ---------------- fold+roll(+3) + LN1 + residual; emit CA query tokens ------
__global__ __launch_bounds__(256)
void merge_ln1(const float* __restrict__ visual,
               const float* __restrict__ g, const float* __restrict__ bt) {
    int pos = blockIdx.x;
    int b = pos / HWSZ, hw = pos % HWSZ;
    int h = hw / WW_, w = hw % WW_;
    int hp = (h + HH - SS_) % HH, wp = (w + WW_ - SS_) % WW_;
    int rm = (b * NW_ + (hp / WS_) * 8 + (wp / WS_)) * T_ + (hp % WS_) * WS_ + (wp % WS_);

    __shared__ float x[CC];
    int tid = threadIdx.x;
    float s = 0.f, ss2 = 0.f;
    for (int c = tid; c < CC; c += 256) {
        float v = g_w2[(size_t)rm * CC + c];
        x[c] = v; s += v; ss2 += v * v;
    }
    float mu, rstd;
    block_meanvar(s, ss2, CC, &mu, &rstd);
    for (int c = tid; c < CC; c += 256) {
        float v = (x[c] - mu) * rstd * g[c] + bt[c]
                + visual[(size_t)(b * CC + c) * HWSZ + hw];
        g_skipa[(size_t)pos * CC + c] = v;
        g_pq  [(size_t)rm  * CC + c] = tf32r(v);
    }
}

// ---------------- cross attention ----------------
__global__ __launch_bounds__(256)
void ca_attn() {
    int bw = blockIdx.x >> 4;
    int hh = blockIdx.x & 15;
    int bkv = bw & 7;
    int tid = threadIdx.x;

    __shared__ float sq[T_ * HD_], sk[L_ * HD_], sv[L_ * HD_];
    __shared__ float ss[T_ * 65];

    for (int idx = tid; idx < T_ * HD_; idx += 256) {
        int t = idx / HD_, d = idx % HD_;
        sq[idx] = g_q2[(size_t)(bw * T_ + t) * CC + hh * HD_ + d];
    }
    for (int idx = tid; idx < L_ * HD_; idx += 256) {
        int l = idx / HD_, d = idx % HD_;
        size_t ro = (size_t)(bkv * L_ + l) * CC + hh * HD_ + d;
        sk[idx] = g_k2[ro];
        sv[idx] = g_v2[ro];
    }
    __syncthreads();

    for (int idx = tid; idx < T_ * L_; idx += 256) {
        int q = idx / L_, l = idx % L_;
        float dot = 0.f;
        #pragma unroll
        for (int d = 0; d < HD_; d++) dot += sq[q * HD_ + d] * sk[l * HD_ + d];
        ss[q * 65 + l] = dot;
    }
    __syncthreads();

    if (tid < T_) {
        float m = -1e30f;
        for (int l = 0; l < L_; l++) m = fmaxf(m, ss[tid * 65 + l]);
        float sum = 0.f;
        for (int l = 0; l < L_; l++) {
            float e = expf(ss[tid * 65 + l] - m);
            ss[tid * 65 + l] = e; sum += e;
        }
        float inv = 1.f / sum;
        for (int l = 0; l < L_; l++) ss[tid * 65 + l] *= inv;
    }
    __syncthreads();

    for (int idx = tid; idx < T_ * HD_; idx += 256) {
        int t = idx / HD_, d = idx % HD_;
        float acc = 0.f;
        #pragma unroll
        for (int l = 0; l < L_; l++) acc += ss[t * 65 + l] * sv[l * HD_ + d];
        g_co1[(size_t)(bw * T_ + t) * CC + hh * HD_ + d] = tf32r(acc);
    }
}

// ---------------- LN2 + fold+roll(+3) + residual ----------------
__global__ __launch_bounds__(256)
void ca_ln2(const float* __restrict__ g, const float* __restrict__ bt) {
    int r = blockIdx.x;
    int bw = r / T_, t = r % T_;
    int b = bw / NW_, win = bw % NW_, wh = win >> 3, ww = win & 7;
    int h = (wh * WS_ + t / WS_ + SS_) % HH;
    int w = (ww * WS_ + t % WS_ + SS_) % WW_;
    int pos = b * HWSZ + h * WW_ + w;

    __shared__ float x[CC];
    int tid = threadIdx.x;
    float s = 0.f, ss2 = 0.f;
    for (int c = tid; c < CC; c += 256) {
        float v = g_co2[(size_t)r * CC + c];
        x[c] = v; s += v; ss2 += v * v;
    }
    float mu, rstd;
    block_meanvar(s, ss2, CC, &mu, &rstd);
    for (int c = tid; c < CC; c += 256) {
        float v = (x[c] - mu) * rstd * g[c] + bt[c]
                + g_skipa[(size_t)pos * CC + c];
        g_skip2 [(size_t)pos * CC + c] = v;
        g_skip2r[(size_t)pos * CC + c] = tf32r(v);
    }
}

// ---------------- LN3(ff) + skip2, write [B,C,H,W] ----------------
__global__ __launch_bounds__(256)
void final_kernel(float* __restrict__ out,
                  const float* __restrict__ g, const float* __restrict__ bt) {
    int pos = blockIdx.x;
    int b = pos / HWSZ, hw = pos % HWSZ;

    __shared__ float x[CC];
    int tid = threadIdx.x;
    float s = 0.f, ss2 = 0.f;
    for (int c = tid; c < CC; c += 256) {
        float v = g_ffo[(size_t)pos * CC + c];
        x[c] = v; s += v; ss2 += v * v;
    }
    float mu, rstd;
    block_meanvar(s, ss2, CC, &mu, &rstd);
    for (int c = tid; c < CC; c += 256) {
        float v = (x[c] - mu) * rstd * g[c] + bt[c];
        out[(size_t)(b * CC + c) * HWSZ + hw] = g_skip2[(size_t)pos * CC + c] + v;
    }
}

// ---------------- launch ----------------
extern "C" void kernel_launch(void* const* d_in, const int* in_sizes, int n_in,
                              void* d_out, int out_size) {
    const float* visual   = (const float*)d_in[0];
    const float* vector   = (const float*)d_in[1];
    const float* tm_w     = (const float*)d_in[2];
    const float* tm_b     = (const float*)d_in[3];
    const float* ln1_g    = (const float*)d_in[4];
    const float* ln1_b    = (const float*)d_in[5];
    const float* ln2_g    = (const float*)d_in[6];
    const float* ln2_b    = (const float*)d_in[7];
    const float* ln3_g    = (const float*)d_in[8];
    const float* ln3_b    = (const float*)d_in[9];
    const float* qkv_w    = (const float*)d_in[10];
    const float* qkv_b    = (const float*)d_in[11];
    const float* wproj_w  = (const float*)d_in[12];
    const float* wproj_b  = (const float*)d_in[13];
    const float* meta_w1  = (const float*)d_in[14];
    const float* meta_b1  = (const float*)d_in[15];
    const float* meta_w2  = (const float*)d_in[16];
    const float* meta_b2  = (const float*)d_in[17];
    const float* tau      = (const float*)d_in[18];
    const float* ca_in_w  = (const float*)d_in[19];
    const float* ca_in_b  = (const float*)d_in[20];
    const float* ca_out_w = (const float*)d_in[21];
    const float* ca_out_b = (const float*)d_in[22];
    const float* ff_w1    = (const float*)d_in[23];
    const float* ff_b1    = (const float*)d_in[24];
    const float* ff_w2    = (const float*)d_in[25];
    const float* ff_b2    = (const float*)d_in[26];
    float* out = (float*)d_out;

    float *vin, *vec, *tok, *qkv, *o1, *w2, *pq, *q2, *k2, *v2, *co1, *co2,
          *sk2r, *ffh, *ffo;
    float *tmwt, *qkvwt, *wprwt, *caint, *caoutt, *ff1t, *ff2t;
    cudaGetSymbolAddress((void**)&vin,   g_vin);
    cudaGetSymbolAddress((void**)&vec,   g_vec);
    cudaGetSymbolAddress((void**)&tok,   g_tok);
    cudaGetSymbolAddress((void**)&qkv,   g_qkv);
    cudaGetSymbolAddress((void**)&o1,    g_o1);
    cudaGetSymbolAddress((void**)&w2,    g_w2);
    cudaGetSymbolAddress((void**)&pq,    g_pq);
    cudaGetSymbolAddress((void**)&q2,    g_q2);
    cudaGetSymbolAddress((void**)&k2,    g_k2);
    cudaGetSymbolAddress((void**)&v2,    g_v2);
    cudaGetSymbolAddress((void**)&co1,   g_co1);
    cudaGetSymbolAddress((void**)&co2,   g_co2);
    cudaGetSymbolAddress((void**)&sk2r,  g_skip2r);
    cudaGetSymbolAddress((void**)&ffh,   g_ffh);
    cudaGetSymbolAddress((void**)&ffo,   g_ffo);
    cudaGetSymbolAddress((void**)&tmwt,  g_tmw_t);
    cudaGetSymbolAddress((void**)&qkvwt, g_qkvw_t);
    cudaGetSymbolAddress((void**)&wprwt, g_wprw_t);
    cudaGetSymbolAddress((void**)&caint, g_cain_t);
    cudaGetSymbolAddress((void**)&caoutt,g_caout_t);
    cudaGetSymbolAddress((void**)&ff1t,  g_ff1_t);
    cudaGetSymbolAddress((void**)&ff2t,  g_ff2_t);

    cudaFuncSetAttribute(tgemm<EPI_NONE>,  cudaFuncAttributeMaxDynamicSharedMemorySize, TGEMM_SMEM);
    cudaFuncSetAttribute(tgemm<EPI_GELU>,  cudaFuncAttributeMaxDynamicSharedMemorySize, TGEMM_SMEM);
    cudaFuncSetAttribute(tgemm<EPI_SCALE>, cudaFuncAttributeMaxDynamicSharedMemorySize, TGEMM_SMEM);

    // weight transposes (+tf32 rounding)
    transpose_w<<<dim3(16,  8), 256>>>(tm_w,     tmwt,  256,  512);
    transpose_w<<<dim3(48, 16), 256>>>(qkv_w,    qkvwt, 512, 1536);
    transpose_w<<<dim3(16, 16), 256>>>(wproj_w,  wprwt, 512,  512);
    transpose_w<<<dim3(48, 16), 256>>>(ca_in_w,  caint, 512, 1536);
    transpose_w<<<dim3(16, 16), 256>>>(ca_out_w, caoutt,512,  512);
    transpose_w<<<dim3(64, 16), 256>>>(ff_w1,    ff1t,  512, 2048);
    transpose_w<<<dim3(16, 64), 256>>>(ff_w2,    ff2t, 2048,  512);
    round_copy<<<512, 256>>>(vector, vin, 512 * 256);

    bias_kernel<<<T_ * T_, 256>>>(meta_w1, meta_b1, meta_w2, meta_b2);

    // vec = gelu(vector @ tm_w + tm_b)
    tgemm<EPI_GELU><<<dim3(4, 4), 256, TGEMM_SMEM>>>(vin, tmwt, tm_b, vec, 512, 512, 256, 0.f);
    // K2/V2 (only B distinct kv sets)
    tgemm<EPI_NONE><<<dim3(4, 4), 256, TGEMM_SMEM>>>(vec, caint + 512 * 512,  ca_in_b + 512,  k2, 512, 512, 512, 0.f);
    tgemm<EPI_NONE><<<dim3(4, 4), 256, TGEMM_SMEM>>>(vec, caint + 1024 * 512, ca_in_b + 1024, v2, 512, 512, 512, 0.f);

    unfold_kernel<<<NTOK, 256>>>(visual);
    tgemm<EPI_NONE><<<dim3(12, 196), 256, TGEMM_SMEM>>>(tok, qkvwt, qkv_b, qkv, NTOK, 3 * CC, CC, 0.f);
    win_attn<<<BW_ * NH_, 256>>>(tau);
    tgemm<EPI_NONE><<<dim3(4, 196), 256, TGEMM_SMEM>>>(o1, wprwt, wproj_b, w2, NTOK, CC, CC, 0.f);
    merge_ln1<<<BB * HWSZ, 256>>>(visual, ln1_g, ln1_b);
    tgemm<EPI_SCALE><<<dim3(4, 196), 256, TGEMM_SMEM>>>(pq, caint, ca_in_b, q2, NTOK, CC, CC, 0.17677669529663687f);
    ca_attn<<<BW_ * NH_, 256>>>();
    tgemm<EPI_NONE><<<dim3(4, 196), 256, TGEMM_SMEM>>>(co1, caoutt, ca_out_b, co2, NTOK, CC, CC, 0.f);
    ca_ln2<<<NTOK, 256>>>(ln2_g, ln2_b);
    tgemm<EPI_GELU><<<dim3(16, 196), 256, TGEMM_SMEM>>>(sk2r, ff1t, ff_b1, ffh, NTOK, 4 * CC, CC, 0.f);
    tgemm<EPI_NONE><<<dim3(4, 196), 256, TGEMM_SMEM>>>(ffh, ff2t, ff_b2, ffo, NTOK, CC, 2048, 0.f);
    final_kernel<<<BB * HWSZ, 256>>>(out, ln3_g, ln3_b);
}

// round 8
// speedup vs baseline: 1.4933x; 1.2338x over previous
#include <cuda_runtime.h>
#include <cuda_fp16.h>
#include <math.h>
#include <stdint.h>

// Problem constants
#define BB    8
#define CC    512
#define HH    56
#define WW_   56
#define HWSZ  3136
#define WS_   7
#define SS_   3
#define NH_   16
#define HD_   32
#define T_    49
#define NW_   64
#define BW_   512          // BB * NW_
#define NTOK  25088        // BW_ * T_
#define L_    64

// ---------------- scratch (device globals; no runtime alloc) ----------------
__device__ __align__(16) __half g_vin [512 * 256];
__device__ __align__(16) __half g_vec [BW_ * CC];
__device__ __align__(16) __half g_tok [NTOK * CC];
__device__ float  g_qkv [NTOK * 3 * CC];
__device__ __align__(16) __half g_o1  [NTOK * CC];
__device__ float  g_w2  [NTOK * CC];
__device__ float  g_skipa[NTOK * CC];       // skip1 [B,HW,C] full fp32
__device__ __align__(16) __half g_pq  [NTOK * CC];
__device__ float  g_q2  [NTOK * CC];
__device__ float  g_k2  [BW_ * CC];
__device__ float  g_v2  [BW_ * CC];
__device__ __align__(16) __half g_co1 [NTOK * CC];
__device__ float  g_co2 [NTOK * CC];
__device__ float  g_skip2[NTOK * CC];       // full fp32
__device__ __align__(16) __half g_skip2r[NTOK * CC]; // fp16 copy for GEMM
__device__ __align__(16) __half g_ffh [NTOK * 4 * CC];
__device__ float  g_ffo [NTOK * CC];
__device__ float  g_bias[NH_ * T_ * T_];

// transposed (fp16) weights: [N, K] K-contiguous
__device__ __align__(16) __half g_tmw_t  [512 * 256];
__device__ __align__(16) __half g_qkvw_t [1536 * 512];
__device__ __align__(16) __half g_wprw_t [512 * 512];
__device__ __align__(16) __half g_cain_t [1536 * 512];
__device__ __align__(16) __half g_caout_t[512 * 512];
__device__ __align__(16) __half g_ff1_t  [2048 * 512];
__device__ __align__(16) __half g_ff2_t  [512 * 2048];

// ---------------- helpers ----------------
__device__ __forceinline__ float gelu_exact(float x) {
    return 0.5f * x * (1.0f + erff(x * 0.70710678118654752f));
}
__device__ __forceinline__ uint32_t s2u(const void* p) {
    uint32_t a;
    asm("{ .reg .u64 t; cvta.to.shared.u64 t, %1; cvt.u32.u64 %0, t; }"
        : "=r"(a) : "l"(p));
    return a;
}

__device__ __forceinline__ void block_meanvar(float s, float ss, int n,
                                              float* mu, float* rstd) {
    #pragma unroll
    for (int o = 16; o > 0; o >>= 1) {
        s  += __shfl_down_sync(0xffffffffu, s,  o);
        ss += __shfl_down_sync(0xffffffffu, ss, o);
    }
    __shared__ float rs[8], rss[8], res[2];
    int lane = threadIdx.x & 31, wid = threadIdx.x >> 5;
    if (lane == 0) { rs[wid] = s; rss[wid] = ss; }
    __syncthreads();
    if (threadIdx.x == 0) {
        float S = 0.f, SS2 = 0.f;
        #pragma unroll
        for (int i = 0; i < 8; i++) { S += rs[i]; SS2 += rss[i]; }
        float m = S / n;
        float var = SS2 / n - m * m;
        res[0] = m; res[1] = rsqrtf(var + 1e-5f);
    }
    __syncthreads();
    *mu = res[0]; *rstd = res[1];
}

// ---------------- fp16 mma.sync GEMM (3-stage pipeline) ----------------
// C[M,N] = epi(A[M,K] @ W[N,K]^T + bias); A,W fp16; accum fp32.
// M%128==0, N%128==0, K%32==0.
#define EPI_NONE  0
#define EPI_GELU  1
#define EPI_SCALE 2

#define LDPAD_H 40
#define TILEH (128 * LDPAD_H)            // halves per tile
#define TGEMM_SMEM (6 * TILEH * 2)       // 3 stages x (A+B), bytes = 61440

__device__ __forceinline__ void mma_f16(float* c, const uint32_t* a,
                                        const uint32_t* b) {
    asm volatile(
        "mma.sync.aligned.m16n8k16.row.col.f32.f16.f16.f32 "
        "{%0,%1,%2,%3}, {%4,%5,%6,%7}, {%8,%9}, {%0,%1,%2,%3};"
        : "+f"(c[0]), "+f"(c[1]), "+f"(c[2]), "+f"(c[3])
        : "r"(a[0]), "r"(a[1]), "r"(a[2]), "r"(a[3]),
          "r"(b[0]), "r"(b[1]));
}

__device__ __forceinline__ void store2(float* p, float a, float b) {
    *(float2*)p = make_float2(a, b);
}
__device__ __forceinline__ void store2(__half* p, float a, float b) {
    *(__half2*)p = __floats2half2_rn(a, b);
}

template <int EPI, typename OutT>
__global__ __launch_bounds__(256)
void tgemm(const __half* __restrict__ A, const __half* __restrict__ W,
           const float* __restrict__ bias, OutT* __restrict__ C,
           int M, int N, int K, float alpha) {
    extern __shared__ __half smh[];
    __half* Abuf = smh;                  // [3][128][LDPAD_H]
    __half* Bbuf = smh + 3 * TILEH;      // [3][128][LDPAD_H]
    const uint32_t sm_a = s2u(Abuf), sm_b = s2u(Bbuf);

    const int tid = threadIdx.x;
    const int wid = tid >> 5, lane = tid & 31;
    const int m0 = blockIdx.y << 7, n0 = blockIdx.x << 7;
    const int wm = wid & 3, wn = wid >> 2;
    const int m_off = wm << 5;           // 32-row warp tile
    const int n_off = wn << 6;           // 64-col warp tile

    const __half* Abase = A + (size_t)m0 * K;
    const __half* Wbase = W + (size_t)n0 * K;
    const int NC = K >> 5;

    const int seg = tid & 3;             // 4 x 16B (8-half) segments per row
    const int lr0 = tid >> 2;            // 0..63

    auto load_chunk = [&](int c, int sel) {
        uint32_t ab = sm_a + sel * (TILEH * 2);
        uint32_t bb = sm_b + sel * (TILEH * 2);
        const __half* As = Abase + c * 32 + seg * 8;
        const __half* Ws = Wbase + c * 32 + seg * 8;
        #pragma unroll
        for (int i = 0; i < 2; i++) {
            int r = lr0 + (i << 6);      // 0..127
            uint32_t so = (uint32_t)(r * (LDPAD_H * 2) + seg * 16);
            asm volatile("cp.async.cg.shared.global [%0], [%1], 16;"
                         :: "r"(ab + so), "l"(As + (size_t)r * K));
            asm volatile("cp.async.cg.shared.global [%0], [%1], 16;"
                         :: "r"(bb + so), "l"(Ws + (size_t)r * K));
        }
        asm volatile("cp.async.commit_group;" ::: "memory");
    };

    float acc[2][8][4];
    #pragma unroll
    for (int i = 0; i < 2; i++)
        #pragma unroll
        for (int j = 0; j < 8; j++)
            #pragma unroll
            for (int q = 0; q < 4; q++) acc[i][j][q] = 0.f;

    // prefetch 2 chunks (3-stage ring, distance 2)
    load_chunk(0, 0);
    if (NC > 1) load_chunk(1, 1);

    const int qr = lane >> 2, qc = lane & 3;
    int sel = 0;

    for (int c = 0; c < NC; c++) {
        if (c + 1 < NC)
            asm volatile("cp.async.wait_group 1;" ::: "memory");
        else
            asm volatile("cp.async.wait_group 0;" ::: "memory");
        __syncthreads();
        if (c + 2 < NC) {
            int s2 = sel + 2; if (s2 >= 3) s2 -= 3;
            load_chunk(c + 2, s2);
        }

        const __half* As = Abuf + sel * TILEH;
        const __half* Bs = Bbuf + sel * TILEH;

        #pragma unroll
        for (int ks = 0; ks < 2; ks++) {
            const int k0 = ks * 16;
            uint32_t a[2][4], b[8][2];
            #pragma unroll
            for (int mt = 0; mt < 2; mt++) {
                const __half* ap = As + (m_off + mt * 16 + qr) * LDPAD_H + k0 + 2 * qc;
                a[mt][0] = *(const uint32_t*)(ap);
                a[mt][1] = *(const uint32_t*)(ap + 8 * LDPAD_H);
                a[mt][2] = *(const uint32_t*)(ap + 8);
                a[mt][3] = *(const uint32_t*)(ap + 8 * LDPAD_H + 8);
            }
            #pragma unroll
            for (int nt = 0; nt < 8; nt++) {
                const __half* bp = Bs + (n_off + nt * 8 + qr) * LDPAD_H + k0 + 2 * qc;
                b[nt][0] = *(const uint32_t*)(bp);
                b[nt][1] = *(const uint32_t*)(bp + 8);
            }
            #pragma unroll
            for (int mt = 0; mt < 2; mt++)
                #pragma unroll
                for (int nt = 0; nt < 8; nt++)
                    mma_f16(acc[mt][nt], a[mt], b[nt]);
        }
        if (++sel >= 3) sel = 0;
    }

    // epilogue
    #pragma unroll
    for (int mt = 0; mt < 2; mt++) {
        #pragma unroll
        for (int half = 0; half < 2; half++) {
            int row = m0 + m_off + mt * 16 + qr + half * 8;
            OutT* Cp = C + (size_t)row * N + n0 + n_off;
            #pragma unroll
            for (int nt = 0; nt < 8; nt++) {
                int col = nt * 8 + qc * 2;
                float v0 = acc[mt][nt][half * 2 + 0] + bias[n0 + n_off + col];
                float v1 = acc[mt][nt][half * 2 + 1] + bias[n0 + n_off + col + 1];
                if (EPI == EPI_GELU)  { v0 = gelu_exact(v0); v1 = gelu_exact(v1); }
                if (EPI == EPI_SCALE) { v0 *= alpha; v1 *= alpha; }
                store2(Cp + col, v0, v1);
            }
        }
    }
}

// ---------------- weight transpose + fp16:  Wt[n,k] = h(W[k,n]) ----
__global__ __launch_bounds__(256)
void transpose_w(const float* __restrict__ W, __half* __restrict__ Wt,
                 int K, int N) {
    __shared__ float tile[32][33];
    int kb = blockIdx.y * 32, nb = blockIdx.x * 32;
    int tx = threadIdx.x & 31, ty = threadIdx.x >> 5;
    #pragma unroll
    for (int i = 0; i < 32; i += 8)
        tile[ty + i][tx] = W[(size_t)(kb + ty + i) * N + nb + tx];
    __syncthreads();
    #pragma unroll
    for (int i = 0; i < 32; i += 8)
        Wt[(size_t)(nb + ty + i) * K + kb + tx] = __float2half_rn(tile[tx][ty + i]);
}

__global__ void half_copy(const float* __restrict__ in, __half* __restrict__ o, int n) {
    int i = blockIdx.x * 256 + threadIdx.x;
    if (i < n) o[i] = __float2half_rn(in[i]);
}

// ---------------- relative-position bias precompute ----------------
__global__ void bias_kernel(const float* __restrict__ w1, const float* __restrict__ b1,
                            const float* __restrict__ w2, const float* __restrict__ b2) {
    int pair = blockIdx.x;
    int q = pair / T_, k = pair % T_;
    float d0 = (float)(q / WS_ - k / WS_);
    float d1 = (float)(q % WS_ - k % WS_);
    float r0 = (d0 > 0.f ? 1.f : (d0 < 0.f ? -1.f : 0.f)) * log1pf(fabsf(d0));
    float r1 = (d1 > 0.f ? 1.f : (d1 < 0.f ? -1.f : 0.f)) * log1pf(fabsf(d1));
    int tid = threadIdx.x;
    __shared__ float hbuf[256];
    float hv = r0 * w1[tid] + r1 * w1[256 + tid] + b1[tid];
    hbuf[tid] = fmaxf(hv, 0.f);
    __syncthreads();
    if (tid < NH_) {
        float s = b2[tid];
        #pragma unroll 8
        for (int j = 0; j < 256; j++) s += hbuf[j] * w2[j * NH_ + tid];
        g_bias[tid * (T_ * T_) + pair] = s;
    }
}

// ---------------- roll(-3,-3) + unfold into token rows (fp16) ---------------
__global__ __launch_bounds__(256)
void unfold_kernel(const float* __restrict__ visual) {
    int r = blockIdx.x;
    int bw = r / T_, t = r % T_;
    int b = bw / NW_, win = bw % NW_, wh = win >> 3, ww = win & 7;
    int h = (wh * WS_ + t / WS_ + SS_) % HH;
    int w = (ww * WS_ + t % WS_ + SS_) % WW_;
    int hw = h * WW_ + w;
    for (int c = threadIdx.x; c < CC; c += 256)
        g_tok[(size_t)r * CC + c] = __float2half_rn(visual[(size_t)(b * CC + c) * HWSZ + hw]);
}

// ---------------- window attention ----------------
__global__ __launch_bounds__(256)
void win_attn(const float* __restrict__ tau) {
    int bw = blockIdx.x >> 4;
    int hh = blockIdx.x & 15;
    int tid = threadIdx.x;

    __shared__ float sq[T_ * HD_], sk[T_ * HD_], sv[T_ * HD_];
    __shared__ float ss[T_ * 50];
    __shared__ float nq[T_], nk[T_];
    __shared__ int   rg[T_];

    size_t base = (size_t)(bw * T_) * (3 * CC);
    for (int idx = tid; idx < T_ * HD_; idx += 256) {
        int t = idx / HD_, d = idx % HD_;
        size_t ro = base + (size_t)t * (3 * CC) + hh * HD_ + d;
        sq[idx] = g_qkv[ro];
        sk[idx] = g_qkv[ro + CC];
        sv[idx] = g_qkv[ro + 2 * CC];
    }
    int win = bw & 63, wh = win >> 3, ww = win & 7;
    if (tid < T_) {
        int row = wh * WS_ + tid / WS_;
        int col = ww * WS_ + tid % WS_;
        int rh = row < 49 ? 0 : (row < 53 ? 1 : 2);
        int rw = col < 49 ? 0 : (col < 53 ? 1 : 2);
        rg[tid] = rh * 3 + rw;
    }
    __syncthreads();

    if (tid < T_) {
        float s1 = 0.f, s2 = 0.f;
        #pragma unroll
        for (int d = 0; d < HD_; d++) {
            float a = sq[tid * HD_ + d], b = sk[tid * HD_ + d];
            s1 += a * a; s2 += b * b;
        }
        nq[tid] = sqrtf(s1); nk[tid] = sqrtf(s2);
    }
    __syncthreads();

    float tauh = fmaxf(tau[hh], 0.01f);
    const float* bh = &g_bias[hh * (T_ * T_)];
    for (int idx = tid; idx < T_ * T_; idx += 256) {
        int q = idx / T_, k = idx % T_;
        float dot = 0.f;
        #pragma unroll
        for (int d = 0; d < HD_; d++) dot += sq[q * HD_ + d] * sk[k * HD_ + d];
        float s = dot / fmaxf(nq[q] * nk[k], 1e-6f) / tauh + bh[idx];
        if (rg[q] != rg[k]) s -= 100.0f;
        ss[q * 50 + k] = s;
    }
    __syncthreads();

    if (tid < T_) {
        float m = -1e30f;
        for (int k = 0; k < T_; k++) m = fmaxf(m, ss[tid * 50 + k]);
        float sum = 0.f;
        for (int k = 0; k < T_; k++) {
            float e = expf(ss[tid * 50 + k] - m);
            ss[tid * 50 + k] = e; sum += e;
        }
        float inv = 1.f / sum;
        for (int k = 0; k < T_; k++) ss[tid * 50 + k] *= inv;
    }
    __syncthreads();

    for (int idx = tid; idx < T_ * HD_; idx += 256) {
        int t = idx / HD_, d = idx % HD_;
        float acc = 0.f;
        #pragma unroll
        for (int k = 0; k < T_; k++) acc += ss[t * 50 + k] * sv[k * HD_ + d];
        g_o1[(size_t)(bw * T_ + t) * CC + hh * HD_ + d] = __float2half_rn(acc);
    }
}

// ---------------- fold+roll(+3) + LN1 + residual; emit CA query tokens ------
__global__ __launch_bounds__(256)
void merge_ln1(const float* __restrict__ visual,
               const float* __restrict__ g, const float* __restrict__ bt) {
    int pos = blockIdx.x;
    int b = pos / HWSZ, hw = pos % HWSZ;
    int h = hw / WW_, w = hw % WW_;
    int hp = (h + HH - SS_) % HH, wp = (w + WW_ - SS_) % WW_;
    int rm = (b * NW_ + (hp / WS_) * 8 + (wp / WS_)) * T_ + (hp % WS_) * WS_ + (wp % WS_);

    __shared__ float x[CC];
    int tid = threadIdx.x;
    float s = 0.f, ss2 = 0.f;
    for (int c = tid; c < CC; c += 256) {
        float v = g_w2[(size_t)rm * CC + c];
        x[c] = v; s += v; ss2 += v * v;
    }
    float mu, rstd;
    block_meanvar(s, ss2, CC, &mu, &rstd);
    for (int c = tid; c < CC; c += 256) {
        float v = (x[c] - mu) * rstd * g[c] + bt[c]
                + visual[(size_t)(b * CC + c) * HWSZ + hw];
        g_skipa[(size_t)pos * CC + c] = v;
        g_pq  [(size_t)rm  * CC + c] = __float2half_rn(v);
    }
}

// ---------------- cross attention ----------------
__global__ __launch_bounds__(256)
void ca_attn() {
    int bw = blockIdx.x >> 4;
    int hh = blockIdx.x & 15;
    int bkv = bw & 7;
    int tid = threadIdx.x;

    __shared__ float sq[T_ * HD_], sk[L_ * HD_], sv[L_ * HD_];
    __shared__ float ss[T_ * 65];

    for (int idx = tid; idx < T_ * HD_; idx += 256) {
        int t = idx / HD_, d = idx % HD_;
        sq[idx] = g_q2[(size_t)(bw * T_ + t) * CC + hh * HD_ + d];
    }
    for (int idx = tid; idx < L_ * HD_; idx += 256) {
        int l = idx / HD_, d = idx % HD_;
        size_t ro = (size_t)(bkv * L_ + l) * CC + hh * HD_ + d;
        sk[idx] = g_k2[ro];
        sv[idx] = g_v2[ro];
    }
    __syncthreads();

    for (int idx = tid; idx < T_ * L_; idx += 256) {
        int q = idx / L_, l = idx % L_;
        float dot = 0.f;
        #pragma unroll
        for (int d = 0; d < HD_; d++) dot += sq[q * HD_ + d] * sk[l * HD_ + d];
        ss[q * 65 + l] = dot;
    }
    __syncthreads();

    if (tid < T_) {
        float m = -1e30f;
        for (int l = 0; l < L_; l++) m = fmaxf(m, ss[tid * 65 + l]);
        float sum = 0.f;
        for (int l = 0; l < L_; l++) {
            float e = expf(ss[tid * 65 + l] - m);
            ss[tid * 65 + l] = e; sum += e;
        }
        float inv = 1.f / sum;
        for (int l = 0; l < L_; l++) ss[tid * 65 + l] *= inv;
    }
    __syncthreads();

    for (int idx = tid; idx < T_ * HD_; idx += 256) {
        int t = idx / HD_, d = idx % HD_;
        float acc = 0.f;
        #pragma unroll
        for (int l = 0; l < L_; l++) acc += ss[t * 65 + l] * sv[l * HD_ + d];
        g_co1[(size_t)(bw * T_ + t) * CC + hh * HD_ + d] = __float2half_rn(acc);
    }
}

// ---------------- LN2 + fold+roll(+3) + residual ----------------
__global__ __launch_bounds__(256)
void ca_ln2(const float* __restrict__ g, const float* __restrict__ bt) {
    int r = blockIdx.x;
    int bw = r / T_, t = r % T_;
    int b = bw / NW_, win = bw % NW_, wh = win >> 3, ww = win & 7;
    int h = (wh * WS_ + t / WS_ + SS_) % HH;
    int w = (ww * WS_ + t % WS_ + SS_) % WW_;
    int pos = b * HWSZ + h * WW_ + w;

    __shared__ float x[CC];
    int tid = threadIdx.x;
    float s = 0.f, ss2 = 0.f;
    for (int c = tid; c < CC; c += 256) {
        float v = g_co2[(size_t)r * CC + c];
        x[c] = v; s += v; ss2 += v * v;
    }
    float mu, rstd;
    block_meanvar(s, ss2, CC, &mu, &rstd);
    for (int c = tid; c < CC; c += 256) {
        float v = (x[c] - mu) * rstd * g[c] + bt[c]
                + g_skipa[(size_t)pos * CC + c];
        g_skip2 [(size_t)pos * CC + c] = v;
        g_skip2r[(size_t)pos * CC + c] = __float2half_rn(v);
    }
}

// ---------------- LN3(ff) + skip2, write [B,C,H,W] ----------------
__global__ __launch_bounds__(256)
void final_kernel(float* __restrict__ out,
                  const float* __restrict__ g, const float* __restrict__ bt) {
    int pos = blockIdx.x;
    int b = pos / HWSZ, hw = pos % HWSZ;

    __shared__ float x[CC];
    int tid = threadIdx.x;
    float s = 0.f, ss2 = 0.f;
    for (int c = tid; c < CC; c += 256) {
        float v = g_ffo[(size_t)pos * CC + c];
        x[c] = v; s += v; ss2 += v * v;
    }
    float mu, rstd;
    block_meanvar(s, ss2, CC, &mu, &rstd);
    for (int c = tid; c < CC; c += 256) {
        float v = (x[c] - mu) * rstd * g[c] + bt[c];
        out[(size_t)(b * CC + c) * HWSZ + hw] = g_skip2[(size_t)pos * CC + c] + v;
    }
}

// ---------------- launch ----------------
extern "C" void kernel_launch(void* const* d_in, const int* in_sizes, int n_in,
                              void* d_out, int out_size) {
    const float* visual   = (const float*)d_in[0];
    const float* vector   = (const float*)d_in[1];
    const float* tm_w     = (const float*)d_in[2];
    const float* tm_b     = (const float*)d_in[3];
    const float* ln1_g    = (const float*)d_in[4];
    const float* ln1_b    = (const float*)d_in[5];
    const float* ln2_g    = (const float*)d_in[6];
    const float* ln2_b    = (const float*)d_in[7];
    const float* ln3_g    = (const float*)d_in[8];
    const float* ln3_b    = (const float*)d_in[9];
    const float* qkv_w    = (const float*)d_in[10];
    const float* qkv_b    = (const float*)d_in[11];
    const float* wproj_w  = (const float*)d_in[12];
    const float* wproj_b  = (const float*)d_in[13];
    const float* meta_w1  = (const float*)d_in[14];
    const float* meta_b1  = (const float*)d_in[15];
    const float* meta_w2  = (const float*)d_in[16];
    const float* meta_b2  = (const float*)d_in[17];
    const float* tau      = (const float*)d_in[18];
    const float* ca_in_w  = (const float*)d_in[19];
    const float* ca_in_b  = (const float*)d_in[20];
    const float* ca_out_w = (const float*)d_in[21];
    const float* ca_out_b = (const float*)d_in[22];
    const float* ff_w1    = (const float*)d_in[23];
    const float* ff_b1    = (const float*)d_in[24];
    const float* ff_w2    = (const float*)d_in[25];
    const float* ff_b2    = (const float*)d_in[26];
    float* out = (float*)d_out;

    __half *vin, *vec, *tok, *o1, *pq, *co1, *sk2r, *ffh;
    float  *qkv, *w2, *q2, *k2, *v2, *co2, *ffo;
    __half *tmwt, *qkvwt, *wprwt, *caint, *caoutt, *ff1t, *ff2t;
    cudaGetSymbolAddress((void**)&vin,   g_vin);
    cudaGetSymbolAddress((void**)&vec,   g_vec);
    cudaGetSymbolAddress((void**)&tok,   g_tok);
    cudaGetSymbolAddress((void**)&qkv,   g_qkv);
    cudaGetSymbolAddress((void**)&o1,    g_o1);
    cudaGetSymbolAddress((void**)&w2,    g_w2);
    cudaGetSymbolAddress((void**)&pq,    g_pq);
    cudaGetSymbolAddress((void**)&q2,    g_q2);
    cudaGetSymbolAddress((void**)&k2,    g_k2);
    cudaGetSymbolAddress((void**)&v2,    g_v2);
    cudaGetSymbolAddress((void**)&co1,   g_co1);
    cudaGetSymbolAddress((void**)&co2,   g_co2);
    cudaGetSymbolAddress((void**)&sk2r,  g_skip2r);
    cudaGetSymbolAddress((void**)&ffh,   g_ffh);
    cudaGetSymbolAddress((void**)&ffo,   g_ffo);
    cudaGetSymbolAddress((void**)&tmwt,  g_tmw_t);
    cudaGetSymbolAddress((void**)&qkvwt, g_qkvw_t);
    cudaGetSymbolAddress((void**)&wprwt, g_wprw_t);
    cudaGetSymbolAddress((void**)&caint, g_cain_t);
    cudaGetSymbolAddress((void**)&caoutt,g_caout_t);
    cudaGetSymbolAddress((void**)&ff1t,  g_ff1_t);
    cudaGetSymbolAddress((void**)&ff2t,  g_ff2_t);

    cudaFuncSetAttribute((const void*)tgemm<EPI_NONE,  float>,  cudaFuncAttributeMaxDynamicSharedMemorySize, TGEMM_SMEM);
    cudaFuncSetAttribute((const void*)tgemm<EPI_GELU,  __half>, cudaFuncAttributeMaxDynamicSharedMemorySize, TGEMM_SMEM);
    cudaFuncSetAttribute((const void*)tgemm<EPI_SCALE, float>,  cudaFuncAttributeMaxDynamicSharedMemorySize, TGEMM_SMEM);

    // weight transposes (+fp16 rounding)
    transpose_w<<<dim3(16,  8), 256>>>(tm_w,     tmwt,  256,  512);
    transpose_w<<<dim3(48, 16), 256>>>(qkv_w,    qkvwt, 512, 1536);
    transpose_w<<<dim3(16, 16), 256>>>(wproj_w,  wprwt, 512,  512);
    transpose_w<<<dim3(48, 16), 256>>>(ca_in_w,  caint, 512, 1536);
    transpose_w<<<dim3(16, 16), 256>>>(ca_out_w, caoutt,512,  512);
    transpose_w<<<dim3(64, 16), 256>>>(ff_w1,    ff1t,  512, 2048);
    transpose_w<<<dim3(16, 64), 256>>>(ff_w2,    ff2t, 2048,  512);
    half_copy<<<512, 256>>>(vector, vin, 512 * 256);

    bias_kernel<<<T_ * T_, 256>>>(meta_w1, meta_b1, meta_w2, meta_b2);

    // vec = gelu(vector @ tm_w + tm_b)   (fp16 out)
    tgemm<EPI_GELU, __half><<<dim3(4, 4), 256, TGEMM_SMEM>>>(vin, tmwt, tm_b, vec, 512, 512, 256, 0.f);
    // K2/V2 (only B distinct kv sets)
    tgemm<EPI_NONE, float><<<dim3(4, 4), 256, TGEMM_SMEM>>>(vec, caint + 512 * 512,  ca_in_b + 512,  k2, 512, 512, 512, 0.f);
    tgemm<EPI_NONE, float><<<dim3(4, 4), 256, TGEMM_SMEM>>>(vec, caint + 1024 * 512, ca_in_b + 1024, v2, 512, 512, 512, 0.f);

    unfold_kernel<<<NTOK, 256>>>(visual);
    tgemm<EPI_NONE, float><<<dim3(12, 196), 256, TGEMM_SMEM>>>(tok, qkvwt, qkv_b, qkv, NTOK, 3 * CC, CC, 0.f);
    win_attn<<<BW_ * NH_, 256>>>(tau);
    tgemm<EPI_NONE, float><<<dim3(4, 196), 256, TGEMM_SMEM>>>(o1, wprwt, wproj_b, w2, NTOK, CC, CC, 0.f);
    merge_ln1<<<BB * HWSZ, 256>>>(visual, ln1_g, ln1_b);
    tgemm<EPI_SCALE, float><<<dim3(4, 196), 256, TGEMM_SMEM>>>(pq, caint, ca_in_b, q2, NTOK, CC, CC, 0.17677669529663687f);
    ca_attn<<<BW_ * NH_, 256>>>();
    tgemm<EPI_NONE, float><<<dim3(4, 196), 256, TGEMM_SMEM>>>(co1, caoutt, ca_out_b, co2, NTOK, CC, CC, 0.f);
    ca_ln2<<<NTOK, 256>>>(ln2_g, ln2_b);
    tgemm<EPI_GELU, __half><<<dim3(16, 196), 256, TGEMM_SMEM>>>(sk2r, ff1t, ff_b1, ffh, NTOK, 4 * CC, CC, 0.f);
    tgemm<EPI_NONE, float><<<dim3(4, 196), 256, TGEMM_SMEM>>>(ffh, ff2t, ff_b2, ffo, NTOK, CC, 2048, 0.f);
    final_kernel<<<BB * HWSZ, 256>>>(out, ln3_g, ln3_b);
}

// round 9
// speedup vs baseline: 1.5382x; 1.0301x over previous
#include <cuda_runtime.h>
#include <cuda_fp16.h>
#include <math.h>
#include <stdint.h>

// Problem constants
#define BB    8
#define CC    512
#define HH    56
#define WW_   56
#define HWSZ  3136
#define WS_   7
#define SS_   3
#define NH_   16
#define HD_   32
#define T_    49
#define NW_   64
#define BW_   512          // BB * NW_
#define NTOK  25088        // BW_ * T_
#define L_    64

// ---------------- scratch (device globals; no runtime alloc) ----------------
__device__ __align__(16) __half g_vin [512 * 256];
__device__ __align__(16) __half g_vec [BW_ * CC];
__device__ __align__(16) __half g_tok [NTOK * CC];
__device__ float  g_qkv [NTOK * 3 * CC];
__device__ __align__(16) __half g_o1  [NTOK * CC];
__device__ float  g_w2  [NTOK * CC];
__device__ float  g_skipa[NTOK * CC];       // skip1 [B,HW,C] full fp32
__device__ __align__(16) __half g_pq  [NTOK * CC];
__device__ float  g_q2  [NTOK * CC];
__device__ float  g_k2  [BW_ * CC];
__device__ float  g_v2  [BW_ * CC];
__device__ __align__(16) __half g_co1 [NTOK * CC];
__device__ float  g_co2 [NTOK * CC];
__device__ float  g_skip2[NTOK * CC];       // full fp32
__device__ __align__(16) __half g_skip2r[NTOK * CC]; // fp16 copy for GEMM
__device__ __align__(16) __half g_ffh [NTOK * 4 * CC];
__device__ float  g_ffo [NTOK * CC];
__device__ float  g_bias[NH_ * T_ * T_];

// transposed (fp16) weights: [N, K] K-contiguous
__device__ __align__(16) __half g_tmw_t  [512 * 256];
__device__ __align__(16) __half g_qkvw_t [1536 * 512];
__device__ __align__(16) __half g_wprw_t [512 * 512];
__device__ __align__(16) __half g_cain_t [1536 * 512];
__device__ __align__(16) __half g_caout_t[512 * 512];
__device__ __align__(16) __half g_ff1_t  [2048 * 512];
__device__ __align__(16) __half g_ff2_t  [512 * 2048];

// ---------------- helpers ----------------
__device__ __forceinline__ float gelu_exact(float x) {
    return 0.5f * x * (1.0f + erff(x * 0.70710678118654752f));
}
__device__ __forceinline__ uint32_t s2u(const void* p) {
    uint32_t a;
    asm("{ .reg .u64 t; cvta.to.shared.u64 t, %1; cvt.u32.u64 %0, t; }"
        : "=r"(a) : "l"(p));
    return a;
}

__device__ __forceinline__ void block_meanvar(float s, float ss, int n,
                                              float* mu, float* rstd) {
    #pragma unroll
    for (int o = 16; o > 0; o >>= 1) {
        s  += __shfl_down_sync(0xffffffffu, s,  o);
        ss += __shfl_down_sync(0xffffffffu, ss, o);
    }
    __shared__ float rs[8], rss[8], res[2];
    int lane = threadIdx.x & 31, wid = threadIdx.x >> 5;
    if (lane == 0) { rs[wid] = s; rss[wid] = ss; }
    __syncthreads();
    if (threadIdx.x == 0) {
        float S = 0.f, SS2 = 0.f;
        #pragma unroll
        for (int i = 0; i < 8; i++) { S += rs[i]; SS2 += rss[i]; }
        float m = S / n;
        float var = SS2 / n - m * m;
        res[0] = m; res[1] = rsqrtf(var + 1e-5f);
    }
    __syncthreads();
    *mu = res[0]; *rstd = res[1];
}

// ---------------- fp16 mma.sync GEMM (3-stage pipeline + ldmatrix) ----------
// C[M,N] = epi(A[M,K] @ W[N,K]^T + bias); A,W fp16; accum fp32.
// M%128==0, N%128==0, K%32==0.
#define EPI_NONE  0
#define EPI_GELU  1
#define EPI_SCALE 2

#define LDPAD_H 40
#define TILEH (128 * LDPAD_H)            // halves per tile
#define TGEMM_SMEM (6 * TILEH * 2)       // 3 stages x (A+B), bytes = 61440

__device__ __forceinline__ void mma_f16(float* c, const uint32_t* a,
                                        const uint32_t* b) {
    asm volatile(
        "mma.sync.aligned.m16n8k16.row.col.f32.f16.f16.f32 "
        "{%0,%1,%2,%3}, {%4,%5,%6,%7}, {%8,%9}, {%0,%1,%2,%3};"
        : "+f"(c[0]), "+f"(c[1]), "+f"(c[2]), "+f"(c[3])
        : "r"(a[0]), "r"(a[1]), "r"(a[2]), "r"(a[3]),
          "r"(b[0]), "r"(b[1]));
}

#define LDSM_X4(r0, r1, r2, r3, addr) \
    asm volatile("ldmatrix.sync.aligned.m8n8.x4.shared.b16 {%0,%1,%2,%3}, [%4];" \
        : "=r"(r0), "=r"(r1), "=r"(r2), "=r"(r3) : "r"(addr))

__device__ __forceinline__ void store2(float* p, float a, float b) {
    *(float2*)p = make_float2(a, b);
}
__device__ __forceinline__ void store2(__half* p, float a, float b) {
    *(__half2*)p = __floats2half2_rn(a, b);
}

template <int EPI, typename OutT>
__global__ __launch_bounds__(256)
void tgemm(const __half* __restrict__ A, const __half* __restrict__ W,
           const float* __restrict__ bias, OutT* __restrict__ C,
           int M, int N, int K, float alpha) {
    extern __shared__ __half smh[];
    __half* Abuf = smh;                  // [3][128][LDPAD_H]
    __half* Bbuf = smh + 3 * TILEH;      // [3][128][LDPAD_H]
    const uint32_t sm_a = s2u(Abuf), sm_b = s2u(Bbuf);

    const int tid = threadIdx.x;
    const int wid = tid >> 5, lane = tid & 31;
    const int m0 = blockIdx.y << 7, n0 = blockIdx.x << 7;
    const int wm = wid & 3, wn = wid >> 2;
    const int m_off = wm << 5;           // 32-row warp tile
    const int n_off = wn << 6;           // 64-col warp tile

    const __half* Abase = A + (size_t)m0 * K;
    const __half* Wbase = W + (size_t)n0 * K;
    const int NC = K >> 5;

    const int seg = tid & 3;             // 4 x 16B (8-half) segments per row
    const int lr0 = tid >> 2;            // 0..63

    auto load_chunk = [&](int c, int sel) {
        uint32_t ab = sm_a + sel * (TILEH * 2);
        uint32_t bb = sm_b + sel * (TILEH * 2);
        const __half* As = Abase + c * 32 + seg * 8;
        const __half* Ws = Wbase + c * 32 + seg * 8;
        #pragma unroll
        for (int i = 0; i < 2; i++) {
            int r = lr0 + (i << 6);      // 0..127
            uint32_t so = (uint32_t)(r * (LDPAD_H * 2) + seg * 16);
            asm volatile("cp.async.cg.shared.global [%0], [%1], 16;"
                         :: "r"(ab + so), "l"(As + (size_t)r * K));
            asm volatile("cp.async.cg.shared.global [%0], [%1], 16;"
                         :: "r"(bb + so), "l"(Ws + (size_t)r * K));
        }
        asm volatile("cp.async.commit_group;" ::: "memory");
    };

    // ldmatrix per-lane address offsets (bytes within a tile)
    const int lm = lane >> 3, lr = lane & 7;
    uint32_t a_off[2], b_off[4];
    #pragma unroll
    for (int mt = 0; mt < 2; mt++) {
        int row = m_off + mt * 16 + lr + (lm & 1) * 8;
        int koff = (lm >> 1) * 8;
        a_off[mt] = (uint32_t)((row * LDPAD_H + koff) * 2);
    }
    #pragma unroll
    for (int g = 0; g < 4; g++) {
        int row = n_off + (2 * g + (lm >> 1)) * 8 + lr;
        int koff = (lm & 1) * 8;
        b_off[g] = (uint32_t)((row * LDPAD_H + koff) * 2);
    }

    float acc[2][8][4];
    #pragma unroll
    for (int i = 0; i < 2; i++)
        #pragma unroll
        for (int j = 0; j < 8; j++)
            #pragma unroll
            for (int q = 0; q < 4; q++) acc[i][j][q] = 0.f;

    // prefetch 2 chunks (3-stage ring, distance 2)
    load_chunk(0, 0);
    if (NC > 1) load_chunk(1, 1);

    const int qr = lane >> 2, qc = lane & 3;
    int sel = 0;

    for (int c = 0; c < NC; c++) {
        if (c + 1 < NC)
            asm volatile("cp.async.wait_group 1;" ::: "memory");
        else
            asm volatile("cp.async.wait_group 0;" ::: "memory");
        __syncthreads();
        if (c + 2 < NC) {
            int s2 = sel + 2; if (s2 >= 3) s2 -= 3;
            load_chunk(c + 2, s2);
        }

        const uint32_t abase = sm_a + sel * (TILEH * 2);
        const uint32_t bbase = sm_b + sel * (TILEH * 2);

        #pragma unroll
        for (int ks = 0; ks < 2; ks++) {
            const uint32_t kb = ks * 32;      // 16 halves = 32 bytes
            uint32_t a[2][4], b[8][2];
            #pragma unroll
            for (int mt = 0; mt < 2; mt++)
                LDSM_X4(a[mt][0], a[mt][1], a[mt][2], a[mt][3],
                        abase + a_off[mt] + kb);
            #pragma unroll
            for (int g = 0; g < 4; g++)
                LDSM_X4(b[2 * g][0], b[2 * g][1], b[2 * g + 1][0], b[2 * g + 1][1],
                        bbase + b_off[g] + kb);
            #pragma unroll
            for (int mt = 0; mt < 2; mt++)
                #pragma unroll
                for (int nt = 0; nt < 8; nt++)
                    mma_f16(acc[mt][nt], a[mt], b[nt]);
        }
        if (++sel >= 3) sel = 0;
    }

    // epilogue
    #pragma unroll
    for (int mt = 0; mt < 2; mt++) {
        #pragma unroll
        for (int half = 0; half < 2; half++) {
            int row = m0 + m_off + mt * 16 + qr + half * 8;
            OutT* Cp = C + (size_t)row * N + n0 + n_off;
            #pragma unroll
            for (int nt = 0; nt < 8; nt++) {
                int col = nt * 8 + qc * 2;
                float v0 = acc[mt][nt][half * 2 + 0] + bias[n0 + n_off + col];
                float v1 = acc[mt][nt][half * 2 + 1] + bias[n0 + n_off + col + 1];
                if (EPI == EPI_GELU)  { v0 = gelu_exact(v0); v1 = gelu_exact(v1); }
                if (EPI == EPI_SCALE) { v0 *= alpha; v1 *= alpha; }
                store2(Cp + col, v0, v1);
            }
        }
    }
}

// ---------------- weight transpose + fp16:  Wt[n,k] = h(W[k,n]) ----
__global__ __launch_bounds__(256)
void transpose_w(const float* __restrict__ W, __half* __restrict__ Wt,
                 int K, int N) {
    __shared__ float tile[32][33];
    int kb = blockIdx.y * 32, nb = blockIdx.x * 32;
    int tx = threadIdx.x & 31, ty = threadIdx.x >> 5;
    #pragma unroll
    for (int i = 0; i < 32; i += 8)
        tile[ty + i][tx] = W[(size_t)(kb + ty + i) * N + nb + tx];
    __syncthreads();
    #pragma unroll
    for (int i = 0; i < 32; i += 8)
        Wt[(size_t)(nb + ty + i) * K + kb + tx] = __float2half_rn(tile[tx][ty + i]);
}

__global__ void half_copy(const float* __restrict__ in, __half* __restrict__ o, int n) {
    int i = blockIdx.x * 256 + threadIdx.x;
    if (i < n) o[i] = __float2half_rn(in[i]);
}

// ---------------- relative-position bias precompute ----------------
__global__ void bias_kernel(const float* __restrict__ w1, const float* __restrict__ b1,
                            const float* __restrict__ w2, const float* __restrict__ b2) {
    int pair = blockIdx.x;
    int q = pair / T_, k = pair % T_;
    float d0 = (float)(q / WS_ - k / WS_);
    float d1 = (float)(q % WS_ - k % WS_);
    float r0 = (d0 > 0.f ? 1.f : (d0 < 0.f ? -1.f : 0.f)) * log1pf(fabsf(d0));
    float r1 = (d1 > 0.f ? 1.f : (d1 < 0.f ? -1.f : 0.f)) * log1pf(fabsf(d1));
    int tid = threadIdx.x;
    __shared__ float hbuf[256];
    float hv = r0 * w1[tid] + r1 * w1[256 + tid] + b1[tid];
    hbuf[tid] = fmaxf(hv, 0.f);
    __syncthreads();
    if (tid < NH_) {
        float s = b2[tid];
        #pragma unroll 8
        for (int j = 0; j < 256; j++) s += hbuf[j] * w2[j * NH_ + tid];
        g_bias[tid * (T_ * T_) + pair] = s;
    }
}

// ---------------- roll(-3,-3) + unfold into token rows (fp16) ---------------
__global__ __launch_bounds__(256)
void unfold_kernel(const float* __restrict__ visual) {
    int r = blockIdx.x;
    int bw = r / T_, t = r % T_;
    int b = bw / NW_, win = bw % NW_, wh = win >> 3, ww = win & 7;
    int h = (wh * WS_ + t / WS_ + SS_) % HH;
    int w = (ww * WS_ + t % WS_ + SS_) % WW_;
    int hw = h * WW_ + w;
    for (int c = threadIdx.x; c < CC; c += 256)
        g_tok[(size_t)r * CC + c] = __float2half_rn(visual[(size_t)(b * CC + c) * HWSZ + hw]);
}

// ---------------- window attention ----------------
__global__ __launch_bounds__(256)
void win_attn(const float* __restrict__ tau) {
    int bw = blockIdx.x >> 4;
    int hh = blockIdx.x & 15;
    int tid = threadIdx.x;

    __shared__ float sq[T_ * HD_], sk[T_ * HD_], sv[T_ * HD_];
    __shared__ float ss[T_ * 50];
    __shared__ float nq[T_], nk[T_];
    __shared__ int   rg[T_];

    size_t base = (size_t)(bw * T_) * (3 * CC);
    for (int idx = tid; idx < T_ * HD_; idx += 256) {
        int t = idx / HD_, d = idx % HD_;
        size_t ro = base + (size_t)t * (3 * CC) + hh * HD_ + d;
        sq[idx] = g_qkv[ro];
        sk[idx] = g_qkv[ro + CC];
        sv[idx] = g_qkv[ro + 2 * CC];
    }
    int win = bw & 63, wh = win >> 3, ww = win & 7;
    if (tid < T_) {
        int row = wh * WS_ + tid / WS_;
        int col = ww * WS_ + tid % WS_;
        int rh = row < 49 ? 0 : (row < 53 ? 1 : 2);
        int rw = col < 49 ? 0 : (col < 53 ? 1 : 2);
        rg[tid] = rh * 3 + rw;
    }
    __syncthreads();

    if (tid < T_) {
        float s1 = 0.f, s2 = 0.f;
        #pragma unroll
        for (int d = 0; d < HD_; d++) {
            float a = sq[tid * HD_ + d], b = sk[tid * HD_ + d];
            s1 += a * a; s2 += b * b;
        }
        nq[tid] = sqrtf(s1); nk[tid] = sqrtf(s2);
    }
    __syncthreads();

    float tauh = fmaxf(tau[hh], 0.01f);
    const float* bh = &g_bias[hh * (T_ * T_)];
    for (int idx = tid; idx < T_ * T_; idx += 256) {
        int q = idx / T_, k = idx % T_;
        float dot = 0.f;
        #pragma unroll
        for (int d = 0; d < HD_; d++) dot += sq[q * HD_ + d] * sk[k * HD_ + d];
        float s = dot / fmaxf(nq[q] * nk[k], 1e-6f) / tauh + bh[idx];
        if (rg[q] != rg[k]) s -= 100.0f;
        ss[q * 50 + k] = s;
    }
    __syncthreads();

    if (tid < T_) {
        float m = -1e30f;
        for (int k = 0; k < T_; k++) m = fmaxf(m, ss[tid * 50 + k]);
        float sum = 0.f;
        for (int k = 0; k < T_; k++) {
            float e = expf(ss[tid * 50 + k] - m);
            ss[tid * 50 + k] = e; sum += e;
        }
        float inv = 1.f / sum;
        for (int k = 0; k < T_; k++) ss[tid * 50 + k] *= inv;
    }
    __syncthreads();

    for (int idx = tid; idx < T_ * HD_; idx += 256) {
        int t = idx / HD_, d = idx % HD_;
        float acc = 0.f;
        #pragma unroll
        for (int k = 0; k < T_; k++) acc += ss[t * 50 + k] * sv[k * HD_ + d];
        g_o1[(size_t)(bw * T_ + t) * CC + hh * HD_ + d] = __float2half_rn(acc);
    }
}

// ---------------- fold+roll(+3) + LN1 + residual; emit CA query tokens ------
__global__ __launch_bounds__(256)
void merge_ln1(const float* __restrict__ visual,
               const float* __restrict__ g, const float* __restrict__ bt) {
    int pos = blockIdx.x;
    int b = pos / HWSZ, hw = pos % HWSZ;
    int h = hw / WW_, w = hw % WW_;
    int hp = (h + HH - SS_) % HH, wp = (w + WW_ - SS_) % WW_;
    int rm = (b * NW_ + (hp / WS_) * 8 + (wp / WS_)) * T_ + (hp % WS_) * WS_ + (wp % WS_);

    __shared__ float x[CC];
    int tid = threadIdx.x;
    float s = 0.f, ss2 = 0.f;
    for (int c = tid; c < CC; c += 256) {
        float v = g_w2[(size_t)rm * CC + c];
        x[c] = v; s += v; ss2 += v * v;
    }
    float mu, rstd;
    block_meanvar(s, ss2, CC, &mu, &rstd);
    for (int c = tid; c < CC; c += 256) {
        float v = (x[c] - mu) * rstd * g[c] + bt[c]
                + visual[(size_t)(b * CC + c) * HWSZ + hw];
        g_skipa[(size_t)pos * CC + c] = v;
        g_pq  [(size_t)rm  * CC + c] = __float2half_rn(v);
    }
}

// ---------------- cross attention ----------------
__global__ __launch_bounds__(256)
void ca_attn() {
    int bw = blockIdx.x >> 4;
    int hh = blockIdx.x & 15;
    int bkv = bw & 7;
    int tid = threadIdx.x;

    __shared__ float sq[T_ * HD_], sk[L_ * HD_], sv[L_ * HD_];
    __shared__ float ss[T_ * 65];

    for (int idx = tid; idx < T_ * HD_; idx += 256) {
        int t = idx / HD_, d = idx % HD_;
        sq[idx] = g_q2[(size_t)(bw * T_ + t) * CC + hh * HD_ + d];
    }
    for (int idx = tid; idx < L_ * HD_; idx += 256) {
        int l = idx / HD_, d = idx % HD_;
        size_t ro = (size_t)(bkv * L_ + l) * CC + hh * HD_ + d;
        sk[idx] = g_k2[ro];
        sv[idx] = g_v2[ro];
    }
    __syncthreads();

    for (int idx = tid; idx < T_ * L_; idx += 256) {
        int q = idx / L_, l = idx % L_;
        float dot = 0.f;
        #pragma unroll
        for (int d = 0; d < HD_; d++) dot += sq[q * HD_ + d] * sk[l * HD_ + d];
        ss[q * 65 + l] = dot;
    }
    __syncthreads();

    if (tid < T_) {
        float m = -1e30f;
        for (int l = 0; l < L_; l++) m = fmaxf(m, ss[tid * 65 + l]);
        float sum = 0.f;
        for (int l = 0; l < L_; l++) {
            float e = expf(ss[tid * 65 + l] - m);
            ss[tid * 65 + l] = e; sum += e;
        }
        float inv = 1.f / sum;
        for (int l = 0; l < L_; l++) ss[tid * 65 + l] *= inv;
    }
    __syncthreads();

    for (int idx = tid; idx < T_ * HD_; idx += 256) {
        int t = idx / HD_, d = idx % HD_;
        float acc = 0.f;
        #pragma unroll
        for (int l = 0; l < L_; l++) acc += ss[t * 65 + l] * sv[l * HD_ + d];
        g_co1[(size_t)(bw * T_ + t) * CC + hh * HD_ + d] = __float2half_rn(acc);
    }
}

// ---------------- LN2 + fold+roll(+3) + residual ----------------
__global__ __launch_bounds__(256)
void ca_ln2(const float* __restrict__ g, const float* __restrict__ bt) {
    int r = blockIdx.x;
    int bw = r / T_, t = r % T_;
    int b = bw / NW_, win = bw % NW_, wh = win >> 3, ww = win & 7;
    int h = (wh * WS_ + t / WS_ + SS_) % HH;
    int w = (ww * WS_ + t % WS_ + SS_) % WW_;
    int pos = b * HWSZ + h * WW_ + w;

    __shared__ float x[CC];
    int tid = threadIdx.x;
    float s = 0.f, ss2 = 0.f;
    for (int c = tid; c < CC; c += 256) {
        float v = g_co2[(size_t)r * CC + c];
        x[c] = v; s += v; ss2 += v * v;
    }
    float mu, rstd;
    block_meanvar(s, ss2, CC, &mu, &rstd);
    for (int c = tid; c < CC; c += 256) {
        float v = (x[c] - mu) * rstd * g[c] + bt[c]
                + g_skipa[(size_t)pos * CC + c];
        g_skip2 [(size_t)pos * CC + c] = v;
        g_skip2r[(size_t)pos * CC + c] = __float2half_rn(v);
    }
}

// ---------------- LN3(ff) + skip2, write [B,C,H,W] ----------------
__global__ __launch_bounds__(256)
void final_kernel(float* __restrict__ out,
                  const float* __restrict__ g, const float* __restrict__ bt) {
    int pos = blockIdx.x;
    int b = pos / HWSZ, hw = pos % HWSZ;

    __shared__ float x[CC];
    int tid = threadIdx.x;
    float s = 0.f, ss2 = 0.f;
    for (int c = tid; c < CC; c += 256) {
        float v = g_ffo[(size_t)pos * CC + c];
        x[c] = v; s += v; ss2 += v * v;
    }
    float mu, rstd;
    block_meanvar(s, ss2, CC, &mu, &rstd);
    for (int c = tid; c < CC; c += 256) {
        float v = (x[c] - mu) * rstd * g[c] + bt[c];
        out[(size_t)(b * CC + c) * HWSZ + hw] = g_skip2[(size_t)pos * CC + c] + v;
    }
}

// ---------------- launch ----------------
extern "C" void kernel_launch(void* const* d_in, const int* in_sizes, int n_in,
                              void* d_out, int out_size) {
    const float* visual   = (const float*)d_in[0];
    const float* vector   = (const float*)d_in[1];
    const float* tm_w     = (const float*)d_in[2];
    const float* tm_b     = (const float*)d_in[3];
    const float* ln1_g    = (const float*)d_in[4];
    const float* ln1_b    = (const float*)d_in[5];
    const float* ln2_g    = (const float*)d_in[6];
    const float* ln2_b    = (const float*)d_in[7];
    const float* ln3_g    = (const float*)d_in[8];
    const float* ln3_b    = (const float*)d_in[9];
    const float* qkv_w    = (const float*)d_in[10];
    const float* qkv_b    = (const float*)d_in[11];
    const float* wproj_w  = (const float*)d_in[12];
    const float* wproj_b  = (const float*)d_in[13];
    const float* meta_w1  = (const float*)d_in[14];
    const float* meta_b1  = (const float*)d_in[15];
    const float* meta_w2  = (const float*)d_in[16];
    const float* meta_b2  = (const float*)d_in[17];
    const float* tau      = (const float*)d_in[18];
    const float* ca_in_w  = (const float*)d_in[19];
    const float* ca_in_b  = (const float*)d_in[20];
    const float* ca_out_w = (const float*)d_in[21];
    const float* ca_out_b = (const float*)d_in[22];
    const float* ff_w1    = (const float*)d_in[23];
    const float* ff_b1    = (const float*)d_in[24];
    const float* ff_w2    = (const float*)d_in[25];
    const float* ff_b2    = (const float*)d_in[26];
    float* out = (float*)d_out;

    __half *vin, *vec, *tok, *o1, *pq, *co1, *sk2r, *ffh;
    float  *qkv, *w2, *q2, *k2, *v2, *co2, *ffo;
    __half *tmwt, *qkvwt, *wprwt, *caint, *caoutt, *ff1t, *ff2t;
    cudaGetSymbolAddress((void**)&vin,   g_vin);
    cudaGetSymbolAddress((void**)&vec,   g_vec);
    cudaGetSymbolAddress((void**)&tok,   g_tok);
    cudaGetSymbolAddress((void**)&qkv,   g_qkv);
    cudaGetSymbolAddress((void**)&o1,    g_o1);
    cudaGetSymbolAddress((void**)&w2,    g_w2);
    cudaGetSymbolAddress((void**)&pq,    g_pq);
    cudaGetSymbolAddress((void**)&q2,    g_q2);
    cudaGetSymbolAddress((void**)&k2,    g_k2);
    cudaGetSymbolAddress((void**)&v2,    g_v2);
    cudaGetSymbolAddress((void**)&co1,   g_co1);
    cudaGetSymbolAddress((void**)&co2,   g_co2);
    cudaGetSymbolAddress((void**)&sk2r,  g_skip2r);
    cudaGetSymbolAddress((void**)&ffh,   g_ffh);
    cudaGetSymbolAddress((void**)&ffo,   g_ffo);
    cudaGetSymbolAddress((void**)&tmwt,  g_tmw_t);
    cudaGetSymbolAddress((void**)&qkvwt, g_qkvw_t);
    cudaGetSymbolAddress((void**)&wprwt, g_wprw_t);
    cudaGetSymbolAddress((void**)&caint, g_cain_t);
    cudaGetSymbolAddress((void**)&caoutt,g_caout_t);
    cudaGetSymbolAddress((void**)&ff1t,  g_ff1_t);
    cudaGetSymbolAddress((void**)&ff2t,  g_ff2_t);

    cudaFuncSetAttribute((const void*)tgemm<EPI_NONE,  float>,  cudaFuncAttributeMaxDynamicSharedMemorySize, TGEMM_SMEM);
    cudaFuncSetAttribute((const void*)tgemm<EPI_GELU,  __half>, cudaFuncAttributeMaxDynamicSharedMemorySize, TGEMM_SMEM);
    cudaFuncSetAttribute((const void*)tgemm<EPI_SCALE, float>,  cudaFuncAttributeMaxDynamicSharedMemorySize, TGEMM_SMEM);

    // weight transposes (+fp16 rounding)
    transpose_w<<<dim3(16,  8), 256>>>(tm_w,     tmwt,  256,  512);
    transpose_w<<<dim3(48, 16), 256>>>(qkv_w,    qkvwt, 512, 1536);
    transpose_w<<<dim3(16, 16), 256>>>(wproj_w,  wprwt, 512,  512);
    transpose_w<<<dim3(48, 16), 256>>>(ca_in_w,  caint, 512, 1536);
    transpose_w<<<dim3(16, 16), 256>>>(ca_out_w, caoutt,512,  512);
    transpose_w<<<dim3(64, 16), 256>>>(ff_w1,    ff1t,  512, 2048);
    transpose_w<<<dim3(16, 64), 256>>>(ff_w2,    ff2t, 2048,  512);
    half_copy<<<512, 256>>>(vector, vin, 512 * 256);

    bias_kernel<<<T_ * T_, 256>>>(meta_w1, meta_b1, meta_w2, meta_b2);

    // vec = gelu(vector @ tm_w + tm_b)   (fp16 out)
    tgemm<EPI_GELU, __half><<<dim3(4, 4), 256, TGEMM_SMEM>>>(vin, tmwt, tm_b, vec, 512, 512, 256, 0.f);
    // K2/V2 (only B distinct kv sets)
    tgemm<EPI_NONE, float><<<dim3(4, 4), 256, TGEMM_SMEM>>>(vec, caint + 512 * 512,  ca_in_b + 512,  k2, 512, 512, 512, 0.f);
    tgemm<EPI_NONE, float><<<dim3(4, 4), 256, TGEMM_SMEM>>>(vec, caint + 1024 * 512, ca_in_b + 1024, v2, 512, 512, 512, 0.f);

    unfold_kernel<<<NTOK, 256>>>(visual);
    tgemm<EPI_NONE, float><<<dim3(12, 196), 256, TGEMM_SMEM>>>(tok, qkvwt, qkv_b, qkv, NTOK, 3 * CC, CC, 0.f);
    win_attn<<<BW_ * NH_, 256>>>(tau);
    tgemm<EPI_NONE, float><<<dim3(4, 196), 256, TGEMM_SMEM>>>(o1, wprwt, wproj_b, w2, NTOK, CC, CC, 0.f);
    merge_ln1<<<BB * HWSZ, 256>>>(visual, ln1_g, ln1_b);
    tgemm<EPI_SCALE, float><<<dim3(4, 196), 256, TGEMM_SMEM>>>(pq, caint, ca_in_b, q2, NTOK, CC, CC, 0.17677669529663687f);
    ca_attn<<<BW_ * NH_, 256>>>();
    tgemm<EPI_NONE, float><<<dim3(4, 196), 256, TGEMM_SMEM>>>(co1, caoutt, ca_out_b, co2, NTOK, CC, CC, 0.f);
    ca_ln2<<<NTOK, 256>>>(ln2_g, ln2_b);
    tgemm<EPI_GELU, __half><<<dim3(16, 196), 256, TGEMM_SMEM>>>(sk2r, ff1t, ff_b1, ffh, NTOK, 4 * CC, CC, 0.f);
    tgemm<EPI_NONE, float><<<dim3(4, 196), 256, TGEMM_SMEM>>>(ffh, ff2t, ff_b2, ffo, NTOK, CC, 2048, 0.f);
    final_kernel<<<BB * HWSZ, 256>>>(out, ln3_g, ln3_b);
}

// round 10
// speedup vs baseline: 1.5617x; 1.0153x over previous
#include <cuda_runtime.h>
#include <cuda_fp16.h>
#include <math.h>
#include <stdint.h>

// Problem constants
#define BB    8
#define CC    512
#define HH    56
#define WW_   56
#define HWSZ  3136
#define WS_   7
#define SS_   3
#define NH_   16
#define HD_   32
#define T_    49
#define NW_   64
#define BW_   512          // BB * NW_
#define NTOK  25088        // BW_ * T_
#define L_    64

// ---------------- scratch (device globals; no runtime alloc) ----------------
__device__ __align__(16) __half g_vin [512 * 256];
__device__ __align__(16) __half g_vec [BW_ * CC];
__device__ __align__(16) __half g_tok [NTOK * CC];
__device__ float  g_qkv [NTOK * 3 * CC];
__device__ __align__(16) __half g_o1  [NTOK * CC];
__device__ float  g_w2  [NTOK * CC];
__device__ float  g_skipa[NTOK * CC];       // skip1 [B,HW,C] full fp32
__device__ __align__(16) __half g_pq  [NTOK * CC];
__device__ float  g_q2  [NTOK * CC];
__device__ float  g_kv2 [BW_ * 2 * CC];     // [B*L, 1024]: k | v concat
__device__ __align__(16) __half g_co1 [NTOK * CC];
__device__ float  g_co2 [NTOK * CC];
__device__ float  g_skip2[NTOK * CC];       // full fp32
__device__ __align__(16) __half g_skip2r[NTOK * CC]; // fp16 copy for GEMM
__device__ __align__(16) __half g_ffh [NTOK * 4 * CC];
__device__ float  g_ffo [NTOK * CC];
__device__ float  g_bias[NH_ * T_ * T_];

// transposed (fp16) weights: [N, K] K-contiguous
__device__ __align__(16) __half g_tmw_t  [512 * 256];
__device__ __align__(16) __half g_qkvw_t [1536 * 512];
__device__ __align__(16) __half g_wprw_t [512 * 512];
__device__ __align__(16) __half g_cain_t [1536 * 512];
__device__ __align__(16) __half g_caout_t[512 * 512];
__device__ __align__(16) __half g_ff1_t  [2048 * 512];
__device__ __align__(16) __half g_ff2_t  [512 * 2048];

// ---------------- helpers ----------------
__device__ __forceinline__ float gelu_exact(float x) {
    return 0.5f * x * (1.0f + erff(x * 0.70710678118654752f));
}
__device__ __forceinline__ uint32_t s2u(const void* p) {
    uint32_t a;
    asm("{ .reg .u64 t; cvta.to.shared.u64 t, %1; cvt.u32.u64 %0, t; }"
        : "=r"(a) : "l"(p));
    return a;
}

__device__ __forceinline__ void block_meanvar(float s, float ss, int n,
                                              float* mu, float* rstd) {
    #pragma unroll
    for (int o = 16; o > 0; o >>= 1) {
        s  += __shfl_down_sync(0xffffffffu, s,  o);
        ss += __shfl_down_sync(0xffffffffu, ss, o);
    }
    __shared__ float rs[8], rss[8], res[2];
    int lane = threadIdx.x & 31, wid = threadIdx.x >> 5;
    if (lane == 0) { rs[wid] = s; rss[wid] = ss; }
    __syncthreads();
    if (threadIdx.x == 0) {
        float S = 0.f, SS2 = 0.f;
        #pragma unroll
        for (int i = 0; i < 8; i++) { S += rs[i]; SS2 += rss[i]; }
        float m = S / n;
        float var = SS2 / n - m * m;
        res[0] = m; res[1] = rsqrtf(var + 1e-5f);
    }
    __syncthreads();
    *mu = res[0]; *rstd = res[1];
}

// ---------------- fp16 mma.sync GEMM (3-stage pipeline + ldmatrix) ----------
// C[M,N] = epi(A[M,K] @ W[N,K]^T + bias); A,W fp16; accum fp32.
// M%128==0, N%128==0, K%32==0.
#define EPI_NONE  0
#define EPI_GELU  1
#define EPI_SCALE 2

#define LDPAD_H 40
#define TILEH (128 * LDPAD_H)            // halves per tile
#define TGEMM_SMEM (6 * TILEH * 2)       // 3 stages x (A+B), bytes = 61440

__device__ __forceinline__ void mma_f16(float* c, const uint32_t* a,
                                        const uint32_t* b) {
    asm volatile(
        "mma.sync.aligned.m16n8k16.row.col.f32.f16.f16.f32 "
        "{%0,%1,%2,%3}, {%4,%5,%6,%7}, {%8,%9}, {%0,%1,%2,%3};"
        : "+f"(c[0]), "+f"(c[1]), "+f"(c[2]), "+f"(c[3])
        : "r"(a[0]), "r"(a[1]), "r"(a[2]), "r"(a[3]),
          "r"(b[0]), "r"(b[1]));
}

#define LDSM_X4(r0, r1, r2, r3, addr) \
    asm volatile("ldmatrix.sync.aligned.m8n8.x4.shared.b16 {%0,%1,%2,%3}, [%4];" \
        : "=r"(r0), "=r"(r1), "=r"(r2), "=r"(r3) : "r"(addr))

__device__ __forceinline__ void store2(float* p, float a, float b) {
    *(float2*)p = make_float2(a, b);
}
__device__ __forceinline__ void store2(__half* p, float a, float b) {
    *(__half2*)p = __floats2half2_rn(a, b);
}

template <int EPI, typename OutT>
__global__ __launch_bounds__(256, 2)
void tgemm(const __half* __restrict__ A, const __half* __restrict__ W,
           const float* __restrict__ bias, OutT* __restrict__ C,
           int M, int N, int K, float alpha) {
    extern __shared__ __half smh[];
    __half* Abuf = smh;                  // [3][128][LDPAD_H]
    __half* Bbuf = smh + 3 * TILEH;      // [3][128][LDPAD_H]
    const uint32_t sm_a = s2u(Abuf), sm_b = s2u(Bbuf);

    const int tid = threadIdx.x;
    const int wid = tid >> 5, lane = tid & 31;
    const int m0 = blockIdx.y << 7, n0 = blockIdx.x << 7;
    const int wm = wid & 3, wn = wid >> 2;
    const int m_off = wm << 5;           // 32-row warp tile
    const int n_off = wn << 6;           // 64-col warp tile

    const __half* Abase = A + (size_t)m0 * K;
    const __half* Wbase = W + (size_t)n0 * K;
    const int NC = K >> 5;

    const int seg = tid & 3;             // 4 x 16B (8-half) segments per row
    const int lr0 = tid >> 2;            // 0..63

    auto load_chunk = [&](int c, int sel) {
        uint32_t ab = sm_a + sel * (TILEH * 2);
        uint32_t bb = sm_b + sel * (TILEH * 2);
        const __half* As = Abase + c * 32 + seg * 8;
        const __half* Ws = Wbase + c * 32 + seg * 8;
        #pragma unroll
        for (int i = 0; i < 2; i++) {
            int r = lr0 + (i << 6);      // 0..127
            uint32_t so = (uint32_t)(r * (LDPAD_H * 2) + seg * 16);
            asm volatile("cp.async.cg.shared.global [%0], [%1], 16;"
                         :: "r"(ab + so), "l"(As + (size_t)r * K));
            asm volatile("cp.async.cg.shared.global [%0], [%1], 16;"
                         :: "r"(bb + so), "l"(Ws + (size_t)r * K));
        }
        asm volatile("cp.async.commit_group;" ::: "memory");
    };

    // ldmatrix per-lane address offsets (bytes within a tile)
    const int lm = lane >> 3, lr = lane & 7;
    uint32_t a_off[2], b_off[4];
    #pragma unroll
    for (int mt = 0; mt < 2; mt++) {
        int row = m_off + mt * 16 + lr + (lm & 1) * 8;
        int koff = (lm >> 1) * 8;
        a_off[mt] = (uint32_t)((row * LDPAD_H + koff) * 2);
    }
    #pragma unroll
    for (int g = 0; g < 4; g++) {
        int row = n_off + (2 * g + (lm >> 1)) * 8 + lr;
        int koff = (lm & 1) * 8;
        b_off[g] = (uint32_t)((row * LDPAD_H + koff) * 2);
    }

    float acc[2][8][4];
    #pragma unroll
    for (int i = 0; i < 2; i++)
        #pragma unroll
        for (int j = 0; j < 8; j++)
            #pragma unroll
            for (int q = 0; q < 4; q++) acc[i][j][q] = 0.f;

    // prefetch 2 chunks (3-stage ring, distance 2)
    load_chunk(0, 0);
    if (NC > 1) load_chunk(1, 1);

    const int qr = lane >> 2, qc = lane & 3;
    int sel = 0;

    for (int c = 0; c < NC; c++) {
        if (c + 1 < NC)
            asm volatile("cp.async.wait_group 1;" ::: "memory");
        else
            asm volatile("cp.async.wait_group 0;" ::: "memory");
        __syncthreads();
        if (c + 2 < NC) {
            int s2 = sel + 2; if (s2 >= 3) s2 -= 3;
            load_chunk(c + 2, s2);
        }

        const uint32_t abase = sm_a + sel * (TILEH * 2);
        const uint32_t bbase = sm_b + sel * (TILEH * 2);

        #pragma unroll
        for (int ks = 0; ks < 2; ks++) {
            const uint32_t kb = ks * 32;      // 16 halves = 32 bytes
            uint32_t a[2][4], b[8][2];
            #pragma unroll
            for (int mt = 0; mt < 2; mt++)
                LDSM_X4(a[mt][0], a[mt][1], a[mt][2], a[mt][3],
                        abase + a_off[mt] + kb);
            #pragma unroll
            for (int g = 0; g < 4; g++)
                LDSM_X4(b[2 * g][0], b[2 * g][1], b[2 * g + 1][0], b[2 * g + 1][1],
                        bbase + b_off[g] + kb);
            #pragma unroll
            for (int mt = 0; mt < 2; mt++)
                #pragma unroll
                for (int nt = 0; nt < 8; nt++)
                    mma_f16(acc[mt][nt], a[mt], b[nt]);
        }
        if (++sel >= 3) sel = 0;
    }

    // epilogue
    #pragma unroll
    for (int mt = 0; mt < 2; mt++) {
        #pragma unroll
        for (int half = 0; half < 2; half++) {
            int row = m0 + m_off + mt * 16 + qr + half * 8;
            OutT* Cp = C + (size_t)row * N + n0 + n_off;
            #pragma unroll
            for (int nt = 0; nt < 8; nt++) {
                int col = nt * 8 + qc * 2;
                float v0 = acc[mt][nt][half * 2 + 0] + bias[n0 + n_off + col];
                float v1 = acc[mt][nt][half * 2 + 1] + bias[n0 + n_off + col + 1];
                if (EPI == EPI_GELU)  { v0 = gelu_exact(v0); v1 = gelu_exact(v1); }
                if (EPI == EPI_SCALE) { v0 *= alpha; v1 *= alpha; }
                store2(Cp + col, v0, v1);
            }
        }
    }
}

// ---------------- weight transpose + fp16:  Wt[n,k] = h(W[k,n]) ----
__global__ __launch_bounds__(256)
void transpose_w(const float* __restrict__ W, __half* __restrict__ Wt,
                 int K, int N) {
    __shared__ float tile[32][33];
    int kb = blockIdx.y * 32, nb = blockIdx.x * 32;
    int tx = threadIdx.x & 31, ty = threadIdx.x >> 5;
    #pragma unroll
    for (int i = 0; i < 32; i += 8)
        tile[ty + i][tx] = W[(size_t)(kb + ty + i) * N + nb + tx];
    __syncthreads();
    #pragma unroll
    for (int i = 0; i < 32; i += 8)
        Wt[(size_t)(nb + ty + i) * K + kb + tx] = __float2half_rn(tile[tx][ty + i]);
}

__global__ void half_copy(const float* __restrict__ in, __half* __restrict__ o, int n) {
    int i = blockIdx.x * 256 + threadIdx.x;
    if (i < n) o[i] = __float2half_rn(in[i]);
}

// ---------------- relative-position bias precompute ----------------
__global__ void bias_kernel(const float* __restrict__ w1, const float* __restrict__ b1,
                            const float* __restrict__ w2, const float* __restrict__ b2) {
    int pair = blockIdx.x;
    int q = pair / T_, k = pair % T_;
    float d0 = (float)(q / WS_ - k / WS_);
    float d1 = (float)(q % WS_ - k % WS_);
    float r0 = (d0 > 0.f ? 1.f : (d0 < 0.f ? -1.f : 0.f)) * log1pf(fabsf(d0));
    float r1 = (d1 > 0.f ? 1.f : (d1 < 0.f ? -1.f : 0.f)) * log1pf(fabsf(d1));
    int tid = threadIdx.x;
    __shared__ float hbuf[256];
    float hv = r0 * w1[tid] + r1 * w1[256 + tid] + b1[tid];
    hbuf[tid] = fmaxf(hv, 0.f);
    __syncthreads();
    if (tid < NH_) {
        float s = b2[tid];
        #pragma unroll 8
        for (int j = 0; j < 256; j++) s += hbuf[j] * w2[j * NH_ + tid];
        g_bias[tid * (T_ * T_) + pair] = s;
    }
}

// ---------------- roll(-3,-3) + unfold into token rows (fp16) ---------------
__global__ __launch_bounds__(256)
void unfold_kernel(const float* __restrict__ visual) {
    int r = blockIdx.x;
    int bw = r / T_, t = r % T_;
    int b = bw / NW_, win = bw % NW_, wh = win >> 3, ww = win & 7;
    int h = (wh * WS_ + t / WS_ + SS_) % HH;
    int w = (ww * WS_ + t % WS_ + SS_) % WW_;
    int hw = h * WW_ + w;
    for (int c = threadIdx.x; c < CC; c += 256)
        g_tok[(size_t)r * CC + c] = __float2half_rn(visual[(size_t)(b * CC + c) * HWSZ + hw]);
}

// ---------------- window attention ----------------
__global__ __launch_bounds__(256)
void win_attn(const float* __restrict__ tau) {
    int bw = blockIdx.x >> 4;
    int hh = blockIdx.x & 15;
    int tid = threadIdx.x;

    __shared__ float sq[T_ * HD_], sk[T_ * HD_], sv[T_ * HD_];
    __shared__ float ss[T_ * 50];
    __shared__ float nq[T_], nk[T_];
    __shared__ int   rg[T_];

    size_t base = (size_t)(bw * T_) * (3 * CC);
    for (int idx = tid; idx < T_ * HD_; idx += 256) {
        int t = idx / HD_, d = idx % HD_;
        size_t ro = base + (size_t)t * (3 * CC) + hh * HD_ + d;
        sq[idx] = g_qkv[ro];
        sk[idx] = g_qkv[ro + CC];
        sv[idx] = g_qkv[ro + 2 * CC];
    }
    int win = bw & 63, wh = win >> 3, ww = win & 7;
    if (tid < T_) {
        int row = wh * WS_ + tid / WS_;
        int col = ww * WS_ + tid % WS_;
        int rh = row < 49 ? 0 : (row < 53 ? 1 : 2);
        int rw = col < 49 ? 0 : (col < 53 ? 1 : 2);
        rg[tid] = rh * 3 + rw;
    }
    __syncthreads();

    if (tid < T_) {
        float s1 = 0.f, s2 = 0.f;
        #pragma unroll
        for (int d = 0; d < HD_; d++) {
            float a = sq[tid * HD_ + d], b = sk[tid * HD_ + d];
            s1 += a * a; s2 += b * b;
        }
        nq[tid] = sqrtf(s1); nk[tid] = sqrtf(s2);
    }
    __syncthreads();

    float tauh = fmaxf(tau[hh], 0.01f);
    const float* bh = &g_bias[hh * (T_ * T_)];
    for (int idx = tid; idx < T_ * T_; idx += 256) {
        int q = idx / T_, k = idx % T_;
        float dot = 0.f;
        #pragma unroll
        for (int d = 0; d < HD_; d++) dot += sq[q * HD_ + d] * sk[k * HD_ + d];
        float s = dot / fmaxf(nq[q] * nk[k], 1e-6f) / tauh + bh[idx];
        if (rg[q] != rg[k]) s -= 100.0f;
        ss[q * 50 + k] = s;
    }
    __syncthreads();

    if (tid < T_) {
        float m = -1e30f;
        for (int k = 0; k < T_; k++) m = fmaxf(m, ss[tid * 50 + k]);
        float sum = 0.f;
        for (int k = 0; k < T_; k++) {
            float e = expf(ss[tid * 50 + k] - m);
            ss[tid * 50 + k] = e; sum += e;
        }
        float inv = 1.f / sum;
        for (int k = 0; k < T_; k++) ss[tid * 50 + k] *= inv;
    }
    __syncthreads();

    for (int idx = tid; idx < T_ * HD_; idx += 256) {
        int t = idx / HD_, d = idx % HD_;
        float acc = 0.f;
        #pragma unroll
        for (int k = 0; k < T_; k++) acc += ss[t * 50 + k] * sv[k * HD_ + d];
        g_o1[(size_t)(bw * T_ + t) * CC + hh * HD_ + d] = __float2half_rn(acc);
    }
}

// ---------------- fold+roll(+3) + LN1 + residual; emit CA query tokens ------
__global__ __launch_bounds__(256)
void merge_ln1(const float* __restrict__ visual,
               const float* __restrict__ g, const float* __restrict__ bt) {
    int pos = blockIdx.x;
    int b = pos / HWSZ, hw = pos % HWSZ;
    int h = hw / WW_, w = hw % WW_;
    int hp = (h + HH - SS_) % HH, wp = (w + WW_ - SS_) % WW_;
    int rm = (b * NW_ + (hp / WS_) * 8 + (wp / WS_)) * T_ + (hp % WS_) * WS_ + (wp % WS_);

    __shared__ float x[CC];
    int tid = threadIdx.x;
    float s = 0.f, ss2 = 0.f;
    for (int c = tid; c < CC; c += 256) {
        float v = g_w2[(size_t)rm * CC + c];
        x[c] = v; s += v; ss2 += v * v;
    }
    float mu, rstd;
    block_meanvar(s, ss2, CC, &mu, &rstd);
    for (int c = tid; c < CC; c += 256) {
        float v = (x[c] - mu) * rstd * g[c] + bt[c]
                + visual[(size_t)(b * CC + c) * HWSZ + hw];
        g_skipa[(size_t)pos * CC + c] = v;
        g_pq  [(size_t)rm  * CC + c] = __float2half_rn(v);
    }
}

// ---------------- cross attention ----------------
__global__ __launch_bounds__(256)
void ca_attn() {
    int bw = blockIdx.x >> 4;
    int hh = blockIdx.x & 15;
    int bkv = bw & 7;
    int tid = threadIdx.x;

    __shared__ float sq[T_ * HD_], sk[L_ * HD_], sv[L_ * HD_];
    __shared__ float ss[T_ * 65];

    for (int idx = tid; idx < T_ * HD_; idx += 256) {
        int t = idx / HD_, d = idx % HD_;
        sq[idx] = g_q2[(size_t)(bw * T_ + t) * CC + hh * HD_ + d];
    }
    for (int idx = tid; idx < L_ * HD_; idx += 256) {
        int l = idx / HD_, d = idx % HD_;
        size_t ro = (size_t)(bkv * L_ + l) * (2 * CC) + hh * HD_ + d;
        sk[idx] = g_kv2[ro];
        sv[idx] = g_kv2[ro + CC];
    }
    __syncthreads();

    for (int idx = tid; idx < T_ * L_; idx += 256) {
        int q = idx / L_, l = idx % L_;
        float dot = 0.f;
        #pragma unroll
        for (int d = 0; d < HD_; d++) dot += sq[q * HD_ + d] * sk[l * HD_ + d];
        ss[q * 65 + l] = dot;
    }
    __syncthreads();

    if (tid < T_) {
        float m = -1e30f;
        for (int l = 0; l < L_; l++) m = fmaxf(m, ss[tid * 65 + l]);
        float sum = 0.f;
        for (int l = 0; l < L_; l++) {
            float e = expf(ss[tid * 65 + l] - m);
            ss[tid * 65 + l] = e; sum += e;
        }
        float inv = 1.f / sum;
        for (int l = 0; l < L_; l++) ss[tid * 65 + l] *= inv;
    }
    __syncthreads();

    for (int idx = tid; idx < T_ * HD_; idx += 256) {
        int t = idx / HD_, d = idx % HD_;
        float acc = 0.f;
        #pragma unroll
        for (int l = 0; l < L_; l++) acc += ss[t * 65 + l] * sv[l * HD_ + d];
        g_co1[(size_t)(bw * T_ + t) * CC + hh * HD_ + d] = __float2half_rn(acc);
    }
}

// ---------------- LN2 + fold+roll(+3) + residual ----------------
__global__ __launch_bounds__(256)
void ca_ln2(const float* __restrict__ g, const float* __restrict__ bt) {
    int r = blockIdx.x;
    int bw = r / T_, t = r % T_;
    int b = bw / NW_, win = bw % NW_, wh = win >> 3, ww = win & 7;
    int h = (wh * WS_ + t / WS_ + SS_) % HH;
    int w = (ww * WS_ + t % WS_ + SS_) % WW_;
    int pos = b * HWSZ + h * WW_ + w;

    __shared__ float x[CC];
    int tid = threadIdx.x;
    float s = 0.f, ss2 = 0.f;
    for (int c = tid; c < CC; c += 256) {
        float v = g_co2[(size_t)r * CC + c];
        x[c] = v; s += v; ss2 += v * v;
    }
    float mu, rstd;
    block_meanvar(s, ss2, CC, &mu, &rstd);
    for (int c = tid; c < CC; c += 256) {
        float v = (x[c] - mu) * rstd * g[c] + bt[c]
                + g_skipa[(size_t)pos * CC + c];
        g_skip2 [(size_t)pos * CC + c] = v;
        g_skip2r[(size_t)pos * CC + c] = __float2half_rn(v);
    }
}

// ---------------- LN3(ff) + skip2, write [B,C,H,W] ----------------
__global__ __launch_bounds__(256)
void final_kernel(float* __restrict__ out,
                  const float* __restrict__ g, const float* __restrict__ bt) {
    int pos = blockIdx.x;
    int b = pos / HWSZ, hw = pos % HWSZ;

    __shared__ float x[CC];
    int tid = threadIdx.x;
    float s = 0.f, ss2 = 0.f;
    for (int c = tid; c < CC; c += 256) {
        float v = g_ffo[(size_t)pos * CC + c];
        x[c] = v; s += v; ss2 += v * v;
    }
    float mu, rstd;
    block_meanvar(s, ss2, CC, &mu, &rstd);
    for (int c = tid; c < CC; c += 256) {
        float v = (x[c] - mu) * rstd * g[c] + bt[c];
        out[(size_t)(b * CC + c) * HWSZ + hw] = g_skip2[(size_t)pos * CC + c] + v;
    }
}

// ---------------- launch ----------------
extern "C" void kernel_launch(void* const* d_in, const int* in_sizes, int n_in,
                              void* d_out, int out_size) {
    const float* visual   = (const float*)d_in[0];
    const float* vector   = (const float*)d_in[1];
    const float* tm_w     = (const float*)d_in[2];
    const float* tm_b     = (const float*)d_in[3];
    const float* ln1_g    = (const float*)d_in[4];
    const float* ln1_b    = (const float*)d_in[5];
    const float* ln2_g    = (const float*)d_in[6];
    const float* ln2_b    = (const float*)d_in[7];
    const float* ln3_g    = (const float*)d_in[8];
    const float* ln3_b    = (const float*)d_in[9];
    const float* qkv_w    = (const float*)d_in[10];
    const float* qkv_b    = (const float*)d_in[11];
    const float* wproj_w  = (const float*)d_in[12];
    const float* wproj_b  = (const float*)d_in[13];
    const float* meta_w1  = (const float*)d_in[14];
    const float* meta_b1  = (const float*)d_in[15];
    const float* meta_w2  = (const float*)d_in[16];
    const float* meta_b2  = (const float*)d_in[17];
    const float* tau      = (const float*)d_in[18];
    const float* ca_in_w  = (const float*)d_in[19];
    const float* ca_in_b  = (const float*)d_in[20];
    const float* ca_out_w = (const float*)d_in[21];
    const float* ca_out_b = (const float*)d_in[22];
    const float* ff_w1    = (const float*)d_in[23];
    const float* ff_b1    = (const float*)d_in[24];
    const float* ff_w2    = (const float*)d_in[25];
    const float* ff_b2    = (const float*)d_in[26];
    float* out = (float*)d_out;

    __half *vin, *vec, *tok, *o1, *pq, *co1, *sk2r, *ffh;
    float  *qkv, *w2, *q2, *kv2, *co2, *ffo;
    __half *tmwt, *qkvwt, *wprwt, *caint, *caoutt, *ff1t, *ff2t;
    cudaGetSymbolAddress((void**)&vin,   g_vin);
    cudaGetSymbolAddress((void**)&vec,   g_vec);
    cudaGetSymbolAddress((void**)&tok,   g_tok);
    cudaGetSymbolAddress((void**)&qkv,   g_qkv);
    cudaGetSymbolAddress((void**)&o1,    g_o1);
    cudaGetSymbolAddress((void**)&w2,    g_w2);
    cudaGetSymbolAddress((void**)&pq,    g_pq);
    cudaGetSymbolAddress((void**)&q2,    g_q2);
    cudaGetSymbolAddress((void**)&kv2,   g_kv2);
    cudaGetSymbolAddress((void**)&co1,   g_co1);
    cudaGetSymbolAddress((void**)&co2,   g_co2);
    cudaGetSymbolAddress((void**)&sk2r,  g_skip2r);
    cudaGetSymbolAddress((void**)&ffh,   g_ffh);
    cudaGetSymbolAddress((void**)&ffo,   g_ffo);
    cudaGetSymbolAddress((void**)&tmwt,  g_tmw_t);
    cudaGetSymbolAddress((void**)&qkvwt, g_qkvw_t);
    cudaGetSymbolAddress((void**)&wprwt, g_wprw_t);
    cudaGetSymbolAddress((void**)&caint, g_cain_t);
    cudaGetSymbolAddress((void**)&caoutt,g_caout_t);
    cudaGetSymbolAddress((void**)&ff1t,  g_ff1_t);
    cudaGetSymbolAddress((void**)&ff2t,  g_ff2_t);

    cudaFuncSetAttribute((const void*)tgemm<EPI_NONE,  float>,  cudaFuncAttributeMaxDynamicSharedMemorySize, TGEMM_SMEM);
    cudaFuncSetAttribute((const void*)tgemm<EPI_GELU,  __half>, cudaFuncAttributeMaxDynamicSharedMemorySize, TGEMM_SMEM);
    cudaFuncSetAttribute((const void*)tgemm<EPI_SCALE, float>,  cudaFuncAttributeMaxDynamicSharedMemorySize, TGEMM_SMEM);

    // weight transposes (+fp16 rounding)
    transpose_w<<<dim3(16,  8), 256>>>(tm_w,     tmwt,  256,  512);
    transpose_w<<<dim3(48, 16), 256>>>(qkv_w,    qkvwt, 512, 1536);
    transpose_w<<<dim3(16, 16), 256>>>(wproj_w,  wprwt, 512,  512);
    transpose_w<<<dim3(48, 16), 256>>>(ca_in_w,  caint, 512, 1536);
    transpose_w<<<dim3(16, 16), 256>>>(ca_out_w, caoutt,512,  512);
    transpose_w<<<dim3(64, 16), 256>>>(ff_w1,    ff1t,  512, 2048);
    transpose_w<<<dim3(16, 64), 256>>>(ff_w2,    ff2t, 2048,  512);
    half_copy<<<512, 256>>>(vector, vin, 512 * 256);

    bias_kernel<<<T_ * T_, 256>>>(meta_w1, meta_b1, meta_w2, meta_b2);

    // vec = gelu(vector @ tm_w + tm_b)   (fp16 out)
    tgemm<EPI_GELU, __half><<<dim3(4, 4), 256, TGEMM_SMEM>>>(vin, tmwt, tm_b, vec, 512, 512, 256, 0.f);
    // K2|V2 fused (weights rows 512..1535 of caint are contiguous)
    tgemm<EPI_NONE, float><<<dim3(8, 4), 256, TGEMM_SMEM>>>(vec, caint + 512 * 512, ca_in_b + 512, kv2, 512, 1024, 512, 0.f);

    unfold_kernel<<<NTOK, 256>>>(visual);
    tgemm<EPI_NONE, float><<<dim3(12, 196), 256, TGEMM_SMEM>>>(tok, qkvwt, qkv_b, qkv, NTOK, 3 * CC, CC, 0.f);
    win_attn<<<BW_ * NH_, 256>>>(tau);
    tgemm<EPI_NONE, float><<<dim3(4, 196), 256, TGEMM_SMEM>>>(o1, wprwt, wproj_b, w2, NTOK, CC, CC, 0.f);
    merge_ln1<<<BB * HWSZ, 256>>>(visual, ln1_g, ln1_b);
    tgemm<EPI_SCALE, float><<<dim3(4, 196), 256, TGEMM_SMEM>>>(pq, caint, ca_in_b, q2, NTOK, CC, CC, 0.17677669529663687f);
    ca_attn<<<BW_ * NH_, 256>>>();
    tgemm<EPI_NONE, float><<<dim3(4, 196), 256, TGEMM_SMEM>>>(co1, caoutt, ca_out_b, co2, NTOK, CC, CC, 0.f);
    ca_ln2<<<NTOK, 256>>>(ln2_g, ln2_b);
    tgemm<EPI_GELU, __half><<<dim3(16, 196), 256, TGEMM_SMEM>>>(sk2r, ff1t, ff_b1, ffh, NTOK, 4 * CC, CC, 0.f);
    tgemm<EPI_NONE, float><<<dim3(4, 196), 256, TGEMM_SMEM>>>(ffh, ff2t, ff_b2, ffo, NTOK, CC, 2048, 0.f);
    final_kernel<<<BB * HWSZ, 256>>>(out, ln3_g, ln3_b);
}

// round 11
// speedup vs baseline: 1.5757x; 1.0090x over previous
#include <cuda_runtime.h>
#include <cuda_fp16.h>
#include <math.h>
#include <stdint.h>

// Problem constants
#define BB    8
#define CC    512
#define HH    56
#define WW_   56
#define HWSZ  3136
#define WS_   7
#define SS_   3
#define NH_   16
#define HD_   32
#define T_    49
#define NW_   64
#define BW_   512          // BB * NW_
#define NTOK  25088        // BW_ * T_
#define L_    64

// ---------------- scratch (device globals; no runtime alloc) ----------------
__device__ __align__(16) __half g_vin [512 * 256];
__device__ __align__(16) __half g_vec [BW_ * CC];
__device__ __align__(16) __half g_tok [NTOK * CC];
__device__ __align__(16) __half g_qkv [NTOK * 3 * CC];
__device__ __align__(16) __half g_o1  [NTOK * CC];
__device__ __align__(16) __half g_w2  [NTOK * CC];
__device__ float  g_skipa[NTOK * CC];       // skip1 [B,HW,C] full fp32
__device__ __align__(16) __half g_pq  [NTOK * CC];
__device__ __align__(16) __half g_q2  [NTOK * CC];
__device__ __align__(16) __half g_kv2 [BW_ * 2 * CC];   // [B*L, 1024]: k | v
__device__ __align__(16) __half g_co1 [NTOK * CC];
__device__ __align__(16) __half g_co2 [NTOK * CC];
__device__ float  g_skip2[NTOK * CC];       // full fp32
__device__ __align__(16) __half g_skip2r[NTOK * CC]; // fp16 copy for GEMM
__device__ __align__(16) __half g_ffh [NTOK * 4 * CC];
__device__ __align__(16) __half g_ffo [NTOK * CC];
__device__ float  g_bias[NH_ * T_ * T_];

// transposed (fp16) weights: [N, K] K-contiguous
__device__ __align__(16) __half g_tmw_t  [512 * 256];
__device__ __align__(16) __half g_qkvw_t [1536 * 512];
__device__ __align__(16) __half g_wprw_t [512 * 512];
__device__ __align__(16) __half g_cain_t [1536 * 512];
__device__ __align__(16) __half g_caout_t[512 * 512];
__device__ __align__(16) __half g_ff1_t  [2048 * 512];
__device__ __align__(16) __half g_ff2_t  [512 * 2048];

// ---------------- helpers ----------------
__device__ __forceinline__ float gelu_exact(float x) {
    return 0.5f * x * (1.0f + erff(x * 0.70710678118654752f));
}
__device__ __forceinline__ uint32_t s2u(const void* p) {
    uint32_t a;
    asm("{ .reg .u64 t; cvta.to.shared.u64 t, %1; cvt.u32.u64 %0, t; }"
        : "=r"(a) : "l"(p));
    return a;
}

__device__ __forceinline__ void block_meanvar(float s, float ss, int n,
                                              float* mu, float* rstd) {
    #pragma unroll
    for (int o = 16; o > 0; o >>= 1) {
        s  += __shfl_down_sync(0xffffffffu, s,  o);
        ss += __shfl_down_sync(0xffffffffu, ss, o);
    }
    __shared__ float rs[8], rss[8], res[2];
    int lane = threadIdx.x & 31, wid = threadIdx.x >> 5;
    if (lane == 0) { rs[wid] = s; rss[wid] = ss; }
    __syncthreads();
    if (threadIdx.x == 0) {
        float S = 0.f, SS2 = 0.f;
        #pragma unroll
        for (int i = 0; i < 8; i++) { S += rs[i]; SS2 += rss[i]; }
        float m = S / n;
        float var = SS2 / n - m * m;
        res[0] = m; res[1] = rsqrtf(var + 1e-5f);
    }
    __syncthreads();
    *mu = res[0]; *rstd = res[1];
}

// ---------------- fp16 mma.sync GEMM (3-stage pipeline + ldmatrix) ----------
// C[M,N] = epi(A[M,K] @ W[N,K]^T + bias); A,W fp16; accum fp32.
// M%128==0, N%128==0, K%32==0.
#define EPI_NONE  0
#define EPI_GELU  1
#define EPI_SCALE 2

#define LDPAD_H 40
#define TILEH (128 * LDPAD_H)            // halves per tile
#define TGEMM_SMEM (6 * TILEH * 2)       // 3 stages x (A+B), bytes = 61440

__device__ __forceinline__ void mma_f16(float* c, const uint32_t* a,
                                        const uint32_t* b) {
    asm volatile(
        "mma.sync.aligned.m16n8k16.row.col.f32.f16.f16.f32 "
        "{%0,%1,%2,%3}, {%4,%5,%6,%7}, {%8,%9}, {%0,%1,%2,%3};"
        : "+f"(c[0]), "+f"(c[1]), "+f"(c[2]), "+f"(c[3])
        : "r"(a[0]), "r"(a[1]), "r"(a[2]), "r"(a[3]),
          "r"(b[0]), "r"(b[1]));
}

#define LDSM_X4(r0, r1, r2, r3, addr) \
    asm volatile("ldmatrix.sync.aligned.m8n8.x4.shared.b16 {%0,%1,%2,%3}, [%4];" \
        : "=r"(r0), "=r"(r1), "=r"(r2), "=r"(r3) : "r"(addr))

__device__ __forceinline__ void store2(float* p, float a, float b) {
    *(float2*)p = make_float2(a, b);
}
__device__ __forceinline__ void store2(__half* p, float a, float b) {
    *(__half2*)p = __floats2half2_rn(a, b);
}

template <int EPI, typename OutT>
__global__ __launch_bounds__(256, 2)
void tgemm(const __half* __restrict__ A, const __half* __restrict__ W,
           const float* __restrict__ bias, OutT* __restrict__ C,
           int M, int N, int K, float alpha) {
    extern __shared__ __half smh[];
    __half* Abuf = smh;                  // [3][128][LDPAD_H]
    __half* Bbuf = smh + 3 * TILEH;      // [3][128][LDPAD_H]
    const uint32_t sm_a = s2u(Abuf), sm_b = s2u(Bbuf);

    const int tid = threadIdx.x;
    const int wid = tid >> 5, lane = tid & 31;
    const int m0 = blockIdx.y << 7, n0 = blockIdx.x << 7;
    const int wm = wid & 3, wn = wid >> 2;
    const int m_off = wm << 5;           // 32-row warp tile
    const int n_off = wn << 6;           // 64-col warp tile

    const __half* Abase = A + (size_t)m0 * K;
    const __half* Wbase = W + (size_t)n0 * K;
    const int NC = K >> 5;

    const int seg = tid & 3;             // 4 x 16B (8-half) segments per row
    const int lr0 = tid >> 2;            // 0..63

    auto load_chunk = [&](int c, int sel) {
        uint32_t ab = sm_a + sel * (TILEH * 2);
        uint32_t bb = sm_b + sel * (TILEH * 2);
        const __half* As = Abase + c * 32 + seg * 8;
        const __half* Ws = Wbase + c * 32 + seg * 8;
        #pragma unroll
        for (int i = 0; i < 2; i++) {
            int r = lr0 + (i << 6);      // 0..127
            uint32_t so = (uint32_t)(r * (LDPAD_H * 2) + seg * 16);
            asm volatile("cp.async.cg.shared.global [%0], [%1], 16;"
                         :: "r"(ab + so), "l"(As + (size_t)r * K));
            asm volatile("cp.async.cg.shared.global [%0], [%1], 16;"
                         :: "r"(bb + so), "l"(Ws + (size_t)r * K));
        }
        asm volatile("cp.async.commit_group;" ::: "memory");
    };

    // ldmatrix per-lane address offsets (bytes within a tile)
    const int lm = lane >> 3, lr = lane & 7;
    uint32_t a_off[2], b_off[4];
    #pragma unroll
    for (int mt = 0; mt < 2; mt++) {
        int row = m_off + mt * 16 + lr + (lm & 1) * 8;
        int koff = (lm >> 1) * 8;
        a_off[mt] = (uint32_t)((row * LDPAD_H + koff) * 2);
    }
    #pragma unroll
    for (int g = 0; g < 4; g++) {
        int row = n_off + (2 * g + (lm >> 1)) * 8 + lr;
        int koff = (lm & 1) * 8;
        b_off[g] = (uint32_t)((row * LDPAD_H + koff) * 2);
    }

    float acc[2][8][4];
    #pragma unroll
    for (int i = 0; i < 2; i++)
        #pragma unroll
        for (int j = 0; j < 8; j++)
            #pragma unroll
            for (int q = 0; q < 4; q++) acc[i][j][q] = 0.f;

    // prefetch 2 chunks (3-stage ring, distance 2)
    load_chunk(0, 0);
    if (NC > 1) load_chunk(1, 1);

    const int qr = lane >> 2, qc = lane & 3;
    int sel = 0;

    for (int c = 0; c < NC; c++) {
        if (c + 1 < NC)
            asm volatile("cp.async.wait_group 1;" ::: "memory");
        else
            asm volatile("cp.async.wait_group 0;" ::: "memory");
        __syncthreads();
        if (c + 2 < NC) {
            int s2 = sel + 2; if (s2 >= 3) s2 -= 3;
            load_chunk(c + 2, s2);
        }

        const uint32_t abase = sm_a + sel * (TILEH * 2);
        const uint32_t bbase = sm_b + sel * (TILEH * 2);

        #pragma unroll
        for (int ks = 0; ks < 2; ks++) {
            const uint32_t kb = ks * 32;      // 16 halves = 32 bytes
            uint32_t a[2][4], b[8][2];
            #pragma unroll
            for (int mt = 0; mt < 2; mt++)
                LDSM_X4(a[mt][0], a[mt][1], a[mt][2], a[mt][3],
                        abase + a_off[mt] + kb);
            #pragma unroll
            for (int g = 0; g < 4; g++)
                LDSM_X4(b[2 * g][0], b[2 * g][1], b[2 * g + 1][0], b[2 * g + 1][1],
                        bbase + b_off[g] + kb);
            #pragma unroll
            for (int mt = 0; mt < 2; mt++)
                #pragma unroll
                for (int nt = 0; nt < 8; nt++)
                    mma_f16(acc[mt][nt], a[mt], b[nt]);
        }
        if (++sel >= 3) sel = 0;
    }

    // epilogue
    #pragma unroll
    for (int mt = 0; mt < 2; mt++) {
        #pragma unroll
        for (int half = 0; half < 2; half++) {
            int row = m0 + m_off + mt * 16 + qr + half * 8;
            OutT* Cp = C + (size_t)row * N + n0 + n_off;
            #pragma unroll
            for (int nt = 0; nt < 8; nt++) {
                int col = nt * 8 + qc * 2;
                float v0 = acc[mt][nt][half * 2 + 0] + bias[n0 + n_off + col];
                float v1 = acc[mt][nt][half * 2 + 1] + bias[n0 + n_off + col + 1];
                if (EPI == EPI_GELU)  { v0 = gelu_exact(v0); v1 = gelu_exact(v1); }
                if (EPI == EPI_SCALE) { v0 *= alpha; v1 *= alpha; }
                store2(Cp + col, v0, v1);
            }
        }
    }
}

// ---------------- weight transpose + fp16:  Wt[n,k] = h(W[k,n]) ----
__global__ __launch_bounds__(256)
void transpose_w(const float* __restrict__ W, __half* __restrict__ Wt,
                 int K, int N) {
    __shared__ float tile[32][33];
    int kb = blockIdx.y * 32, nb = blockIdx.x * 32;
    int tx = threadIdx.x & 31, ty = threadIdx.x >> 5;
    #pragma unroll
    for (int i = 0; i < 32; i += 8)
        tile[ty + i][tx] = W[(size_t)(kb + ty + i) * N + nb + tx];
    __syncthreads();
    #pragma unroll
    for (int i = 0; i < 32; i += 8)
        Wt[(size_t)(nb + ty + i) * K + kb + tx] = __float2half_rn(tile[tx][ty + i]);
}

__global__ void half_copy(const float* __restrict__ in, __half* __restrict__ o, int n) {
    int i = blockIdx.x * 256 + threadIdx.x;
    if (i < n) o[i] = __float2half_rn(in[i]);
}

// ---------------- relative-position bias precompute ----------------
__global__ void bias_kernel(const float* __restrict__ w1, const float* __restrict__ b1,
                            const float* __restrict__ w2, const float* __restrict__ b2) {
    int pair = blockIdx.x;
    int q = pair / T_, k = pair % T_;
    float d0 = (float)(q / WS_ - k / WS_);
    float d1 = (float)(q % WS_ - k % WS_);
    float r0 = (d0 > 0.f ? 1.f : (d0 < 0.f ? -1.f : 0.f)) * log1pf(fabsf(d0));
    float r1 = (d1 > 0.f ? 1.f : (d1 < 0.f ? -1.f : 0.f)) * log1pf(fabsf(d1));
    int tid = threadIdx.x;
    __shared__ float hbuf[256];
    float hv = r0 * w1[tid] + r1 * w1[256 + tid] + b1[tid];
    hbuf[tid] = fmaxf(hv, 0.f);
    __syncthreads();
    if (tid < NH_) {
        float s = b2[tid];
        #pragma unroll 8
        for (int j = 0; j < 256; j++) s += hbuf[j] * w2[j * NH_ + tid];
        g_bias[tid * (T_ * T_) + pair] = s;
    }
}

// ---------------- roll(-3,-3) + unfold into token rows (fp16) ---------------
__global__ __launch_bounds__(256)
void unfold_kernel(const float* __restrict__ visual) {
    int r = blockIdx.x;
    int bw = r / T_, t = r % T_;
    int b = bw / NW_, win = bw % NW_, wh = win >> 3, ww = win & 7;
    int h = (wh * WS_ + t / WS_ + SS_) % HH;
    int w = (ww * WS_ + t % WS_ + SS_) % WW_;
    int hw = h * WW_ + w;
    for (int c = threadIdx.x; c < CC; c += 256)
        g_tok[(size_t)r * CC + c] = __float2half_rn(visual[(size_t)(b * CC + c) * HWSZ + hw]);
}

// ---------------- window attention ----------------
__global__ __launch_bounds__(256)
void win_attn(const float* __restrict__ tau) {
    int bw = blockIdx.x >> 4;
    int hh = blockIdx.x & 15;
    int tid = threadIdx.x;

    __shared__ float sq[T_ * HD_], sk[T_ * HD_], sv[T_ * HD_];
    __shared__ float ss[T_ * 50];
    __shared__ float nq[T_], nk[T_];
    __shared__ int   rg[T_];

    size_t base = (size_t)(bw * T_) * (3 * CC);
    for (int idx = tid; idx < T_ * HD_; idx += 256) {
        int t = idx / HD_, d = idx % HD_;
        size_t ro = base + (size_t)t * (3 * CC) + hh * HD_ + d;
        sq[idx] = __half2float(g_qkv[ro]);
        sk[idx] = __half2float(g_qkv[ro + CC]);
        sv[idx] = __half2float(g_qkv[ro + 2 * CC]);
    }
    int win = bw & 63, wh = win >> 3, ww = win & 7;
    if (tid < T_) {
        int row = wh * WS_ + tid / WS_;
        int col = ww * WS_ + tid % WS_;
        int rh = row < 49 ? 0 : (row < 53 ? 1 : 2);
        int rw = col < 49 ? 0 : (col < 53 ? 1 : 2);
        rg[tid] = rh * 3 + rw;
    }
    __syncthreads();

    if (tid < T_) {
        float s1 = 0.f, s2 = 0.f;
        #pragma unroll
        for (int d = 0; d < HD_; d++) {
            float a = sq[tid * HD_ + d], b = sk[tid * HD_ + d];
            s1 += a * a; s2 += b * b;
        }
        nq[tid] = sqrtf(s1); nk[tid] = sqrtf(s2);
    }
    __syncthreads();

    float tauh = fmaxf(tau[hh], 0.01f);
    const float* bh = &g_bias[hh * (T_ * T_)];
    for (int idx = tid; idx < T_ * T_; idx += 256) {
        int q = idx / T_, k = idx % T_;
        float dot = 0.f;
        #pragma unroll
        for (int d = 0; d < HD_; d++) dot += sq[q * HD_ + d] * sk[k * HD_ + d];
        float s = dot / fmaxf(nq[q] * nk[k], 1e-6f) / tauh + bh[idx];
        if (rg[q] != rg[k]) s -= 100.0f;
        ss[q * 50 + k] = s;
    }
    __syncthreads();

    if (tid < T_) {
        float m = -1e30f;
        for (int k = 0; k < T_; k++) m = fmaxf(m, ss[tid * 50 + k]);
        float sum = 0.f;
        for (int k = 0; k < T_; k++) {
            float e = expf(ss[tid * 50 + k] - m);
            ss[tid * 50 + k] = e; sum += e;
        }
        float inv = 1.f / sum;
        for (int k = 0; k < T_; k++) ss[tid * 50 + k] *= inv;
    }
    __syncthreads();

    for (int idx = tid; idx < T_ * HD_; idx += 256) {
        int t = idx / HD_, d = idx % HD_;
        float acc = 0.f;
        #pragma unroll
        for (int k = 0; k < T_; k++) acc += ss[t * 50 + k] * sv[k * HD_ + d];
        g_o1[(size_t)(bw * T_ + t) * CC + hh * HD_ + d] = __float2half_rn(acc);
    }
}

// ---------------- fold+roll(+3) + LN1 + residual; emit CA query tokens ------
__global__ __launch_bounds__(256)
void merge_ln1(const float* __restrict__ visual,
               const float* __restrict__ g, const float* __restrict__ bt) {
    int pos = blockIdx.x;
    int b = pos / HWSZ, hw = pos % HWSZ;
    int h = hw / WW_, w = hw % WW_;
    int hp = (h + HH - SS_) % HH, wp = (w + WW_ - SS_) % WW_;
    int rm = (b * NW_ + (hp / WS_) * 8 + (wp / WS_)) * T_ + (hp % WS_) * WS_ + (wp % WS_);

    __shared__ float x[CC];
    int tid = threadIdx.x;
    float s = 0.f, ss2 = 0.f;
    for (int c = tid; c < CC; c += 256) {
        float v = __half2float(g_w2[(size_t)rm * CC + c]);
        x[c] = v; s += v; ss2 += v * v;
    }
    float mu, rstd;
    block_meanvar(s, ss2, CC, &mu, &rstd);
    for (int c = tid; c < CC; c += 256) {
        float v = (x[c] - mu) * rstd * g[c] + bt[c]
                + visual[(size_t)(b * CC + c) * HWSZ + hw];
        g_skipa[(size_t)pos * CC + c] = v;
        g_pq  [(size_t)rm  * CC + c] = __float2half_rn(v);
    }
}

// ---------------- cross attention ----------------
__global__ __launch_bounds__(256)
void ca_attn() {
    int bw = blockIdx.x >> 4;
    int hh = blockIdx.x & 15;
    int bkv = bw & 7;
    int tid = threadIdx.x;

    __shared__ float sq[T_ * HD_], sk[L_ * HD_], sv[L_ * HD_];
    __shared__ float ss[T_ * 65];

    for (int idx = tid; idx < T_ * HD_; idx += 256) {
        int t = idx / HD_, d = idx % HD_;
        sq[idx] = __half2float(g_q2[(size_t)(bw * T_ + t) * CC + hh * HD_ + d]);
    }
    for (int idx = tid; idx < L_ * HD_; idx += 256) {
        int l = idx / HD_, d = idx % HD_;
        size_t ro = (size_t)(bkv * L_ + l) * (2 * CC) + hh * HD_ + d;
        sk[idx] = __half2float(g_kv2[ro]);
        sv[idx] = __half2float(g_kv2[ro + CC]);
    }
    __syncthreads();

    for (int idx = tid; idx < T_ * L_; idx += 256) {
        int q = idx / L_, l = idx % L_;
        float dot = 0.f;
        #pragma unroll
        for (int d = 0; d < HD_; d++) dot += sq[q * HD_ + d] * sk[l * HD_ + d];
        ss[q * 65 + l] = dot;
    }
    __syncthreads();

    if (tid < T_) {
        float m = -1e30f;
        for (int l = 0; l < L_; l++) m = fmaxf(m, ss[tid * 65 + l]);
        float sum = 0.f;
        for (int l = 0; l < L_; l++) {
            float e = expf(ss[tid * 65 + l] - m);
            ss[tid * 65 + l] = e; sum += e;
        }
        float inv = 1.f / sum;
        for (int l = 0; l < L_; l++) ss[tid * 65 + l] *= inv;
    }
    __syncthreads();

    for (int idx = tid; idx < T_ * HD_; idx += 256) {
        int t = idx / HD_, d = idx % HD_;
        float acc = 0.f;
        #pragma unroll
        for (int l = 0; l < L_; l++) acc += ss[t * 65 + l] * sv[l * HD_ + d];
        g_co1[(size_t)(bw * T_ + t) * CC + hh * HD_ + d] = __float2half_rn(acc);
    }
}

// ---------------- LN2 + fold+roll(+3) + residual ----------------
__global__ __launch_bounds__(256)
void ca_ln2(const float* __restrict__ g, const float* __restrict__ bt) {
    int r = blockIdx.x;
    int bw = r / T_, t = r % T_;
    int b = bw / NW_, win = bw % NW_, wh = win >> 3, ww = win & 7;
    int h = (wh * WS_ + t / WS_ + SS_) % HH;
    int w = (ww * WS_ + t % WS_ + SS_) % WW_;
    int pos = b * HWSZ + h * WW_ + w;

    __shared__ float x[CC];
    int tid = threadIdx.x;
    float s = 0.f, ss2 = 0.f;
    for (int c = tid; c < CC; c += 256) {
        float v = __half2float(g_co2[(size_t)r * CC + c]);
        x[c] = v; s += v; ss2 += v * v;
    }
    float mu, rstd;
    block_meanvar(s, ss2, CC, &mu, &rstd);
    for (int c = tid; c < CC; c += 256) {
        float v = (x[c] - mu) * rstd * g[c] + bt[c]
                + g_skipa[(size_t)pos * CC + c];
        g_skip2 [(size_t)pos * CC + c] = v;
        g_skip2r[(size_t)pos * CC + c] = __float2half_rn(v);
    }
}

// ---------------- LN3(ff) + skip2, write [B,C,H,W] ----------------
__global__ __launch_bounds__(256)
void final_kernel(float* __restrict__ out,
                  const float* __restrict__ g, const float* __restrict__ bt) {
    int pos = blockIdx.x;
    int b = pos / HWSZ, hw = pos % HWSZ;

    __shared__ float x[CC];
    int tid = threadIdx.x;
    float s = 0.f, ss2 = 0.f;
    for (int c = tid; c < CC; c += 256) {
        float v = __half2float(g_ffo[(size_t)pos * CC + c]);
        x[c] = v; s += v; ss2 += v * v;
    }
    float mu, rstd;
    block_meanvar(s, ss2, CC, &mu, &rstd);
    for (int c = tid; c < CC; c += 256) {
        float v = (x[c] - mu) * rstd * g[c] + bt[c];
        out[(size_t)(b * CC + c) * HWSZ + hw] = g_skip2[(size_t)pos * CC + c] + v;
    }
}

// ---------------- launch ----------------
extern "C" void kernel_launch(void* const* d_in, const int* in_sizes, int n_in,
                              void* d_out, int out_size) {
    const float* visual   = (const float*)d_in[0];
    const float* vector   = (const float*)d_in[1];
    const float* tm_w     = (const float*)d_in[2];
    const float* tm_b     = (const float*)d_in[3];
    const float* ln1_g    = (const float*)d_in[4];
    const float* ln1_b    = (const float*)d_in[5];
    const float* ln2_g    = (const float*)d_in[6];
    const float* ln2_b    = (const float*)d_in[7];
    const float* ln3_g    = (const float*)d_in[8];
    const float* ln3_b    = (const float*)d_in[9];
    const float* qkv_w    = (const float*)d_in[10];
    const float* qkv_b    = (const float*)d_in[11];
    const float* wproj_w  = (const float*)d_in[12];
    const float* wproj_b  = (const float*)d_in[13];
    const float* meta_w1  = (const float*)d_in[14];
    const float* meta_b1  = (const float*)d_in[15];
    const float* meta_w2  = (const float*)d_in[16];
    const float* meta_b2  = (const float*)d_in[17];
    const float* tau      = (const float*)d_in[18];
    const float* ca_in_w  = (const float*)d_in[19];
    const float* ca_in_b  = (const float*)d_in[20];
    const float* ca_out_w = (const float*)d_in[21];
    const float* ca_out_b = (const float*)d_in[22];
    const float* ff_w1    = (const float*)d_in[23];
    const float* ff_b1    = (const float*)d_in[24];
    const float* ff_w2    = (const float*)d_in[25];
    const float* ff_b2    = (const float*)d_in[26];
    float* out = (float*)d_out;

    __half *vin, *vec, *tok, *o1, *pq, *co1, *sk2r, *ffh;
    __half *qkv, *w2, *q2, *kv2, *co2, *ffo;
    __half *tmwt, *qkvwt, *wprwt, *caint, *caoutt, *ff1t, *ff2t;
    cudaGetSymbolAddress((void**)&vin,   g_vin);
    cudaGetSymbolAddress((void**)&vec,   g_vec);
    cudaGetSymbolAddress((void**)&tok,   g_tok);
    cudaGetSymbolAddress((void**)&qkv,   g_qkv);
    cudaGetSymbolAddress((void**)&o1,    g_o1);
    cudaGetSymbolAddress((void**)&w2,    g_w2);
    cudaGetSymbolAddress((void**)&pq,    g_pq);
    cudaGetSymbolAddress((void**)&q2,    g_q2);
    cudaGetSymbolAddress((void**)&kv2,   g_kv2);
    cudaGetSymbolAddress((void**)&co1,   g_co1);
    cudaGetSymbolAddress((void**)&co2,   g_co2);
    cudaGetSymbolAddress((void**)&sk2r,  g_skip2r);
    cudaGetSymbolAddress((void**)&ffh,   g_ffh);
    cudaGetSymbolAddress((void**)&ffo,   g_ffo);
    cudaGetSymbolAddress((void**)&tmwt,  g_tmw_t);
    cudaGetSymbolAddress((void**)&qkvwt, g_qkvw_t);
    cudaGetSymbolAddress((void**)&wprwt, g_wprw_t);
    cudaGetSymbolAddress((void**)&caint, g_cain_t);
    cudaGetSymbolAddress((void**)&caoutt,g_caout_t);
    cudaGetSymbolAddress((void**)&ff1t,  g_ff1_t);
    cudaGetSymbolAddress((void**)&ff2t,  g_ff2_t);

    cudaFuncSetAttribute((const void*)tgemm<EPI_NONE,  __half>, cudaFuncAttributeMaxDynamicSharedMemorySize, TGEMM_SMEM);
    cudaFuncSetAttribute((const void*)tgemm<EPI_GELU,  __half>, cudaFuncAttributeMaxDynamicSharedMemorySize, TGEMM_SMEM);
    cudaFuncSetAttribute((const void*)tgemm<EPI_SCALE, __half>, cudaFuncAttributeMaxDynamicSharedMemorySize, TGEMM_SMEM);

    // weight transposes (+fp16 rounding)
    transpose_w<<<dim3(16,  8), 256>>>(tm_w,     tmwt,  256,  512);
    transpose_w<<<dim3(48, 16), 256>>>(qkv_w,    qkvwt, 512, 1536);
    transpose_w<<<dim3(16, 16), 256>>>(wproj_w,  wprwt, 512,  512);
    transpose_w<<<dim3(48, 16), 256>>>(ca_in_w,  caint, 512, 1536);
    transpose_w<<<dim3(16, 16), 256>>>(ca_out_w, caoutt,512,  512);
    transpose_w<<<dim3(64, 16), 256>>>(ff_w1,    ff1t,  512, 2048);
    transpose_w<<<dim3(16, 64), 256>>>(ff_w2,    ff2t, 2048,  512);
    half_copy<<<512, 256>>>(vector, vin, 512 * 256);

    bias_kernel<<<T_ * T_, 256>>>(meta_w1, meta_b1, meta_w2, meta_b2);

    // vec = gelu(vector @ tm_w + tm_b)   (fp16 out)
    tgemm<EPI_GELU, __half><<<dim3(4, 4), 256, TGEMM_SMEM>>>(vin, tmwt, tm_b, vec, 512, 512, 256, 0.f);
    // K2|V2 fused (weights rows 512..1535 of caint are contiguous)
    tgemm<EPI_NONE, __half><<<dim3(8, 4), 256, TGEMM_SMEM>>>(vec, caint + 512 * 512, ca_in_b + 512, kv2, 512, 1024, 512, 0.f);

    unfold_kernel<<<NTOK, 256>>>(visual);
    tgemm<EPI_NONE, __half><<<dim3(12, 196), 256, TGEMM_SMEM>>>(tok, qkvwt, qkv_b, qkv, NTOK, 3 * CC, CC, 0.f);
    win_attn<<<BW_ * NH_, 256>>>(tau);
    tgemm<EPI_NONE, __half><<<dim3(4, 196), 256, TGEMM_SMEM>>>(o1, wprwt, wproj_b, w2, NTOK, CC, CC, 0.f);
    merge_ln1<<<BB * HWSZ, 256>>>(visual, ln1_g, ln1_b);
    tgemm<EPI_SCALE, __half><<<dim3(4, 196), 256, TGEMM_SMEM>>>(pq, caint, ca_in_b, q2, NTOK, CC, CC, 0.17677669529663687f);
    ca_attn<<<BW_ * NH_, 256>>>();
    tgemm<EPI_NONE, __half><<<dim3(4, 196), 256, TGEMM_SMEM>>>(co1, caoutt, ca_out_b, co2, NTOK, CC, CC, 0.f);
    ca_ln2<<<NTOK, 256>>>(ln2_g, ln2_b);
    tgemm<EPI_GELU, __half><<<dim3(16, 196), 256, TGEMM_SMEM>>>(sk2r, ff1t, ff_b1, ffh, NTOK, 4 * CC, CC, 0.f);
    tgemm<EPI_NONE, __half><<<dim3(4, 196), 256, TGEMM_SMEM>>>(ffh, ff2t, ff_b2, ffo, NTOK, CC, 2048, 0.f);
    final_kernel<<<BB * HWSZ, 256>>>(out, ln3_g, ln3_b);
}

// round 12
// speedup vs baseline: 2.1095x; 1.3387x over previous
#include <cuda_runtime.h>
#include <cuda_fp16.h>
#include <math.h>
#include <stdint.h>

// Problem constants
#define BB    8
#define CC    512
#define HH    56
#define WW_   56
#define HWSZ  3136
#define WS_   7
#define SS_   3
#define NH_   16
#define HD_   32
#define T_    49
#define NW_   64
#define BW_   512          // BB * NW_
#define NTOK  25088        // BW_ * T_
#define L_    64

// ---------------- scratch (device globals; no runtime alloc) ----------------
__device__ __align__(16) __half g_vin [512 * 256];
__device__ __align__(16) __half g_vec [BW_ * CC];
__device__ __align__(16) __half g_tok [NTOK * CC];
__device__ __align__(16) __half g_qkv [NTOK * 3 * CC];
__device__ __align__(16) __half g_o1  [NTOK * CC];
__device__ __align__(16) __half g_w2  [NTOK * CC];
__device__ float  g_skipa[NTOK * CC];       // skip1 [B,HW,C] full fp32
__device__ __align__(16) __half g_pq  [NTOK * CC];
__device__ __align__(16) __half g_q2  [NTOK * CC];
__device__ __align__(16) __half g_kv2 [BW_ * 2 * CC];   // [B*L, 1024]: k | v
__device__ __align__(16) __half g_co1 [NTOK * CC];
__device__ __align__(16) __half g_co2 [NTOK * CC];
__device__ float  g_skip2[NTOK * CC];       // full fp32
__device__ __align__(16) __half g_skip2r[NTOK * CC]; // fp16 copy for GEMM
__device__ __align__(16) __half g_ffh [NTOK * 4 * CC];
__device__ __align__(16) __half g_ffo [NTOK * CC];
__device__ float  g_bias[NH_ * T_ * T_];

// transposed (fp16) weights: [N, K] K-contiguous
__device__ __align__(16) __half g_tmw_t  [512 * 256];
__device__ __align__(16) __half g_qkvw_t [1536 * 512];
__device__ __align__(16) __half g_wprw_t [512 * 512];
__device__ __align__(16) __half g_cain_t [1536 * 512];
__device__ __align__(16) __half g_caout_t[512 * 512];
__device__ __align__(16) __half g_ff1_t  [2048 * 512];
__device__ __align__(16) __half g_ff2_t  [512 * 2048];

// ---------------- helpers ----------------
__device__ __forceinline__ float gelu_exact(float x) {
    return 0.5f * x * (1.0f + erff(x * 0.70710678118654752f));
}
__device__ __forceinline__ uint32_t s2u(const void* p) {
    uint32_t a;
    asm("{ .reg .u64 t; cvta.to.shared.u64 t, %1; cvt.u32.u64 %0, t; }"
        : "=r"(a) : "l"(p));
    return a;
}

__device__ __forceinline__ void block_meanvar(float s, float ss, int n,
                                              float* mu, float* rstd) {
    #pragma unroll
    for (int o = 16; o > 0; o >>= 1) {
        s  += __shfl_down_sync(0xffffffffu, s,  o);
        ss += __shfl_down_sync(0xffffffffu, ss, o);
    }
    __shared__ float rs[8], rss[8], res[2];
    int lane = threadIdx.x & 31, wid = threadIdx.x >> 5;
    if (lane == 0) { rs[wid] = s; rss[wid] = ss; }
    __syncthreads();
    if (threadIdx.x == 0) {
        float S = 0.f, SS2 = 0.f;
        #pragma unroll
        for (int i = 0; i < 8; i++) { S += rs[i]; SS2 += rss[i]; }
        float m = S / n;
        float var = SS2 / n - m * m;
        res[0] = m; res[1] = rsqrtf(var + 1e-5f);
    }
    __syncthreads();
    *mu = res[0]; *rstd = res[1];
}

// ---------------- fp16 mma.sync GEMM (3-stage pipeline + ldmatrix) ----------
#define EPI_NONE  0
#define EPI_GELU  1
#define EPI_SCALE 2

#define LDPAD_H 40
#define TILEH (128 * LDPAD_H)            // halves per tile
#define TGEMM_SMEM (6 * TILEH * 2)       // 3 stages x (A+B), bytes = 61440

__device__ __forceinline__ void mma_f16(float* c, const uint32_t* a,
                                        const uint32_t* b) {
    asm volatile(
        "mma.sync.aligned.m16n8k16.row.col.f32.f16.f16.f32 "
        "{%0,%1,%2,%3}, {%4,%5,%6,%7}, {%8,%9}, {%0,%1,%2,%3};"
        : "+f"(c[0]), "+f"(c[1]), "+f"(c[2]), "+f"(c[3])
        : "r"(a[0]), "r"(a[1]), "r"(a[2]), "r"(a[3]),
          "r"(b[0]), "r"(b[1]));
}

#define LDSM_X4(r0, r1, r2, r3, addr) \
    asm volatile("ldmatrix.sync.aligned.m8n8.x4.shared.b16 {%0,%1,%2,%3}, [%4];" \
        : "=r"(r0), "=r"(r1), "=r"(r2), "=r"(r3) : "r"(addr))

__device__ __forceinline__ void store2(float* p, float a, float b) {
    *(float2*)p = make_float2(a, b);
}
__device__ __forceinline__ void store2(__half* p, float a, float b) {
    *(__half2*)p = __floats2half2_rn(a, b);
}

template <int EPI, typename OutT>
__global__ __launch_bounds__(256, 2)
void tgemm(const __half* __restrict__ A, const __half* __restrict__ W,
           const float* __restrict__ bias, OutT* __restrict__ C,
           int M, int N, int K, float alpha) {
    extern __shared__ __half smh[];
    __half* Abuf = smh;                  // [3][128][LDPAD_H]
    __half* Bbuf = smh + 3 * TILEH;      // [3][128][LDPAD_H]
    const uint32_t sm_a = s2u(Abuf), sm_b = s2u(Bbuf);

    const int tid = threadIdx.x;
    const int wid = tid >> 5, lane = tid & 31;
    const int m0 = blockIdx.y << 7, n0 = blockIdx.x << 7;
    const int wm = wid & 3, wn = wid >> 2;
    const int m_off = wm << 5;
    const int n_off = wn << 6;

    const __half* Abase = A + (size_t)m0 * K;
    const __half* Wbase = W + (size_t)n0 * K;
    const int NC = K >> 5;

    const int seg = tid & 3;
    const int lr0 = tid >> 2;

    auto load_chunk = [&](int c, int sel) {
        uint32_t ab = sm_a + sel * (TILEH * 2);
        uint32_t bb = sm_b + sel * (TILEH * 2);
        const __half* As = Abase + c * 32 + seg * 8;
        const __half* Ws = Wbase + c * 32 + seg * 8;
        #pragma unroll
        for (int i = 0; i < 2; i++) {
            int r = lr0 + (i << 6);
            uint32_t so = (uint32_t)(r * (LDPAD_H * 2) + seg * 16);
            asm volatile("cp.async.cg.shared.global [%0], [%1], 16;"
                         :: "r"(ab + so), "l"(As + (size_t)r * K));
            asm volatile("cp.async.cg.shared.global [%0], [%1], 16;"
                         :: "r"(bb + so), "l"(Ws + (size_t)r * K));
        }
        asm volatile("cp.async.commit_group;" ::: "memory");
    };

    const int lm = lane >> 3, lr = lane & 7;
    uint32_t a_off[2], b_off[4];
    #pragma unroll
    for (int mt = 0; mt < 2; mt++) {
        int row = m_off + mt * 16 + lr + (lm & 1) * 8;
        int koff = (lm >> 1) * 8;
        a_off[mt] = (uint32_t)((row * LDPAD_H + koff) * 2);
    }
    #pragma unroll
    for (int g = 0; g < 4; g++) {
        int row = n_off + (2 * g + (lm >> 1)) * 8 + lr;
        int koff = (lm & 1) * 8;
        b_off[g] = (uint32_t)((row * LDPAD_H + koff) * 2);
    }

    float acc[2][8][4];
    #pragma unroll
    for (int i = 0; i < 2; i++)
        #pragma unroll
        for (int j = 0; j < 8; j++)
            #pragma unroll
            for (int q = 0; q < 4; q++) acc[i][j][q] = 0.f;

    load_chunk(0, 0);
    if (NC > 1) load_chunk(1, 1);

    const int qr = lane >> 2, qc = lane & 3;
    int sel = 0;

    for (int c = 0; c < NC; c++) {
        if (c + 1 < NC)
            asm volatile("cp.async.wait_group 1;" ::: "memory");
        else
            asm volatile("cp.async.wait_group 0;" ::: "memory");
        __syncthreads();
        if (c + 2 < NC) {
            int s2 = sel + 2; if (s2 >= 3) s2 -= 3;
            load_chunk(c + 2, s2);
        }

        const uint32_t abase = sm_a + sel * (TILEH * 2);
        const uint32_t bbase = sm_b + sel * (TILEH * 2);

        #pragma unroll
        for (int ks = 0; ks < 2; ks++) {
            const uint32_t kb = ks * 32;
            uint32_t a[2][4], b[8][2];
            #pragma unroll
            for (int mt = 0; mt < 2; mt++)
                LDSM_X4(a[mt][0], a[mt][1], a[mt][2], a[mt][3],
                        abase + a_off[mt] + kb);
            #pragma unroll
            for (int g = 0; g < 4; g++)
                LDSM_X4(b[2 * g][0], b[2 * g][1], b[2 * g + 1][0], b[2 * g + 1][1],
                        bbase + b_off[g] + kb);
            #pragma unroll
            for (int mt = 0; mt < 2; mt++)
                #pragma unroll
                for (int nt = 0; nt < 8; nt++)
                    mma_f16(acc[mt][nt], a[mt], b[nt]);
        }
        if (++sel >= 3) sel = 0;
    }

    #pragma unroll
    for (int mt = 0; mt < 2; mt++) {
        #pragma unroll
        for (int half = 0; half < 2; half++) {
            int row = m0 + m_off + mt * 16 + qr + half * 8;
            OutT* Cp = C + (size_t)row * N + n0 + n_off;
            #pragma unroll
            for (int nt = 0; nt < 8; nt++) {
                int col = nt * 8 + qc * 2;
                float v0 = acc[mt][nt][half * 2 + 0] + bias[n0 + n_off + col];
                float v1 = acc[mt][nt][half * 2 + 1] + bias[n0 + n_off + col + 1];
                if (EPI == EPI_GELU)  { v0 = gelu_exact(v0); v1 = gelu_exact(v1); }
                if (EPI == EPI_SCALE) { v0 *= alpha; v1 *= alpha; }
                store2(Cp + col, v0, v1);
            }
        }
    }
}

// ---------------- weight transpose + fp16 ----------------
__global__ __launch_bounds__(256)
void transpose_w(const float* __restrict__ W, __half* __restrict__ Wt,
                 int K, int N) {
    __shared__ float tile[32][33];
    int kb = blockIdx.y * 32, nb = blockIdx.x * 32;
    int tx = threadIdx.x & 31, ty = threadIdx.x >> 5;
    #pragma unroll
    for (int i = 0; i < 32; i += 8)
        tile[ty + i][tx] = W[(size_t)(kb + ty + i) * N + nb + tx];
    __syncthreads();
    #pragma unroll
    for (int i = 0; i < 32; i += 8)
        Wt[(size_t)(nb + ty + i) * K + kb + tx] = __float2half_rn(tile[tx][ty + i]);
}

__global__ void half_copy(const float* __restrict__ in, __half* __restrict__ o, int n) {
    int i = blockIdx.x * 256 + threadIdx.x;
    if (i < n) o[i] = __float2half_rn(in[i]);
}

// ---------------- relative-position bias precompute ----------------
__global__ void bias_kernel(const float* __restrict__ w1, const float* __restrict__ b1,
                            const float* __restrict__ w2, const float* __restrict__ b2) {
    int pair = blockIdx.x;
    int q = pair / T_, k = pair % T_;
    float d0 = (float)(q / WS_ - k / WS_);
    float d1 = (float)(q % WS_ - k % WS_);
    float r0 = (d0 > 0.f ? 1.f : (d0 < 0.f ? -1.f : 0.f)) * log1pf(fabsf(d0));
    float r1 = (d1 > 0.f ? 1.f : (d1 < 0.f ? -1.f : 0.f)) * log1pf(fabsf(d1));
    int tid = threadIdx.x;
    __shared__ float hbuf[256];
    float hv = r0 * w1[tid] + r1 * w1[256 + tid] + b1[tid];
    hbuf[tid] = fmaxf(hv, 0.f);
    __syncthreads();
    if (tid < NH_) {
        float s = b2[tid];
        #pragma unroll 8
        for (int j = 0; j < 256; j++) s += hbuf[j] * w2[j * NH_ + tid];
        g_bias[tid * (T_ * T_) + pair] = s;
    }
}

// ---------------- roll(-3,-3) + unfold into token rows (fp16) ---------------
__global__ __launch_bounds__(256)
void unfold_kernel(const float* __restrict__ visual) {
    int r = blockIdx.x;
    int bw = r / T_, t = r % T_;
    int b = bw / NW_, win = bw % NW_, wh = win >> 3, ww = win & 7;
    int h = (wh * WS_ + t / WS_ + SS_) % HH;
    int w = (ww * WS_ + t % WS_ + SS_) % WW_;
    int hw = h * WW_ + w;
    for (int c = threadIdx.x; c < CC; c += 256)
        g_tok[(size_t)r * CC + c] = __float2half_rn(visual[(size_t)(b * CC + c) * HWSZ + hw]);
}

// ---------------- window attention (register-blocked) ----------------
#define SQS 36   // padded row stride (floats)
__global__ __launch_bounds__(256)
void win_attn(const float* __restrict__ tau) {
    int bw = blockIdx.x >> 4;
    int hh = blockIdx.x & 15;
    int tid = threadIdx.x;

    __shared__ __align__(16) float sq[52 * SQS], sk[52 * SQS], sv[52 * SQS];
    __shared__ float ss[50 * 50];
    __shared__ float nq[52], nk[52];
    __shared__ int   rg[T_];

    // zero pad rows 49..51 (cols 0..31)
    for (int i = tid; i < 3 * 32; i += 256) {
        int r = 49 + i / 32, c = i % 32;
        sq[r * SQS + c] = 0.f; sk[r * SQS + c] = 0.f; sv[r * SQS + c] = 0.f;
    }

    size_t base = (size_t)(bw * T_) * (3 * CC);
    for (int idx = tid; idx < T_ * HD_; idx += 256) {
        int t = idx / HD_, d = idx % HD_;
        size_t ro = base + (size_t)t * (3 * CC) + hh * HD_ + d;
        sq[t * SQS + d] = __half2float(g_qkv[ro]);
        sk[t * SQS + d] = __half2float(g_qkv[ro + CC]);
        sv[t * SQS + d] = __half2float(g_qkv[ro + 2 * CC]);
    }
    int win = bw & 63, wh = win >> 3, ww = win & 7;
    if (tid < T_) {
        int row = wh * WS_ + tid / WS_;
        int col = ww * WS_ + tid % WS_;
        int rh = row < 49 ? 0 : (row < 53 ? 1 : 2);
        int rw = col < 49 ? 0 : (col < 53 ? 1 : 2);
        rg[tid] = rh * 3 + rw;
    }
    __syncthreads();

    if (tid < 52) {
        if (tid < T_) {
            float s1 = 0.f, s2 = 0.f;
            #pragma unroll
            for (int d = 0; d < HD_; d++) {
                float a = sq[tid * SQS + d], b = sk[tid * SQS + d];
                s1 += a * a; s2 += b * b;
            }
            nq[tid] = sqrtf(s1); nk[tid] = sqrtf(s2);
        } else {
            nq[tid] = 1.f; nk[tid] = 1.f;
        }
    }
    __syncthreads();

    float tauh = fmaxf(tau[hh], 0.01f);
    const float* bh = &g_bias[hh * (T_ * T_)];
    // QK: 4x4 register tiles; 13x13 = 169 tiles
    if (tid < 169) {
        int q0 = (tid / 13) * 4, k0 = (tid % 13) * 4;
        float acc[4][4];
        #pragma unroll
        for (int i = 0; i < 4; i++)
            #pragma unroll
            for (int j = 0; j < 4; j++) acc[i][j] = 0.f;
        #pragma unroll
        for (int d4 = 0; d4 < 8; d4++) {
            float4 qv[4], kv[4];
            #pragma unroll
            for (int i = 0; i < 4; i++)
                qv[i] = *(const float4*)&sq[(q0 + i) * SQS + d4 * 4];
            #pragma unroll
            for (int j = 0; j < 4; j++)
                kv[j] = *(const float4*)&sk[(k0 + j) * SQS + d4 * 4];
            #pragma unroll
            for (int i = 0; i < 4; i++)
                #pragma unroll
                for (int j = 0; j < 4; j++)
                    acc[i][j] += qv[i].x * kv[j].x + qv[i].y * kv[j].y
                               + qv[i].z * kv[j].z + qv[i].w * kv[j].w;
        }
        #pragma unroll
        for (int i = 0; i < 4; i++) {
            int q = q0 + i;
            if (q >= T_) break;
            #pragma unroll
            for (int j = 0; j < 4; j++) {
                int k = k0 + j;
                if (k >= T_) continue;
                float s = acc[i][j] / fmaxf(nq[q] * nk[k], 1e-6f) / tauh
                        + bh[q * T_ + k];
                if (rg[q] != rg[k]) s -= 100.0f;
                ss[q * 50 + k] = s;
            }
        }
    }
    __syncthreads();

    if (tid < T_) {
        float m = -1e30f;
        for (int k = 0; k < T_; k++) m = fmaxf(m, ss[tid * 50 + k]);
        float sum = 0.f;
        for (int k = 0; k < T_; k++) {
            float e = expf(ss[tid * 50 + k] - m);
            ss[tid * 50 + k] = e; sum += e;
        }
        float inv = 1.f / sum;
        for (int k = 0; k < T_; k++) ss[tid * 50 + k] *= inv;
    }
    __syncthreads();

    // AV: 2 rows x 4 cols per thread; 25 x 8 = 200 tiles
    if (tid < 200) {
        int t0 = (tid / 8) * 2, d4 = tid % 8;
        float4 a0 = make_float4(0.f, 0.f, 0.f, 0.f), a1 = a0;
        for (int k = 0; k < T_; k++) {
            float s0 = ss[t0 * 50 + k];
            float s1 = ss[(t0 + 1) * 50 + k];
            float4 v = *(const float4*)&sv[k * SQS + d4 * 4];
            a0.x += s0 * v.x; a0.y += s0 * v.y; a0.z += s0 * v.z; a0.w += s0 * v.w;
            a1.x += s1 * v.x; a1.y += s1 * v.y; a1.z += s1 * v.z; a1.w += s1 * v.w;
        }
        __half* op = g_o1 + (size_t)(bw * T_ + t0) * CC + hh * HD_ + d4 * 4;
        ((__half2*)op)[0] = __floats2half2_rn(a0.x, a0.y);
        ((__half2*)op)[1] = __floats2half2_rn(a0.z, a0.w);
        if (t0 + 1 < T_) {
            __half* op1 = op + CC;
            ((__half2*)op1)[0] = __floats2half2_rn(a1.x, a1.y);
            ((__half2*)op1)[1] = __floats2half2_rn(a1.z, a1.w);
        }
    }
}

// ---------------- fold+roll(+3) + LN1 + residual; emit CA query tokens ------
__global__ __launch_bounds__(256)
void merge_ln1(const float* __restrict__ visual,
               const float* __restrict__ g, const float* __restrict__ bt) {
    int pos = blockIdx.x;
    int b = pos / HWSZ, hw = pos % HWSZ;
    int h = hw / WW_, w = hw % WW_;
    int hp = (h + HH - SS_) % HH, wp = (w + WW_ - SS_) % WW_;
    int rm = (b * NW_ + (hp / WS_) * 8 + (wp / WS_)) * T_ + (hp % WS_) * WS_ + (wp % WS_);

    __shared__ float x[CC];
    int tid = threadIdx.x;
    float s = 0.f, ss2 = 0.f;
    for (int c = tid; c < CC; c += 256) {
        float v = __half2float(g_w2[(size_t)rm * CC + c]);
        x[c] = v; s += v; ss2 += v * v;
    }
    float mu, rstd;
    block_meanvar(s, ss2, CC, &mu, &rstd);
    for (int c = tid; c < CC; c += 256) {
        float v = (x[c] - mu) * rstd * g[c] + bt[c]
                + visual[(size_t)(b * CC + c) * HWSZ + hw];
        g_skipa[(size_t)pos * CC + c] = v;
        g_pq  [(size_t)rm  * CC + c] = __float2half_rn(v);
    }
}

// ---------------- cross attention (register-blocked) ----------------
__global__ __launch_bounds__(256)
void ca_attn() {
    int bw = blockIdx.x >> 4;
    int hh = blockIdx.x & 15;
    int bkv = bw & 7;
    int tid = threadIdx.x;

    __shared__ __align__(16) float sq[52 * SQS], sk[L_ * SQS], sv[L_ * SQS];
    __shared__ float ss[50 * 65];

    for (int i = tid; i < 3 * 32; i += 256) {
        int r = 49 + i / 32, c = i % 32;
        sq[r * SQS + c] = 0.f;
    }
    for (int idx = tid; idx < T_ * HD_; idx += 256) {
        int t = idx / HD_, d = idx % HD_;
        sq[t * SQS + d] = __half2float(g_q2[(size_t)(bw * T_ + t) * CC + hh * HD_ + d]);
    }
    for (int idx = tid; idx < L_ * HD_; idx += 256) {
        int l = idx / HD_, d = idx % HD_;
        size_t ro = (size_t)(bkv * L_ + l) * (2 * CC) + hh * HD_ + d;
        sk[l * SQS + d] = __half2float(g_kv2[ro]);
        sv[l * SQS + d] = __half2float(g_kv2[ro + CC]);
    }
    __syncthreads();

    // QK: 4x4 tiles, 13 x 16 = 208 tiles
    if (tid < 208) {
        int q0 = (tid / 16) * 4, l0 = (tid % 16) * 4;
        float acc[4][4];
        #pragma unroll
        for (int i = 0; i < 4; i++)
            #pragma unroll
            for (int j = 0; j < 4; j++) acc[i][j] = 0.f;
        #pragma unroll
        for (int d4 = 0; d4 < 8; d4++) {
            float4 qv[4], kv[4];
            #pragma unroll
            for (int i = 0; i < 4; i++)
                qv[i] = *(const float4*)&sq[(q0 + i) * SQS + d4 * 4];
            #pragma unroll
            for (int j = 0; j < 4; j++)
                kv[j] = *(const float4*)&sk[(l0 + j) * SQS + d4 * 4];
            #pragma unroll
            for (int i = 0; i < 4; i++)
                #pragma unroll
                for (int j = 0; j < 4; j++)
                    acc[i][j] += qv[i].x * kv[j].x + qv[i].y * kv[j].y
                               + qv[i].z * kv[j].z + qv[i].w * kv[j].w;
        }
        #pragma unroll
        for (int i = 0; i < 4; i++) {
            int q = q0 + i;
            if (q >= T_) break;
            #pragma unroll
            for (int j = 0; j < 4; j++)
                ss[q * 65 + l0 + j] = acc[i][j];
        }
    }
    __syncthreads();

    if (tid < T_) {
        float m = -1e30f;
        for (int l = 0; l < L_; l++) m = fmaxf(m, ss[tid * 65 + l]);
        float sum = 0.f;
        for (int l = 0; l < L_; l++) {
            float e = expf(ss[tid * 65 + l] - m);
            ss[tid * 65 + l] = e; sum += e;
        }
        float inv = 1.f / sum;
        for (int l = 0; l < L_; l++) ss[tid * 65 + l] *= inv;
    }
    __syncthreads();

    // AV: 2 rows x 4 cols; 25 x 8 = 200 tiles
    if (tid < 200) {
        int t0 = (tid / 8) * 2, d4 = tid % 8;
        float4 a0 = make_float4(0.f, 0.f, 0.f, 0.f), a1 = a0;
        for (int l = 0; l < L_; l++) {
            float s0 = ss[t0 * 65 + l];
            float s1 = ss[(t0 + 1) * 65 + l];
            float4 v = *(const float4*)&sv[l * SQS + d4 * 4];
            a0.x += s0 * v.x; a0.y += s0 * v.y; a0.z += s0 * v.z; a0.w += s0 * v.w;
            a1.x += s1 * v.x; a1.y += s1 * v.y; a1.z += s1 * v.z; a1.w += s1 * v.w;
        }
        __half* op = g_co1 + (size_t)(bw * T_ + t0) * CC + hh * HD_ + d4 * 4;
        ((__half2*)op)[0] = __floats2half2_rn(a0.x, a0.y);
        ((__half2*)op)[1] = __floats2half2_rn(a0.z, a0.w);
        if (t0 + 1 < T_) {
            __half* op1 = op + CC;
            ((__half2*)op1)[0] = __floats2half2_rn(a1.x, a1.y);
            ((__half2*)op1)[1] = __floats2half2_rn(a1.z, a1.w);
        }
    }
}

// ---------------- LN2 + fold+roll(+3) + residual ----------------
__global__ __launch_bounds__(256)
void ca_ln2(const float* __restrict__ g, const float* __restrict__ bt) {
    int r = blockIdx.x;
    int bw = r / T_, t = r % T_;
    int b = bw / NW_, win = bw % NW_, wh = win >> 3, ww = win & 7;
    int h = (wh * WS_ + t / WS_ + SS_) % HH;
    int w = (ww * WS_ + t % WS_ + SS_) % WW_;
    int pos = b * HWSZ + h * WW_ + w;

    __shared__ float x[CC];
    int tid = threadIdx.x;
    float s = 0.f, ss2 = 0.f;
    for (int c = tid; c < CC; c += 256) {
        float v = __half2float(g_co2[(size_t)r * CC + c]);
        x[c] = v; s += v; ss2 += v * v;
    }
    float mu, rstd;
    block_meanvar(s, ss2, CC, &mu, &rstd);
    for (int c = tid; c < CC; c += 256) {
        float v = (x[c] - mu) * rstd * g[c] + bt[c]
                + g_skipa[(size_t)pos * CC + c];
        g_skip2 [(size_t)pos * CC + c] = v;
        g_skip2r[(size_t)pos * CC + c] = __float2half_rn(v);
    }
}

// ---------------- LN3(ff) + skip2, write [B,C,H,W] ----------------
__global__ __launch_bounds__(256)
void final_kernel(float* __restrict__ out,
                  const float* __restrict__ g, const float* __restrict__ bt) {
    int pos = blockIdx.x;
    int b = pos / HWSZ, hw = pos % HWSZ;

    __shared__ float x[CC];
    int tid = threadIdx.x;
    float s = 0.f, ss2 = 0.f;
    for (int c = tid; c < CC; c += 256) {
        float v = __half2float(g_ffo[(size_t)pos * CC + c]);
        x[c] = v; s += v; ss2 += v * v;
    }
    float mu, rstd;
    block_meanvar(s, ss2, CC, &mu, &rstd);
    for (int c = tid; c < CC; c += 256) {
        float v = (x[c] - mu) * rstd * g[c] + bt[c];
        out[(size_t)(b * CC + c) * HWSZ + hw] = g_skip2[(size_t)pos * CC + c] + v;
    }
}

// ---------------- launch ----------------
extern "C" void kernel_launch(void* const* d_in, const int* in_sizes, int n_in,
                              void* d_out, int out_size) {
    const float* visual   = (const float*)d_in[0];
    const float* vector   = (const float*)d_in[1];
    const float* tm_w     = (const float*)d_in[2];
    const float* tm_b     = (const float*)d_in[3];
    const float* ln1_g    = (const float*)d_in[4];
    const float* ln1_b    = (const float*)d_in[5];
    const float* ln2_g    = (const float*)d_in[6];
    const float* ln2_b    = (const float*)d_in[7];
    const float* ln3_g    = (const float*)d_in[8];
    const float* ln3_b    = (const float*)d_in[9];
    const float* qkv_w    = (const float*)d_in[10];
    const float* qkv_b    = (const float*)d_in[11];
    const float* wproj_w  = (const float*)d_in[12];
    const float* wproj_b  = (const float*)d_in[13];
    const float* meta_w1  = (const float*)d_in[14];
    const float* meta_b1  = (const float*)d_in[15];
    const float* meta_w2  = (const float*)d_in[16];
    const float* meta_b2  = (const float*)d_in[17];
    const float* tau      = (const float*)d_in[18];
    const float* ca_in_w  = (const float*)d_in[19];
    const float* ca_in_b  = (const float*)d_in[20];
    const float* ca_out_w = (const float*)d_in[21];
    const float* ca_out_b = (const float*)d_in[22];
    const float* ff_w1    = (const float*)d_in[23];
    const float* ff_b1    = (const float*)d_in[24];
    const float* ff_w2    = (const float*)d_in[25];
    const float* ff_b2    = (const float*)d_in[26];
    float* out = (float*)d_out;

    __half *vin, *vec, *tok, *o1, *pq, *co1, *sk2r, *ffh;
    __half *qkv, *w2, *q2, *kv2, *co2, *ffo;
    __half *tmwt, *qkvwt, *wprwt, *caint, *caoutt, *ff1t, *ff2t;
    cudaGetSymbolAddress((void**)&vin,   g_vin);
    cudaGetSymbolAddress((void**)&vec,   g_vec);
    cudaGetSymbolAddress((void**)&tok,   g_tok);
    cudaGetSymbolAddress((void**)&qkv,   g_qkv);
    cudaGetSymbolAddress((void**)&o1,    g_o1);
    cudaGetSymbolAddress((void**)&w2,    g_w2);
    cudaGetSymbolAddress((void**)&pq,    g_pq);
    cudaGetSymbolAddress((void**)&q2,    g_q2);
    cudaGetSymbolAddress((void**)&kv2,   g_kv2);
    cudaGetSymbolAddress((void**)&co1,   g_co1);
    cudaGetSymbolAddress((void**)&co2,   g_co2);
    cudaGetSymbolAddress((void**)&sk2r,  g_skip2r);
    cudaGetSymbolAddress((void**)&ffh,   g_ffh);
    cudaGetSymbolAddress((void**)&ffo,   g_ffo);
    cudaGetSymbolAddress((void**)&tmwt,  g_tmw_t);
    cudaGetSymbolAddress((void**)&qkvwt, g_qkvw_t);
    cudaGetSymbolAddress((void**)&wprwt, g_wprw_t);
    cudaGetSymbolAddress((void**)&caint, g_cain_t);
    cudaGetSymbolAddress((void**)&caoutt,g_caout_t);
    cudaGetSymbolAddress((void**)&ff1t,  g_ff1_t);
    cudaGetSymbolAddress((void**)&ff2t,  g_ff2_t);

    cudaFuncSetAttribute((const void*)tgemm<EPI_NONE,  __half>, cudaFuncAttributeMaxDynamicSharedMemorySize, TGEMM_SMEM);
    cudaFuncSetAttribute((const void*)tgemm<EPI_GELU,  __half>, cudaFuncAttributeMaxDynamicSharedMemorySize, TGEMM_SMEM);
    cudaFuncSetAttribute((const void*)tgemm<EPI_SCALE, __half>, cudaFuncAttributeMaxDynamicSharedMemorySize, TGEMM_SMEM);

    // weight transposes (+fp16 rounding)
    transpose_w<<<dim3(16,  8), 256>>>(tm_w,     tmwt,  256,  512);
    transpose_w<<<dim3(48, 16), 256>>>(qkv_w,    qkvwt, 512, 1536);
    transpose_w<<<dim3(16, 16), 256>>>(wproj_w,  wprwt, 512,  512);
    transpose_w<<<dim3(48, 16), 256>>>(ca_in_w,  caint, 512, 1536);
    transpose_w<<<dim3(16, 16), 256>>>(ca_out_w, caoutt,512,  512);
    transpose_w<<<dim3(64, 16), 256>>>(ff_w1,    ff1t,  512, 2048);
    transpose_w<<<dim3(16, 64), 256>>>(ff_w2,    ff2t, 2048,  512);
    half_copy<<<512, 256>>>(vector, vin, 512 * 256);

    bias_kernel<<<T_ * T_, 256>>>(meta_w1, meta_b1, meta_w2, meta_b2);

    // vec = gelu(vector @ tm_w + tm_b)
    tgemm<EPI_GELU, __half><<<dim3(4, 4), 256, TGEMM_SMEM>>>(vin, tmwt, tm_b, vec, 512, 512, 256, 0.f);
    // K2|V2 fused
    tgemm<EPI_NONE, __half><<<dim3(8, 4), 256, TGEMM_SMEM>>>(vec, caint + 512 * 512, ca_in_b + 512, kv2, 512, 1024, 512, 0.f);

    unfold_kernel<<<NTOK, 256>>>(visual);
    tgemm<EPI_NONE, __half><<<dim3(12, 196), 256, TGEMM_SMEM>>>(tok, qkvwt, qkv_b, qkv, NTOK, 3 * CC, CC, 0.f);
    win_attn<<<BW_ * NH_, 256>>>(tau);
    tgemm<EPI_NONE, __half><<<dim3(4, 196), 256, TGEMM_SMEM>>>(o1, wprwt, wproj_b, w2, NTOK, CC, CC, 0.f);
    merge_ln1<<<BB * HWSZ, 256>>>(visual, ln1_g, ln1_b);
    tgemm<EPI_SCALE, __half><<<dim3(4, 196), 256, TGEMM_SMEM>>>(pq, caint, ca_in_b, q2, NTOK, CC, CC, 0.17677669529663687f);
    ca_attn<<<BW_ * NH_, 256>>>();
    tgemm<EPI_NONE, __half><<<dim3(4, 196), 256, TGEMM_SMEM>>>(co1, caoutt, ca_out_b, co2, NTOK, CC, CC, 0.f);
    ca_ln2<<<NTOK, 256>>>(ln2_g, ln2_b);
    tgemm<EPI_GELU, __half><<<dim3(16, 196), 256, TGEMM_SMEM>>>(sk2r, ff1t, ff_b1, ffh, NTOK, 4 * CC, CC, 0.f);
    tgemm<EPI_NONE, __half><<<dim3(4, 196), 256, TGEMM_SMEM>>>(ffh, ff2t, ff_b2, ffo, NTOK, CC, 2048, 0.f);
    final_kernel<<<BB * HWSZ, 256>>>(out, ln3_g, ln3_b);
}